// round 6
// baseline (speedup 1.0000x reference)
#include <cuda_runtime.h>
#include <cuda_bf16.h>
#include <math.h>
#include <stdint.h>

#define Cc 512
#define Bb 8
#define Nn 4096
#define GROUPS 8
#define EPS 1e-5f

#define MC ((size_t)Bb * Nn * Cc)
#define SC ((size_t)Bb * Nn * Nn)
#define NCs ((long long)Nn * Cc)
#define NNs ((long long)Nn * Nn)

// ---------------- scratch ----------------
__device__ __nv_bfloat16 g_hh[MC], g_hl[MC];
__device__ __nv_bfloat16 g_w4h[4 * Cc * Cc], g_w4l[4 * Cc * Cc];
__device__ __nv_bfloat16 g_qh[MC], g_ql[MC];
__device__ __nv_bfloat16 g_kh[MC], g_kl[MC];
__device__ float         g_v[MC];
__device__ __nv_bfloat16 g_vth[MC], g_vtl[MC];
__device__ float         g_s[SC];
__device__ __nv_bfloat16 g_ph[SC], g_pl[SC];
__device__ __nv_bfloat16 g_aoh[MC], g_aol[MC];
__device__ float         g_y[MC];
__device__ float         g_stats[Bb * GROUPS * 2];

__device__ __forceinline__ void split_store(float v, __nv_bfloat16* ph, __nv_bfloat16* pl) {
    __nv_bfloat16 h = __float2bfloat16_rn(v);
    *ph = h;
    *pl = __float2bfloat16_rn(v - __bfloat162float(h));
}

// ---------------- 1) group-norm statistics ----------------
__global__ void gn_stats_kernel(const float* __restrict__ x) {
    int bg = blockIdx.x;
    const size_t cnt = (size_t)(Cc / GROUPS) * Nn;
    const float4* p = (const float4*)(x + (size_t)bg * cnt);
    int tid = threadIdx.x;
    float s = 0.f, sq = 0.f;
    for (int i = tid; i < (int)(cnt / 4); i += blockDim.x) {
        float4 v = p[i];
        s  += v.x + v.y + v.z + v.w;
        sq += v.x * v.x + v.y * v.y + v.z * v.z + v.w * v.w;
    }
    __shared__ float ss[256], ssq[256];
    ss[tid] = s; ssq[tid] = sq;
    __syncthreads();
    for (int o = 128; o > 0; o >>= 1) {
        if (tid < o) { ss[tid] += ss[tid + o]; ssq[tid] += ssq[tid + o]; }
        __syncthreads();
    }
    if (tid == 0) {
        float mu  = ss[0] / (float)cnt;
        float var = ssq[0] / (float)cnt - mu * mu;
        g_stats[bg * 2 + 0] = mu;
        g_stats[bg * 2 + 1] = rsqrtf(var + EPS);
    }
}

// ---------------- 2) GN apply + transpose -> split bf16 [B,N,C] ----------------
__global__ void gn_apply_kernel(const float* __restrict__ x,
                                const float* __restrict__ w,
                                const float* __restrict__ b) {
    __shared__ float sm[32][33];
    int bz = blockIdx.z;
    int n0 = blockIdx.x * 32;
    int c0 = blockIdx.y * 32;
    int tx = threadIdx.x, ty = threadIdx.y;
    {
        int c = c0 + ty, n = n0 + tx;
        int g = c >> 6;
        float mu   = g_stats[(bz * GROUPS + g) * 2 + 0];
        float rstd = g_stats[(bz * GROUPS + g) * 2 + 1];
        float v = x[((size_t)bz * Cc + c) * Nn + n];
        sm[ty][tx] = (v - mu) * rstd * w[c] + b[c];
    }
    __syncthreads();
    {
        int n = n0 + ty, c = c0 + tx;
        size_t idx = ((size_t)bz * Nn + n) * Cc + c;
        split_store(sm[tx][ty], g_hh + idx, g_hl + idx);
    }
}

__global__ void split_kernel(const float* __restrict__ src,
                             __nv_bfloat16* __restrict__ dh,
                             __nv_bfloat16* __restrict__ dl) {
    int i = blockIdx.x * 256 + threadIdx.x;
    split_store(src[i], dh + i, dl + i);
}

__global__ void vtrans_kernel() {
    __shared__ float sm[32][33];
    int bz = blockIdx.z;
    int m0 = blockIdx.x * 32;
    int d0 = blockIdx.y * 32;
    int tx = threadIdx.x, ty = threadIdx.y;
    sm[ty][tx] = g_v[((size_t)bz * Nn + (m0 + ty)) * Cc + (d0 + tx)];
    __syncthreads();
    size_t idx = ((size_t)bz * Cc + (d0 + ty)) * Nn + (m0 + tx);
    split_store(sm[tx][ty], g_vth + idx, g_vtl + idx);
}

// ---------------- tensor-core TN GEMM, bf16x3 split ----------------
// C = alpha * A·B^T (+bias). A[M,K], B[N,K], hi/lo bf16 planes, K-contiguous.
// CTA tile 256x128x32, 512 threads, 16 warps (8 M-slots x 2 N-slots),
// warp tile 32x64, 3-stage cp.async pipeline.
#define SROW 40
#define PLA (256 * SROW)      // A plane elems
#define PLB (128 * SROW)      // B plane elems
#define STG (2 * PLA + 2 * PLB)   // stage elems (30720) = 60 KB
#define NSTAGE 3

__device__ __forceinline__ uint32_t cvta_s(const void* p) {
    return (uint32_t)__cvta_generic_to_shared(p);
}
__device__ __forceinline__ void cp16(uint32_t s, const void* g) {
    asm volatile("cp.async.cg.shared.global [%0], [%1], 16;" :: "r"(s), "l"(g));
}
__device__ __forceinline__ void ldsm4(uint32_t& r0, uint32_t& r1, uint32_t& r2, uint32_t& r3, uint32_t a) {
    asm volatile("ldmatrix.sync.aligned.m8n8.x4.shared.b16 {%0,%1,%2,%3}, [%4];"
                 : "=r"(r0), "=r"(r1), "=r"(r2), "=r"(r3) : "r"(a));
}
__device__ __forceinline__ void mma16816(float* c, const uint32_t* a, const uint32_t* b) {
    asm volatile("mma.sync.aligned.m16n8k16.row.col.f32.bf16.bf16.f32 "
                 "{%0,%1,%2,%3},{%4,%5,%6,%7},{%8,%9},{%0,%1,%2,%3};"
                 : "+f"(c[0]), "+f"(c[1]), "+f"(c[2]), "+f"(c[3])
                 : "r"(a[0]), "r"(a[1]), "r"(a[2]), "r"(a[3]), "r"(b[0]), "r"(b[1]));
}

__global__ __launch_bounds__(512, 1)
void mma_tn(const __nv_bfloat16* __restrict__ Ah, const __nv_bfloat16* __restrict__ Al,
            const __nv_bfloat16* __restrict__ Bh, const __nv_bfloat16* __restrict__ Bl,
            const float* __restrict__ bias,
            float* __restrict__ Cf,
            __nv_bfloat16* __restrict__ Ch, __nv_bfloat16* __restrict__ Cl,
            int M, int N, int K, float alpha,
            long long sA, long long sB, long long sC) {
    extern __shared__ __nv_bfloat16 smbuf[];
    long long zb = blockIdx.z;
    Ah += zb * sA; Al += zb * sA;
    Bh += zb * sB; Bl += zb * sB;
    if (Cf) Cf += zb * sC;
    if (Ch) { Ch += zb * sC; Cl += zb * sC; }

    int tid = threadIdx.x;
    int lane = tid & 31, warp = tid >> 5;
    int wm = warp & 7, wn = warp >> 3;
    int brow = blockIdx.y * 256, bcol = blockIdx.x * 128;
    uint32_t sbase = cvta_s(smbuf);

    // loader indices
    int tA_row = tid >> 1;            // 0..255
    int tA_seg = (tid & 1) * 16;      // 0 / 16
    int tB_row = tid >> 2;            // 0..127
    int tB_seg = (tid & 3) * 8;       // 0,8,16,24

    float acc[2][8][4];
    #pragma unroll
    for (int i = 0; i < 2; i++)
        #pragma unroll
        for (int j = 0; j < 8; j++)
            #pragma unroll
            for (int q = 0; q < 4; q++) acc[i][j][q] = 0.f;

    auto load_stage = [&](int slot, int k0) {
        uint32_t so = sbase + (uint32_t)(slot * STG * 2);
        size_t ga = (size_t)(brow + tA_row) * K + k0 + tA_seg;
        uint32_t sa = so + (uint32_t)(tA_row * SROW + tA_seg) * 2;
        cp16(sa,                    Ah + ga);
        cp16(sa + 16,               Ah + ga + 8);
        cp16(sa + PLA * 2,          Al + ga);
        cp16(sa + PLA * 2 + 16,     Al + ga + 8);
        size_t gb = (size_t)(bcol + tB_row) * K + k0 + tB_seg;
        uint32_t sb = so + 2 * PLA * 2 + (uint32_t)(tB_row * SROW + tB_seg) * 2;
        cp16(sb,            Bh + gb);
        cp16(sb + PLB * 2,  Bl + gb);
    };

    int nk = K >> 5;
    load_stage(0, 0);
    asm volatile("cp.async.commit_group;");
    if (nk > 1) {
        load_stage(1, 32);
        asm volatile("cp.async.commit_group;");
    }

    for (int kt = 0; kt < nk; kt++) {
        if (kt + 2 < nk) {
            asm volatile("cp.async.wait_group 1;");
            __syncthreads();
            load_stage((kt + 2) % NSTAGE, (kt + 2) << 5);
            asm volatile("cp.async.commit_group;");
        } else {
            asm volatile("cp.async.wait_group 0;");
            __syncthreads();
        }
        uint32_t so = sbase + (uint32_t)((kt % NSTAGE) * STG * 2);
        #pragma unroll
        for (int kk = 0; kk < 2; kk++) {
            // A fragments
            uint32_t ah[2][4], al[2][4];
            int arow = wm * 32 + ((lane >> 3) & 1) * 8 + (lane & 7);
            int akof = kk * 16 + (lane >> 4) * 8;
            #pragma unroll
            for (int mt = 0; mt < 2; mt++) {
                uint32_t addr = so + (uint32_t)(((arow + mt * 16) * SROW + akof) * 2);
                ldsm4(ah[mt][0], ah[mt][1], ah[mt][2], ah[mt][3], addr);
                ldsm4(al[mt][0], al[mt][1], al[mt][2], al[mt][3], addr + PLA * 2);
            }
            // B fragments
            uint32_t bh[8][2], bl[8][2];
            int bphase = lane >> 3;
            int brl = wn * 64 + (lane & 7) + (bphase >> 1) * 8;
            int bkof = kk * 16 + (bphase & 1) * 8;
            #pragma unroll
            for (int np = 0; np < 4; np++) {
                uint32_t addr = so + 2 * PLA * 2 + (uint32_t)(((brl + np * 16) * SROW + bkof) * 2);
                uint32_t r0, r1, r2, r3;
                ldsm4(r0, r1, r2, r3, addr);
                bh[np * 2][0] = r0; bh[np * 2][1] = r1;
                bh[np * 2 + 1][0] = r2; bh[np * 2 + 1][1] = r3;
                ldsm4(r0, r1, r2, r3, addr + PLB * 2);
                bl[np * 2][0] = r0; bl[np * 2][1] = r1;
                bl[np * 2 + 1][0] = r2; bl[np * 2 + 1][1] = r3;
            }
            #pragma unroll
            for (int mt = 0; mt < 2; mt++)
                #pragma unroll
                for (int nt = 0; nt < 8; nt++)
                    mma16816(acc[mt][nt], ah[mt], bh[nt]);
            #pragma unroll
            for (int mt = 0; mt < 2; mt++)
                #pragma unroll
                for (int nt = 0; nt < 8; nt++)
                    mma16816(acc[mt][nt], ah[mt], bl[nt]);
            #pragma unroll
            for (int mt = 0; mt < 2; mt++)
                #pragma unroll
                for (int nt = 0; nt < 8; nt++)
                    mma16816(acc[mt][nt], al[mt], bh[nt]);
        }
        __syncthreads();
    }

    // epilogue
    int gid = lane >> 2, tig = lane & 3;
    #pragma unroll
    for (int nt = 0; nt < 8; nt++) {
        int col = bcol + wn * 64 + nt * 8 + tig * 2;
        float b0 = bias ? bias[col] : 0.f;
        float b1 = bias ? bias[col + 1] : 0.f;
        #pragma unroll
        for (int mt = 0; mt < 2; mt++) {
            int row0 = brow + wm * 32 + mt * 16 + gid;
            float v00 = acc[mt][nt][0] * alpha + b0;
            float v01 = acc[mt][nt][1] * alpha + b1;
            float v10 = acc[mt][nt][2] * alpha + b0;
            float v11 = acc[mt][nt][3] * alpha + b1;
            if (Cf) {
                float2 p0 = {v00, v01}, p1 = {v10, v11};
                *(float2*)(Cf + (size_t)row0 * N + col) = p0;
                *(float2*)(Cf + (size_t)(row0 + 8) * N + col) = p1;
            }
            if (Ch) {
                __nv_bfloat16 h00 = __float2bfloat16_rn(v00);
                __nv_bfloat16 h01 = __float2bfloat16_rn(v01);
                __nv_bfloat16 h10 = __float2bfloat16_rn(v10);
                __nv_bfloat16 h11 = __float2bfloat16_rn(v11);
                __nv_bfloat162 hh0 = {h00, h01}, hh1 = {h10, h11};
                __nv_bfloat162 ll0 = {__float2bfloat16_rn(v00 - __bfloat162float(h00)),
                                      __float2bfloat16_rn(v01 - __bfloat162float(h01))};
                __nv_bfloat162 ll1 = {__float2bfloat16_rn(v10 - __bfloat162float(h10)),
                                      __float2bfloat16_rn(v11 - __bfloat162float(h11))};
                *(__nv_bfloat162*)(Ch + (size_t)row0 * N + col) = hh0;
                *(__nv_bfloat162*)(Cl + (size_t)row0 * N + col) = ll0;
                *(__nv_bfloat162*)(Ch + (size_t)(row0 + 8) * N + col) = hh1;
                *(__nv_bfloat162*)(Cl + (size_t)(row0 + 8) * N + col) = ll1;
            }
        }
    }
}

// ---------------- softmax rows of g_s -> split bf16 probs ----------------
__global__ void softmax_kernel() {
    size_t row = blockIdx.x;
    float4* p = (float4*)(g_s + row * Nn);
    int tid = threadIdx.x;
    float4 v[4];
    float mx = -1e30f;
    #pragma unroll
    for (int i = 0; i < 4; i++) {
        v[i] = p[tid + i * 256];
        mx = fmaxf(mx, fmaxf(fmaxf(v[i].x, v[i].y), fmaxf(v[i].z, v[i].w)));
    }
    __shared__ float sm[256];
    sm[tid] = mx; __syncthreads();
    for (int o = 128; o > 0; o >>= 1) {
        if (tid < o) sm[tid] = fmaxf(sm[tid], sm[tid + o]);
        __syncthreads();
    }
    mx = sm[0];
    __syncthreads();
    float s = 0.f;
    #pragma unroll
    for (int i = 0; i < 4; i++) {
        v[i].x = __expf(v[i].x - mx); v[i].y = __expf(v[i].y - mx);
        v[i].z = __expf(v[i].z - mx); v[i].w = __expf(v[i].w - mx);
        s += v[i].x + v[i].y + v[i].z + v[i].w;
    }
    sm[tid] = s; __syncthreads();
    for (int o = 128; o > 0; o >>= 1) {
        if (tid < o) sm[tid] += sm[tid + o];
        __syncthreads();
    }
    float inv = 1.f / sm[0];
    #pragma unroll
    for (int i = 0; i < 4; i++) {
        float e0 = v[i].x * inv, e1 = v[i].y * inv, e2 = v[i].z * inv, e3 = v[i].w * inv;
        size_t base = row * Nn + (size_t)(tid + i * 256) * 4;
        __nv_bfloat16 h0 = __float2bfloat16_rn(e0), h1 = __float2bfloat16_rn(e1);
        __nv_bfloat16 h2 = __float2bfloat16_rn(e2), h3 = __float2bfloat16_rn(e3);
        __nv_bfloat162 hh0 = {h0, h1}, hh1 = {h2, h3};
        __nv_bfloat162 ll0 = {__float2bfloat16_rn(e0 - __bfloat162float(h0)),
                              __float2bfloat16_rn(e1 - __bfloat162float(h1))};
        __nv_bfloat162 ll1 = {__float2bfloat16_rn(e2 - __bfloat162float(h2)),
                              __float2bfloat16_rn(e3 - __bfloat162float(h3))};
        ((__nv_bfloat162*)(g_ph + base))[0] = hh0;
        ((__nv_bfloat162*)(g_ph + base))[1] = hh1;
        ((__nv_bfloat162*)(g_pl + base))[0] = ll0;
        ((__nv_bfloat162*)(g_pl + base))[1] = ll1;
    }
}

// ---------------- residual ----------------
__global__ void residual_kernel(const float* __restrict__ x, float* __restrict__ out) {
    __shared__ float sm[32][33];
    int bz = blockIdx.z;
    int n0 = blockIdx.x * 32;
    int c0 = blockIdx.y * 32;
    int tx = threadIdx.x, ty = threadIdx.y;
    sm[ty][tx] = g_y[((size_t)bz * Nn + (n0 + ty)) * Cc + (c0 + tx)];
    __syncthreads();
    size_t idx = ((size_t)bz * Cc + (c0 + ty)) * Nn + (n0 + tx);
    out[idx] = x[idx] + sm[tx][ty];
}

// ---------------- launch ----------------
extern "C" void kernel_launch(void* const* d_in, const int* in_sizes, int n_in,
                              void* d_out, int out_size) {
    const float* x    = (const float*)d_in[0];
    const float* gn_w = (const float*)d_in[1];
    const float* gn_b = (const float*)d_in[2];
    const float* wq   = (const float*)d_in[3];
    const float* bq   = (const float*)d_in[4];
    const float* wk   = (const float*)d_in[5];
    const float* bk   = (const float*)d_in[6];
    const float* wv   = (const float*)d_in[7];
    const float* bv   = (const float*)d_in[8];
    const float* wo   = (const float*)d_in[9];
    const float* bo   = (const float*)d_in[10];
    float* out = (float*)d_out;

    __nv_bfloat16 *hh, *hl, *w4h, *w4l, *qh, *ql, *kh, *kl, *vth, *vtl, *ph, *pl, *aoh, *aol;
    float *v, *s, *y;
    cudaGetSymbolAddress((void**)&hh, g_hh);   cudaGetSymbolAddress((void**)&hl, g_hl);
    cudaGetSymbolAddress((void**)&w4h, g_w4h); cudaGetSymbolAddress((void**)&w4l, g_w4l);
    cudaGetSymbolAddress((void**)&qh, g_qh);   cudaGetSymbolAddress((void**)&ql, g_ql);
    cudaGetSymbolAddress((void**)&kh, g_kh);   cudaGetSymbolAddress((void**)&kl, g_kl);
    cudaGetSymbolAddress((void**)&vth, g_vth); cudaGetSymbolAddress((void**)&vtl, g_vtl);
    cudaGetSymbolAddress((void**)&ph, g_ph);   cudaGetSymbolAddress((void**)&pl, g_pl);
    cudaGetSymbolAddress((void**)&aoh, g_aoh); cudaGetSymbolAddress((void**)&aol, g_aol);
    cudaGetSymbolAddress((void**)&v, g_v);
    cudaGetSymbolAddress((void**)&s, g_s);
    cudaGetSymbolAddress((void**)&y, g_y);

    const int Mtot = Bb * Nn;                        // 32768
    const float scale = 0.044194173824159216f;       // 1/sqrt(512)
    const int WSZ = Cc * Cc;                         // 262144
    const int SMEM = NSTAGE * STG * 2;               // 3 stages * 60 KB

    cudaFuncSetAttribute(mma_tn, cudaFuncAttributeMaxDynamicSharedMemorySize, SMEM);

    // launch order chosen so ncu (-s 5 -c 1) captures the first mma_tn
    gn_stats_kernel<<<Bb * GROUPS, 256>>>(x);                               // 1
    split_kernel<<<WSZ / 256, 256>>>(wq, w4h + 0 * WSZ, w4l + 0 * WSZ);     // 2
    split_kernel<<<WSZ / 256, 256>>>(wk, w4h + 1 * WSZ, w4l + 1 * WSZ);     // 3
    split_kernel<<<WSZ / 256, 256>>>(wv, w4h + 2 * WSZ, w4l + 2 * WSZ);     // 4
    gn_apply_kernel<<<dim3(Nn / 32, Cc / 32, Bb), dim3(32, 32)>>>(x, gn_w, gn_b); // 5

    dim3 gproj(Cc / 128, Mtot / 256, 1);
    mma_tn<<<gproj, 512, SMEM>>>(hh, hl, w4h + 0 * WSZ, w4l + 0 * WSZ, bq,  // 6 <- ncu
                                 nullptr, qh, ql, Mtot, Cc, Cc, 1.f, 0, 0, 0);
    mma_tn<<<gproj, 512, SMEM>>>(hh, hl, w4h + 1 * WSZ, w4l + 1 * WSZ, bk,
                                 nullptr, kh, kl, Mtot, Cc, Cc, 1.f, 0, 0, 0);
    mma_tn<<<gproj, 512, SMEM>>>(hh, hl, w4h + 2 * WSZ, w4l + 2 * WSZ, bv,
                                 v, nullptr, nullptr, Mtot, Cc, Cc, 1.f, 0, 0, 0);
    vtrans_kernel<<<dim3(Nn / 32, Cc / 32, Bb), dim3(32, 32)>>>();
    mma_tn<<<dim3(Nn / 128, Nn / 256, Bb), 512, SMEM>>>(qh, ql, kh, kl, nullptr,
                                 s, nullptr, nullptr, Nn, Nn, Cc, scale, NCs, NCs, NNs);
    softmax_kernel<<<Bb * Nn, 256>>>();
    mma_tn<<<dim3(Cc / 128, Nn / 256, Bb), 512, SMEM>>>(ph, pl, vth, vtl, nullptr,
                                 nullptr, aoh, aol, Nn, Cc, Nn, 1.f, NNs, NCs, NCs);
    split_kernel<<<WSZ / 256, 256>>>(wo, w4h + 3 * WSZ, w4l + 3 * WSZ);
    mma_tn<<<gproj, 512, SMEM>>>(aoh, aol, w4h + 3 * WSZ, w4l + 3 * WSZ, bo,
                                 y, nullptr, nullptr, Mtot, Cc, Cc, 1.f, 0, 0, 0);
    residual_kernel<<<dim3(Nn / 32, Cc / 32, Bb), dim3(32, 32)>>>(x, out);
}

// round 7
// speedup vs baseline: 1.3044x; 1.3044x over previous
#include <cuda_runtime.h>
#include <cuda_bf16.h>
#include <math.h>
#include <stdint.h>

#define Cc 512
#define Bb 8
#define Nn 4096
#define GROUPS 8
#define EPS 1e-5f

#define MC ((size_t)Bb * Nn * Cc)
#define SC ((size_t)Bb * Nn * Nn)
#define NCs ((long long)Nn * Cc)
#define NNs ((long long)Nn * Nn)

// ---------------- scratch ----------------
__device__ __nv_bfloat16 g_hh[MC], g_hl[MC];
__device__ __nv_bfloat16 g_w4h[4 * Cc * Cc], g_w4l[4 * Cc * Cc];
__device__ __nv_bfloat16 g_qh[MC], g_ql[MC];
__device__ __nv_bfloat16 g_kh[MC], g_kl[MC];
__device__ float         g_v[MC];
__device__ __nv_bfloat16 g_vth[MC], g_vtl[MC];
__device__ float         g_s[SC];
__device__ __nv_bfloat16 g_ph[SC], g_pl[SC];
__device__ __nv_bfloat16 g_aoh[MC], g_aol[MC];
__device__ float         g_y[MC];
__device__ float         g_stats[Bb * GROUPS * 2];

__device__ __forceinline__ void split_store(float v, __nv_bfloat16* ph, __nv_bfloat16* pl) {
    __nv_bfloat16 h = __float2bfloat16_rn(v);
    *ph = h;
    *pl = __float2bfloat16_rn(v - __bfloat162float(h));
}

// ---------------- 1) group-norm statistics ----------------
__global__ void gn_stats_kernel(const float* __restrict__ x) {
    int bg = blockIdx.x;
    const size_t cnt = (size_t)(Cc / GROUPS) * Nn;
    const float4* p = (const float4*)(x + (size_t)bg * cnt);
    int tid = threadIdx.x;
    float s = 0.f, sq = 0.f;
    for (int i = tid; i < (int)(cnt / 4); i += blockDim.x) {
        float4 v = p[i];
        s  += v.x + v.y + v.z + v.w;
        sq += v.x * v.x + v.y * v.y + v.z * v.z + v.w * v.w;
    }
    __shared__ float ss[256], ssq[256];
    ss[tid] = s; ssq[tid] = sq;
    __syncthreads();
    for (int o = 128; o > 0; o >>= 1) {
        if (tid < o) { ss[tid] += ss[tid + o]; ssq[tid] += ssq[tid + o]; }
        __syncthreads();
    }
    if (tid == 0) {
        float mu  = ss[0] / (float)cnt;
        float var = ssq[0] / (float)cnt - mu * mu;
        g_stats[bg * 2 + 0] = mu;
        g_stats[bg * 2 + 1] = rsqrtf(var + EPS);
    }
}

// ---------------- 2) GN apply + transpose -> split bf16 [B,N,C] ----------------
__global__ void gn_apply_kernel(const float* __restrict__ x,
                                const float* __restrict__ w,
                                const float* __restrict__ b) {
    __shared__ float sm[32][33];
    int bz = blockIdx.z;
    int n0 = blockIdx.x * 32;
    int c0 = blockIdx.y * 32;
    int tx = threadIdx.x, ty = threadIdx.y;
    {
        int c = c0 + ty, n = n0 + tx;
        int g = c >> 6;
        float mu   = g_stats[(bz * GROUPS + g) * 2 + 0];
        float rstd = g_stats[(bz * GROUPS + g) * 2 + 1];
        float v = x[((size_t)bz * Cc + c) * Nn + n];
        sm[ty][tx] = (v - mu) * rstd * w[c] + b[c];
    }
    __syncthreads();
    {
        int n = n0 + ty, c = c0 + tx;
        size_t idx = ((size_t)bz * Nn + n) * Cc + c;
        split_store(sm[tx][ty], g_hh + idx, g_hl + idx);
    }
}

__global__ void split_kernel(const float* __restrict__ src,
                             __nv_bfloat16* __restrict__ dh,
                             __nv_bfloat16* __restrict__ dl) {
    int i = blockIdx.x * 256 + threadIdx.x;
    split_store(src[i], dh + i, dl + i);
}

__global__ void vtrans_kernel() {
    __shared__ float sm[32][33];
    int bz = blockIdx.z;
    int m0 = blockIdx.x * 32;
    int d0 = blockIdx.y * 32;
    int tx = threadIdx.x, ty = threadIdx.y;
    sm[ty][tx] = g_v[((size_t)bz * Nn + (m0 + ty)) * Cc + (d0 + tx)];
    __syncthreads();
    size_t idx = ((size_t)bz * Cc + (d0 + ty)) * Nn + (m0 + tx);
    split_store(sm[tx][ty], g_vth + idx, g_vtl + idx);
}

// ---------------- tensor-core TN GEMM, bf16x3 split ----------------
// C = alpha*A·B^T (+bias). A[M,K], B[N,K], hi/lo bf16 planes, K-contiguous.
// CTA 128x128x32, 256 thr, 8 warps (4M x 2N), warp tile 32x64.
// 3-stage cp.async pipeline, one __syncthreads per stage.
// Smem: unpadded 64B rows with XOR chunk swizzle c' = c ^ ((row>>1)&3).
#define PLB 8192                 // bytes per plane (128 rows * 64B)
#define STGB (4 * PLB)           // 32 KB per stage
#define NSTAGE 3

__device__ __forceinline__ uint32_t cvta_s(const void* p) {
    return (uint32_t)__cvta_generic_to_shared(p);
}
__device__ __forceinline__ void cp16(uint32_t s, const void* g) {
    asm volatile("cp.async.cg.shared.global [%0], [%1], 16;" :: "r"(s), "l"(g));
}
__device__ __forceinline__ void ldsm4(uint32_t& r0, uint32_t& r1, uint32_t& r2, uint32_t& r3, uint32_t a) {
    asm volatile("ldmatrix.sync.aligned.m8n8.x4.shared.b16 {%0,%1,%2,%3}, [%4];"
                 : "=r"(r0), "=r"(r1), "=r"(r2), "=r"(r3) : "r"(a));
}
__device__ __forceinline__ void mma16816(float* c, const uint32_t* a, const uint32_t* b) {
    asm volatile("mma.sync.aligned.m16n8k16.row.col.f32.bf16.bf16.f32 "
                 "{%0,%1,%2,%3},{%4,%5,%6,%7},{%8,%9},{%0,%1,%2,%3};"
                 : "+f"(c[0]), "+f"(c[1]), "+f"(c[2]), "+f"(c[3])
                 : "r"(a[0]), "r"(a[1]), "r"(a[2]), "r"(a[3]), "r"(b[0]), "r"(b[1]));
}
// physical smem byte offset for (row, chunk) in a plane; chunk = 16B unit 0..3
__device__ __forceinline__ uint32_t swz(int row, int chunk) {
    return (uint32_t)(row * 64 + ((chunk ^ ((row >> 1) & 3)) << 4));
}

__global__ __launch_bounds__(256, 2)
void mma_tn(const __nv_bfloat16* __restrict__ Ah, const __nv_bfloat16* __restrict__ Al,
            const __nv_bfloat16* __restrict__ Bh, const __nv_bfloat16* __restrict__ Bl,
            const float* __restrict__ bias,
            float* __restrict__ Cf,
            __nv_bfloat16* __restrict__ Ch, __nv_bfloat16* __restrict__ Cl,
            int M, int N, int K, float alpha,
            long long sA, long long sB, long long sC) {
    extern __shared__ __nv_bfloat16 smbuf[];
    long long zb = blockIdx.z;
    Ah += zb * sA; Al += zb * sA;
    Bh += zb * sB; Bl += zb * sB;
    if (Cf) Cf += zb * sC;
    if (Ch) { Ch += zb * sC; Cl += zb * sC; }

    int tid = threadIdx.x;
    int lane = tid & 31, warp = tid >> 5;
    int wm = warp & 3, wn = warp >> 2;
    int brow = blockIdx.y * 128, bcol = blockIdx.x * 128;
    uint32_t sbase = cvta_s(smbuf);

    float acc[2][8][4];
    #pragma unroll
    for (int i = 0; i < 2; i++)
        #pragma unroll
        for (int j = 0; j < 8; j++)
            #pragma unroll
            for (int q = 0; q < 4; q++) acc[i][j][q] = 0.f;

    int ldrow = tid >> 1;            // 0..127
    int ldc0 = (tid & 1) * 2;        // chunks {0,1} or {2,3}

    auto load_stage = [&](int slot, int k0) {
        uint32_t so = sbase + (uint32_t)(slot * STGB);
        size_t ga = (size_t)(brow + ldrow) * K + k0;
        size_t gb = (size_t)(bcol + ldrow) * K + k0;
        #pragma unroll
        for (int cc = 0; cc < 2; cc++) {
            int c = ldc0 + cc;
            uint32_t off = swz(ldrow, c);
            cp16(so + 0 * PLB + off, Ah + ga + c * 8);
            cp16(so + 1 * PLB + off, Al + ga + c * 8);
            cp16(so + 2 * PLB + off, Bh + gb + c * 8);
            cp16(so + 3 * PLB + off, Bl + gb + c * 8);
        }
    };

    int nk = K >> 5;
    load_stage(0, 0);
    asm volatile("cp.async.commit_group;");
    load_stage(1, 32);
    asm volatile("cp.async.commit_group;");

    for (int kt = 0; kt < nk; kt++) {
        if (kt + 1 < nk) {
            asm volatile("cp.async.wait_group 1;");
        } else {
            asm volatile("cp.async.wait_group 0;");
        }
        __syncthreads();
        uint32_t so = sbase + (uint32_t)((kt % NSTAGE) * STGB);
        #pragma unroll
        for (int kk = 0; kk < 2; kk++) {
            // A fragments
            uint32_t ah[2][4], al[2][4];
            int arow = wm * 32 + ((lane >> 3) & 1) * 8 + (lane & 7);
            int akof = kk * 16 + (lane >> 4) * 8;
            int achk = akof >> 3;
            #pragma unroll
            for (int mt = 0; mt < 2; mt++) {
                uint32_t addr = so + swz(arow + mt * 16, achk);
                ldsm4(ah[mt][0], ah[mt][1], ah[mt][2], ah[mt][3], addr);
                ldsm4(al[mt][0], al[mt][1], al[mt][2], al[mt][3], addr + PLB);
            }
            // B fragments
            uint32_t bh[8][2], bl[8][2];
            int bphase = lane >> 3;
            int brl = wn * 64 + (lane & 7) + (bphase >> 1) * 8;
            int bkof = kk * 16 + (bphase & 1) * 8;
            int bchk = bkof >> 3;
            #pragma unroll
            for (int np = 0; np < 4; np++) {
                uint32_t addr = so + 2 * PLB + swz(brl + np * 16, bchk);
                uint32_t r0, r1, r2, r3;
                ldsm4(r0, r1, r2, r3, addr);
                bh[np * 2][0] = r0; bh[np * 2][1] = r1;
                bh[np * 2 + 1][0] = r2; bh[np * 2 + 1][1] = r3;
                ldsm4(r0, r1, r2, r3, addr + PLB);
                bl[np * 2][0] = r0; bl[np * 2][1] = r1;
                bl[np * 2 + 1][0] = r2; bl[np * 2 + 1][1] = r3;
            }
            #pragma unroll
            for (int mt = 0; mt < 2; mt++)
                #pragma unroll
                for (int nt = 0; nt < 8; nt++)
                    mma16816(acc[mt][nt], ah[mt], bh[nt]);
            #pragma unroll
            for (int mt = 0; mt < 2; mt++)
                #pragma unroll
                for (int nt = 0; nt < 8; nt++)
                    mma16816(acc[mt][nt], ah[mt], bl[nt]);
            #pragma unroll
            for (int mt = 0; mt < 2; mt++)
                #pragma unroll
                for (int nt = 0; nt < 8; nt++)
                    mma16816(acc[mt][nt], al[mt], bh[nt]);
        }
        // issue next-next stage AFTER compute; its slot was last read at kt-1,
        // protected by the __syncthreads at top of this iteration.
        if (kt + 2 < nk) {
            load_stage((kt + 2) % NSTAGE, (kt + 2) << 5);
            asm volatile("cp.async.commit_group;");
        }
    }

    // epilogue
    int gid = lane >> 2, tig = lane & 3;
    #pragma unroll
    for (int nt = 0; nt < 8; nt++) {
        int col = bcol + wn * 64 + nt * 8 + tig * 2;
        float b0 = bias ? bias[col] : 0.f;
        float b1 = bias ? bias[col + 1] : 0.f;
        #pragma unroll
        for (int mt = 0; mt < 2; mt++) {
            int row0 = brow + wm * 32 + mt * 16 + gid;
            float v00 = acc[mt][nt][0] * alpha + b0;
            float v01 = acc[mt][nt][1] * alpha + b1;
            float v10 = acc[mt][nt][2] * alpha + b0;
            float v11 = acc[mt][nt][3] * alpha + b1;
            if (Cf) {
                float2 p0 = {v00, v01}, p1 = {v10, v11};
                *(float2*)(Cf + (size_t)row0 * N + col) = p0;
                *(float2*)(Cf + (size_t)(row0 + 8) * N + col) = p1;
            }
            if (Ch) {
                __nv_bfloat16 h00 = __float2bfloat16_rn(v00);
                __nv_bfloat16 h01 = __float2bfloat16_rn(v01);
                __nv_bfloat16 h10 = __float2bfloat16_rn(v10);
                __nv_bfloat16 h11 = __float2bfloat16_rn(v11);
                __nv_bfloat162 hh0 = {h00, h01}, hh1 = {h10, h11};
                __nv_bfloat162 ll0 = {__float2bfloat16_rn(v00 - __bfloat162float(h00)),
                                      __float2bfloat16_rn(v01 - __bfloat162float(h01))};
                __nv_bfloat162 ll1 = {__float2bfloat16_rn(v10 - __bfloat162float(h10)),
                                      __float2bfloat16_rn(v11 - __bfloat162float(h11))};
                *(__nv_bfloat162*)(Ch + (size_t)row0 * N + col) = hh0;
                *(__nv_bfloat162*)(Cl + (size_t)row0 * N + col) = ll0;
                *(__nv_bfloat162*)(Ch + (size_t)(row0 + 8) * N + col) = hh1;
                *(__nv_bfloat162*)(Cl + (size_t)(row0 + 8) * N + col) = ll1;
            }
        }
    }
}

// ---------------- softmax rows of g_s -> split bf16 probs ----------------
__global__ void softmax_kernel() {
    size_t row = blockIdx.x;
    float4* p = (float4*)(g_s + row * Nn);
    int tid = threadIdx.x;
    float4 v[4];
    float mx = -1e30f;
    #pragma unroll
    for (int i = 0; i < 4; i++) {
        v[i] = p[tid + i * 256];
        mx = fmaxf(mx, fmaxf(fmaxf(v[i].x, v[i].y), fmaxf(v[i].z, v[i].w)));
    }
    __shared__ float sm[256];
    sm[tid] = mx; __syncthreads();
    for (int o = 128; o > 0; o >>= 1) {
        if (tid < o) sm[tid] = fmaxf(sm[tid], sm[tid + o]);
        __syncthreads();
    }
    mx = sm[0];
    __syncthreads();
    float s = 0.f;
    #pragma unroll
    for (int i = 0; i < 4; i++) {
        v[i].x = __expf(v[i].x - mx); v[i].y = __expf(v[i].y - mx);
        v[i].z = __expf(v[i].z - mx); v[i].w = __expf(v[i].w - mx);
        s += v[i].x + v[i].y + v[i].z + v[i].w;
    }
    sm[tid] = s; __syncthreads();
    for (int o = 128; o > 0; o >>= 1) {
        if (tid < o) sm[tid] += sm[tid + o];
        __syncthreads();
    }
    float inv = 1.f / sm[0];
    #pragma unroll
    for (int i = 0; i < 4; i++) {
        float e0 = v[i].x * inv, e1 = v[i].y * inv, e2 = v[i].z * inv, e3 = v[i].w * inv;
        size_t base = row * Nn + (size_t)(tid + i * 256) * 4;
        __nv_bfloat16 h0 = __float2bfloat16_rn(e0), h1 = __float2bfloat16_rn(e1);
        __nv_bfloat16 h2 = __float2bfloat16_rn(e2), h3 = __float2bfloat16_rn(e3);
        __nv_bfloat162 hh0 = {h0, h1}, hh1 = {h2, h3};
        __nv_bfloat162 ll0 = {__float2bfloat16_rn(e0 - __bfloat162float(h0)),
                              __float2bfloat16_rn(e1 - __bfloat162float(h1))};
        __nv_bfloat162 ll1 = {__float2bfloat16_rn(e2 - __bfloat162float(h2)),
                              __float2bfloat16_rn(e3 - __bfloat162float(h3))};
        ((__nv_bfloat162*)(g_ph + base))[0] = hh0;
        ((__nv_bfloat162*)(g_ph + base))[1] = hh1;
        ((__nv_bfloat162*)(g_pl + base))[0] = ll0;
        ((__nv_bfloat162*)(g_pl + base))[1] = ll1;
    }
}

// ---------------- residual ----------------
__global__ void residual_kernel(const float* __restrict__ x, float* __restrict__ out) {
    __shared__ float sm[32][33];
    int bz = blockIdx.z;
    int n0 = blockIdx.x * 32;
    int c0 = blockIdx.y * 32;
    int tx = threadIdx.x, ty = threadIdx.y;
    sm[ty][tx] = g_y[((size_t)bz * Nn + (n0 + ty)) * Cc + (c0 + tx)];
    __syncthreads();
    size_t idx = ((size_t)bz * Cc + (c0 + ty)) * Nn + (n0 + tx);
    out[idx] = x[idx] + sm[tx][ty];
}

// ---------------- launch ----------------
extern "C" void kernel_launch(void* const* d_in, const int* in_sizes, int n_in,
                              void* d_out, int out_size) {
    const float* x    = (const float*)d_in[0];
    const float* gn_w = (const float*)d_in[1];
    const float* gn_b = (const float*)d_in[2];
    const float* wq   = (const float*)d_in[3];
    const float* bq   = (const float*)d_in[4];
    const float* wk   = (const float*)d_in[5];
    const float* bk   = (const float*)d_in[6];
    const float* wv   = (const float*)d_in[7];
    const float* bv   = (const float*)d_in[8];
    const float* wo   = (const float*)d_in[9];
    const float* bo   = (const float*)d_in[10];
    float* out = (float*)d_out;

    __nv_bfloat16 *hh, *hl, *w4h, *w4l, *qh, *ql, *kh, *kl, *vth, *vtl, *ph, *pl, *aoh, *aol;
    float *v, *s, *y;
    cudaGetSymbolAddress((void**)&hh, g_hh);   cudaGetSymbolAddress((void**)&hl, g_hl);
    cudaGetSymbolAddress((void**)&w4h, g_w4h); cudaGetSymbolAddress((void**)&w4l, g_w4l);
    cudaGetSymbolAddress((void**)&qh, g_qh);   cudaGetSymbolAddress((void**)&ql, g_ql);
    cudaGetSymbolAddress((void**)&kh, g_kh);   cudaGetSymbolAddress((void**)&kl, g_kl);
    cudaGetSymbolAddress((void**)&vth, g_vth); cudaGetSymbolAddress((void**)&vtl, g_vtl);
    cudaGetSymbolAddress((void**)&ph, g_ph);   cudaGetSymbolAddress((void**)&pl, g_pl);
    cudaGetSymbolAddress((void**)&aoh, g_aoh); cudaGetSymbolAddress((void**)&aol, g_aol);
    cudaGetSymbolAddress((void**)&v, g_v);
    cudaGetSymbolAddress((void**)&s, g_s);
    cudaGetSymbolAddress((void**)&y, g_y);

    const int Mtot = Bb * Nn;                        // 32768
    const float scale = 0.044194173824159216f;       // 1/sqrt(512)
    const int WSZ = Cc * Cc;                         // 262144
    const int SMEM = NSTAGE * STGB;                  // 96 KB

    cudaFuncSetAttribute(mma_tn, cudaFuncAttributeMaxDynamicSharedMemorySize, SMEM);

    gn_stats_kernel<<<Bb * GROUPS, 256>>>(x);
    gn_apply_kernel<<<dim3(Nn / 32, Cc / 32, Bb), dim3(32, 32)>>>(x, gn_w, gn_b);
    split_kernel<<<WSZ / 256, 256>>>(wq, w4h + 0 * WSZ, w4l + 0 * WSZ);
    split_kernel<<<WSZ / 256, 256>>>(wk, w4h + 1 * WSZ, w4l + 1 * WSZ);
    split_kernel<<<WSZ / 256, 256>>>(wv, w4h + 2 * WSZ, w4l + 2 * WSZ);
    split_kernel<<<WSZ / 256, 256>>>(wo, w4h + 3 * WSZ, w4l + 3 * WSZ);

    dim3 gproj(Cc / 128, Mtot / 128, 1);
    mma_tn<<<gproj, 256, SMEM>>>(hh, hl, w4h + 0 * WSZ, w4l + 0 * WSZ, bq,
                                 nullptr, qh, ql, Mtot, Cc, Cc, 1.f, 0, 0, 0);
    mma_tn<<<gproj, 256, SMEM>>>(hh, hl, w4h + 1 * WSZ, w4l + 1 * WSZ, bk,
                                 nullptr, kh, kl, Mtot, Cc, Cc, 1.f, 0, 0, 0);
    mma_tn<<<gproj, 256, SMEM>>>(hh, hl, w4h + 2 * WSZ, w4l + 2 * WSZ, bv,
                                 v, nullptr, nullptr, Mtot, Cc, Cc, 1.f, 0, 0, 0);
    vtrans_kernel<<<dim3(Nn / 32, Cc / 32, Bb), dim3(32, 32)>>>();
    mma_tn<<<dim3(Nn / 128, Nn / 128, Bb), 256, SMEM>>>(qh, ql, kh, kl, nullptr,
                                 s, nullptr, nullptr, Nn, Nn, Cc, scale, NCs, NCs, NNs);
    softmax_kernel<<<Bb * Nn, 256>>>();
    mma_tn<<<dim3(Cc / 128, Nn / 128, Bb), 256, SMEM>>>(ph, pl, vth, vtl, nullptr,
                                 nullptr, aoh, aol, Nn, Cc, Nn, 1.f, NNs, NCs, NCs);
    mma_tn<<<gproj, 256, SMEM>>>(aoh, aol, w4h + 3 * WSZ, w4l + 3 * WSZ, bo,
                                 y, nullptr, nullptr, Mtot, Cc, Cc, 1.f, 0, 0, 0);
    residual_kernel<<<dim3(Nn / 32, Cc / 32, Bb), dim3(32, 32)>>>(x, out);
}

// round 8
// speedup vs baseline: 1.3526x; 1.0369x over previous
#include <cuda_runtime.h>
#include <cuda_bf16.h>
#include <math.h>
#include <stdint.h>

#define Cc 512
#define Bb 8
#define Nn 4096
#define GROUPS 8
#define EPS 1e-5f

#define MC ((size_t)Bb * Nn * Cc)
#define SC ((size_t)Bb * Nn * Nn)
#define NCs ((long long)Nn * Cc)
#define NNs ((long long)Nn * Nn)

// ---------------- scratch ----------------
__device__ __nv_bfloat16 g_hh[MC], g_hl[MC];
__device__ __nv_bfloat16 g_w4h[4 * Cc * Cc], g_w4l[4 * Cc * Cc];
__device__ __nv_bfloat16 g_qh[MC], g_ql[MC];
__device__ __nv_bfloat16 g_kh[MC], g_kl[MC];
__device__ float         g_v[MC];
__device__ __nv_bfloat16 g_vth[MC], g_vtl[MC];
__device__ float         g_s[SC];
__device__ __nv_bfloat16 g_ph[SC], g_pl[SC];
__device__ __nv_bfloat16 g_aoh[MC], g_aol[MC];
__device__ float         g_y[MC];
__device__ float         g_stats[Bb * GROUPS * 2];
__device__ float         g_part[512 * 2];

__device__ __forceinline__ void split_store(float v, __nv_bfloat16* ph, __nv_bfloat16* pl) {
    __nv_bfloat16 h = __float2bfloat16_rn(v);
    *ph = h;
    *pl = __float2bfloat16_rn(v - __bfloat162float(h));
}

// ---------------- 1) group-norm statistics (two-phase) ----------------
__global__ void gn_stats1_kernel(const float* __restrict__ x) {
    // 512 blocks: 8 per (b,g). Each covers 32768 elems.
    int blk = blockIdx.x;
    int bg = blk >> 3, sub = blk & 7;
    const size_t cnt = (size_t)(Cc / GROUPS) * Nn;       // 262144
    const float4* p = (const float4*)(x + (size_t)bg * cnt + (size_t)sub * (cnt / 8));
    int tid = threadIdx.x;
    float s = 0.f, sq = 0.f;
    #pragma unroll 4
    for (int i = tid; i < (int)(cnt / 8 / 4); i += 256) {
        float4 v = p[i];
        s  += v.x + v.y + v.z + v.w;
        sq += v.x * v.x + v.y * v.y + v.z * v.z + v.w * v.w;
    }
    int lane = tid & 31, warp = tid >> 5;
    #pragma unroll
    for (int o = 16; o > 0; o >>= 1) {
        s  += __shfl_xor_sync(~0u, s, o);
        sq += __shfl_xor_sync(~0u, sq, o);
    }
    __shared__ float ss[8], ssq[8];
    if (lane == 0) { ss[warp] = s; ssq[warp] = sq; }
    __syncthreads();
    if (tid == 0) {
        float ts = 0.f, tq = 0.f;
        #pragma unroll
        for (int j = 0; j < 8; j++) { ts += ss[j]; tq += ssq[j]; }
        g_part[blk * 2 + 0] = ts;
        g_part[blk * 2 + 1] = tq;
    }
}
__global__ void gn_stats2_kernel() {
    int bg = blockIdx.x * blockDim.x + threadIdx.x;   // 64 total
    if (bg >= Bb * GROUPS) return;
    const float cnt = (float)((Cc / GROUPS) * Nn);
    float s = 0.f, sq = 0.f;
    #pragma unroll
    for (int j = 0; j < 8; j++) {
        s  += g_part[(bg * 8 + j) * 2 + 0];
        sq += g_part[(bg * 8 + j) * 2 + 1];
    }
    float mu = s / cnt;
    float var = sq / cnt - mu * mu;
    g_stats[bg * 2 + 0] = mu;
    g_stats[bg * 2 + 1] = rsqrtf(var + EPS);
}

// ---------------- 2) GN apply + transpose -> split bf16 [B,N,C] ----------------
__global__ void gn_apply_kernel(const float* __restrict__ x,
                                const float* __restrict__ w,
                                const float* __restrict__ b) {
    __shared__ float sm[32][33];
    int bz = blockIdx.z;
    int n0 = blockIdx.x * 32;
    int c0 = blockIdx.y * 32;
    int tx = threadIdx.x, ty = threadIdx.y;
    {
        int c = c0 + ty, n = n0 + tx;
        int g = c >> 6;
        float mu   = g_stats[(bz * GROUPS + g) * 2 + 0];
        float rstd = g_stats[(bz * GROUPS + g) * 2 + 1];
        float v = x[((size_t)bz * Cc + c) * Nn + n];
        sm[ty][tx] = (v - mu) * rstd * w[c] + b[c];
    }
    __syncthreads();
    {
        int n = n0 + ty, c = c0 + tx;
        size_t idx = ((size_t)bz * Nn + n) * Cc + c;
        split_store(sm[tx][ty], g_hh + idx, g_hl + idx);
    }
}

__global__ void split_kernel(const float* __restrict__ src,
                             __nv_bfloat16* __restrict__ dh,
                             __nv_bfloat16* __restrict__ dl) {
    int i = (blockIdx.x * 256 + threadIdx.x) * 4;
    float4 v = *(const float4*)(src + i);
    __nv_bfloat16 h0 = __float2bfloat16_rn(v.x), h1 = __float2bfloat16_rn(v.y);
    __nv_bfloat16 h2 = __float2bfloat16_rn(v.z), h3 = __float2bfloat16_rn(v.w);
    __nv_bfloat162 hh0 = {h0, h1}, hh1 = {h2, h3};
    __nv_bfloat162 ll0 = {__float2bfloat16_rn(v.x - __bfloat162float(h0)),
                          __float2bfloat16_rn(v.y - __bfloat162float(h1))};
    __nv_bfloat162 ll1 = {__float2bfloat16_rn(v.z - __bfloat162float(h2)),
                          __float2bfloat16_rn(v.w - __bfloat162float(h3))};
    ((__nv_bfloat162*)(dh + i))[0] = hh0;
    ((__nv_bfloat162*)(dh + i))[1] = hh1;
    ((__nv_bfloat162*)(dl + i))[0] = ll0;
    ((__nv_bfloat162*)(dl + i))[1] = ll1;
}

__global__ void vtrans_kernel() {
    __shared__ float sm[32][33];
    int bz = blockIdx.z;
    int m0 = blockIdx.x * 32;
    int d0 = blockIdx.y * 32;
    int tx = threadIdx.x, ty = threadIdx.y;
    sm[ty][tx] = g_v[((size_t)bz * Nn + (m0 + ty)) * Cc + (d0 + tx)];
    __syncthreads();
    size_t idx = ((size_t)bz * Cc + (d0 + ty)) * Nn + (m0 + tx);
    split_store(sm[tx][ty], g_vth + idx, g_vtl + idx);
}

// ---------------- tensor-core TN GEMM machinery ----------------
#define PLB 8192                 // bytes per plane (128 rows * 64B)
#define STGB (4 * PLB)           // 32 KB per stage
#define NSTAGE 3

__device__ __forceinline__ uint32_t cvta_s(const void* p) {
    return (uint32_t)__cvta_generic_to_shared(p);
}
__device__ __forceinline__ void cp16(uint32_t s, const void* g) {
    asm volatile("cp.async.cg.shared.global [%0], [%1], 16;" :: "r"(s), "l"(g));
}
__device__ __forceinline__ void ldsm4(uint32_t& r0, uint32_t& r1, uint32_t& r2, uint32_t& r3, uint32_t a) {
    asm volatile("ldmatrix.sync.aligned.m8n8.x4.shared.b16 {%0,%1,%2,%3}, [%4];"
                 : "=r"(r0), "=r"(r1), "=r"(r2), "=r"(r3) : "r"(a));
}
__device__ __forceinline__ void mma16816(float* c, const uint32_t* a, const uint32_t* b) {
    asm volatile("mma.sync.aligned.m16n8k16.row.col.f32.bf16.bf16.f32 "
                 "{%0,%1,%2,%3},{%4,%5,%6,%7},{%8,%9},{%0,%1,%2,%3};"
                 : "+f"(c[0]), "+f"(c[1]), "+f"(c[2]), "+f"(c[3])
                 : "r"(a[0]), "r"(a[1]), "r"(a[2]), "r"(a[3]), "r"(b[0]), "r"(b[1]));
}
__device__ __forceinline__ uint32_t swz(int row, int chunk) {
    return (uint32_t)(row * 64 + ((chunk ^ ((row >> 1) & 3)) << 4));
}

// Shared mainloop: fills acc[2][8][4] for this warp's 32x64 tile.
__device__ __forceinline__ void gemm_mainloop(
    const __nv_bfloat16* Ah, const __nv_bfloat16* Al,
    const __nv_bfloat16* Bh, const __nv_bfloat16* Bl,
    int brow, int bcol, int K, uint32_t sbase,
    int tid, int lane, int wm, int wn,
    float acc[2][8][4]) {

    int ldrow = tid >> 1;
    int ldc0 = (tid & 1) * 2;

    auto load_stage = [&](int slot, int k0) {
        uint32_t so = sbase + (uint32_t)(slot * STGB);
        size_t ga = (size_t)(brow + ldrow) * K + k0;
        size_t gb = (size_t)(bcol + ldrow) * K + k0;
        #pragma unroll
        for (int cc = 0; cc < 2; cc++) {
            int c = ldc0 + cc;
            uint32_t off = swz(ldrow, c);
            cp16(so + 0 * PLB + off, Ah + ga + c * 8);
            cp16(so + 1 * PLB + off, Al + ga + c * 8);
            cp16(so + 2 * PLB + off, Bh + gb + c * 8);
            cp16(so + 3 * PLB + off, Bl + gb + c * 8);
        }
    };

    int nk = K >> 5;
    load_stage(0, 0);
    asm volatile("cp.async.commit_group;");
    load_stage(1, 32);
    asm volatile("cp.async.commit_group;");

    for (int kt = 0; kt < nk; kt++) {
        if (kt + 1 < nk) {
            asm volatile("cp.async.wait_group 1;");
        } else {
            asm volatile("cp.async.wait_group 0;");
        }
        __syncthreads();
        uint32_t so = sbase + (uint32_t)((kt % NSTAGE) * STGB);
        #pragma unroll
        for (int kk = 0; kk < 2; kk++) {
            uint32_t ah[2][4], al[2][4];
            int arow = wm * 32 + ((lane >> 3) & 1) * 8 + (lane & 7);
            int akof = kk * 16 + (lane >> 4) * 8;
            int achk = akof >> 3;
            #pragma unroll
            for (int mt = 0; mt < 2; mt++) {
                uint32_t addr = so + swz(arow + mt * 16, achk);
                ldsm4(ah[mt][0], ah[mt][1], ah[mt][2], ah[mt][3], addr);
                ldsm4(al[mt][0], al[mt][1], al[mt][2], al[mt][3], addr + PLB);
            }
            uint32_t bh[8][2], bl[8][2];
            int bphase = lane >> 3;
            int brl = wn * 64 + (lane & 7) + (bphase >> 1) * 8;
            int bkof = kk * 16 + (bphase & 1) * 8;
            int bchk = bkof >> 3;
            #pragma unroll
            for (int np = 0; np < 4; np++) {
                uint32_t addr = so + 2 * PLB + swz(brl + np * 16, bchk);
                uint32_t r0, r1, r2, r3;
                ldsm4(r0, r1, r2, r3, addr);
                bh[np * 2][0] = r0; bh[np * 2][1] = r1;
                bh[np * 2 + 1][0] = r2; bh[np * 2 + 1][1] = r3;
                ldsm4(r0, r1, r2, r3, addr + PLB);
                bl[np * 2][0] = r0; bl[np * 2][1] = r1;
                bl[np * 2 + 1][0] = r2; bl[np * 2 + 1][1] = r3;
            }
            #pragma unroll
            for (int mt = 0; mt < 2; mt++)
                #pragma unroll
                for (int nt = 0; nt < 8; nt++)
                    mma16816(acc[mt][nt], ah[mt], bh[nt]);
            #pragma unroll
            for (int mt = 0; mt < 2; mt++)
                #pragma unroll
                for (int nt = 0; nt < 8; nt++)
                    mma16816(acc[mt][nt], ah[mt], bl[nt]);
            #pragma unroll
            for (int mt = 0; mt < 2; mt++)
                #pragma unroll
                for (int nt = 0; nt < 8; nt++)
                    mma16816(acc[mt][nt], al[mt], bh[nt]);
        }
        if (kt + 2 < nk) {
            load_stage((kt + 2) % NSTAGE, (kt + 2) << 5);
            asm volatile("cp.async.commit_group;");
        }
    }
}

// generic TN GEMM (fp32 out and/or split bf16 out)
__global__ __launch_bounds__(256, 2)
void mma_tn(const __nv_bfloat16* __restrict__ Ah, const __nv_bfloat16* __restrict__ Al,
            const __nv_bfloat16* __restrict__ Bh, const __nv_bfloat16* __restrict__ Bl,
            const float* __restrict__ bias,
            float* __restrict__ Cf,
            __nv_bfloat16* __restrict__ Ch, __nv_bfloat16* __restrict__ Cl,
            int M, int N, int K, float alpha,
            long long sA, long long sB, long long sC) {
    extern __shared__ __nv_bfloat16 smbuf[];
    long long zb = blockIdx.z;
    Ah += zb * sA; Al += zb * sA;
    Bh += zb * sB; Bl += zb * sB;
    if (Cf) Cf += zb * sC;
    if (Ch) { Ch += zb * sC; Cl += zb * sC; }

    int tid = threadIdx.x;
    int lane = tid & 31, warp = tid >> 5;
    int wm = warp & 3, wn = warp >> 2;
    int brow = blockIdx.y * 128, bcol = blockIdx.x * 128;
    uint32_t sbase = cvta_s(smbuf);

    float acc[2][8][4];
    #pragma unroll
    for (int i = 0; i < 2; i++)
        #pragma unroll
        for (int j = 0; j < 8; j++)
            #pragma unroll
            for (int q = 0; q < 4; q++) acc[i][j][q] = 0.f;

    gemm_mainloop(Ah, Al, Bh, Bl, brow, bcol, K, sbase, tid, lane, wm, wn, acc);

    int gid = lane >> 2, tig = lane & 3;
    #pragma unroll
    for (int nt = 0; nt < 8; nt++) {
        int col = bcol + wn * 64 + nt * 8 + tig * 2;
        float b0 = bias ? bias[col] : 0.f;
        float b1 = bias ? bias[col + 1] : 0.f;
        #pragma unroll
        for (int mt = 0; mt < 2; mt++) {
            int row0 = brow + wm * 32 + mt * 16 + gid;
            float v00 = acc[mt][nt][0] * alpha + b0;
            float v01 = acc[mt][nt][1] * alpha + b1;
            float v10 = acc[mt][nt][2] * alpha + b0;
            float v11 = acc[mt][nt][3] * alpha + b1;
            if (Cf) {
                float2 p0 = {v00, v01}, p1 = {v10, v11};
                *(float2*)(Cf + (size_t)row0 * N + col) = p0;
                *(float2*)(Cf + (size_t)(row0 + 8) * N + col) = p1;
            }
            if (Ch) {
                __nv_bfloat16 h00 = __float2bfloat16_rn(v00);
                __nv_bfloat16 h01 = __float2bfloat16_rn(v01);
                __nv_bfloat16 h10 = __float2bfloat16_rn(v10);
                __nv_bfloat16 h11 = __float2bfloat16_rn(v11);
                __nv_bfloat162 hh0 = {h00, h01}, hh1 = {h10, h11};
                __nv_bfloat162 ll0 = {__float2bfloat16_rn(v00 - __bfloat162float(h00)),
                                      __float2bfloat16_rn(v01 - __bfloat162float(h01))};
                __nv_bfloat162 ll1 = {__float2bfloat16_rn(v10 - __bfloat162float(h10)),
                                      __float2bfloat16_rn(v11 - __bfloat162float(h11))};
                *(__nv_bfloat162*)(Ch + (size_t)row0 * N + col) = hh0;
                *(__nv_bfloat162*)(Cl + (size_t)row0 * N + col) = ll0;
                *(__nv_bfloat162*)(Ch + (size_t)(row0 + 8) * N + col) = hh1;
                *(__nv_bfloat162*)(Cl + (size_t)(row0 + 8) * N + col) = ll1;
            }
        }
    }
}

// fused QKV projection: B = concat(wq,wk,wv) split planes [1536, 512].
// Output section by bcol: 0->q split, 1->k split, 2->v fp32.
__global__ __launch_bounds__(256, 2)
void mma_qkv(const __nv_bfloat16* __restrict__ Ah, const __nv_bfloat16* __restrict__ Al,
             const __nv_bfloat16* __restrict__ Bh, const __nv_bfloat16* __restrict__ Bl,
             const float* __restrict__ bq, const float* __restrict__ bk,
             const float* __restrict__ bv,
             float* __restrict__ Vout,
             __nv_bfloat16* __restrict__ Qh, __nv_bfloat16* __restrict__ Ql,
             __nv_bfloat16* __restrict__ Kh, __nv_bfloat16* __restrict__ Kl,
             int K) {
    extern __shared__ __nv_bfloat16 smbuf[];
    int tid = threadIdx.x;
    int lane = tid & 31, warp = tid >> 5;
    int wm = warp & 3, wn = warp >> 2;
    int brow = blockIdx.y * 128, bcol = blockIdx.x * 128;
    uint32_t sbase = cvta_s(smbuf);

    float acc[2][8][4];
    #pragma unroll
    for (int i = 0; i < 2; i++)
        #pragma unroll
        for (int j = 0; j < 8; j++)
            #pragma unroll
            for (int q = 0; q < 4; q++) acc[i][j][q] = 0.f;

    gemm_mainloop(Ah, Al, Bh, Bl, brow, bcol, K, sbase, tid, lane, wm, wn, acc);

    int sec = bcol >> 9;            // 0=q 1=k 2=v
    int colbase = bcol & 511;
    const float* bias = (sec == 0) ? bq : (sec == 1) ? bk : bv;
    __nv_bfloat16* Ch = (sec == 0) ? Qh : (sec == 1) ? Kh : nullptr;
    __nv_bfloat16* Cl = (sec == 0) ? Ql : Kl;

    int gid = lane >> 2, tig = lane & 3;
    #pragma unroll
    for (int nt = 0; nt < 8; nt++) {
        int col = colbase + wn * 64 + nt * 8 + tig * 2;
        float b0 = bias[col], b1 = bias[col + 1];
        #pragma unroll
        for (int mt = 0; mt < 2; mt++) {
            int row0 = brow + wm * 32 + mt * 16 + gid;
            float v00 = acc[mt][nt][0] + b0;
            float v01 = acc[mt][nt][1] + b1;
            float v10 = acc[mt][nt][2] + b0;
            float v11 = acc[mt][nt][3] + b1;
            if (sec == 2) {
                float2 p0 = {v00, v01}, p1 = {v10, v11};
                *(float2*)(Vout + (size_t)row0 * Cc + col) = p0;
                *(float2*)(Vout + (size_t)(row0 + 8) * Cc + col) = p1;
            } else {
                __nv_bfloat16 h00 = __float2bfloat16_rn(v00);
                __nv_bfloat16 h01 = __float2bfloat16_rn(v01);
                __nv_bfloat16 h10 = __float2bfloat16_rn(v10);
                __nv_bfloat16 h11 = __float2bfloat16_rn(v11);
                __nv_bfloat162 hh0 = {h00, h01}, hh1 = {h10, h11};
                __nv_bfloat162 ll0 = {__float2bfloat16_rn(v00 - __bfloat162float(h00)),
                                      __float2bfloat16_rn(v01 - __bfloat162float(h01))};
                __nv_bfloat162 ll1 = {__float2bfloat16_rn(v10 - __bfloat162float(h10)),
                                      __float2bfloat16_rn(v11 - __bfloat162float(h11))};
                *(__nv_bfloat162*)(Ch + (size_t)row0 * Cc + col) = hh0;
                *(__nv_bfloat162*)(Cl + (size_t)row0 * Cc + col) = ll0;
                *(__nv_bfloat162*)(Ch + (size_t)(row0 + 8) * Cc + col) = hh1;
                *(__nv_bfloat162*)(Cl + (size_t)(row0 + 8) * Cc + col) = ll1;
            }
        }
    }
}

// ---------------- softmax rows of g_s -> split bf16 probs ----------------
__global__ void softmax_kernel() {
    size_t row = blockIdx.x;
    float4* p = (float4*)(g_s + row * Nn);
    int tid = threadIdx.x;
    int lane = tid & 31, warp = tid >> 5;
    __shared__ float sm1[8], sm2[8];
    float4 v[4];
    float mx = -1e30f;
    #pragma unroll
    for (int i = 0; i < 4; i++) {
        v[i] = p[tid + i * 256];
        mx = fmaxf(mx, fmaxf(fmaxf(v[i].x, v[i].y), fmaxf(v[i].z, v[i].w)));
    }
    #pragma unroll
    for (int o = 16; o > 0; o >>= 1) mx = fmaxf(mx, __shfl_xor_sync(~0u, mx, o));
    if (lane == 0) sm1[warp] = mx;
    __syncthreads();
    mx = sm1[0];
    #pragma unroll
    for (int j = 1; j < 8; j++) mx = fmaxf(mx, sm1[j]);

    float s = 0.f;
    #pragma unroll
    for (int i = 0; i < 4; i++) {
        v[i].x = __expf(v[i].x - mx); v[i].y = __expf(v[i].y - mx);
        v[i].z = __expf(v[i].z - mx); v[i].w = __expf(v[i].w - mx);
        s += v[i].x + v[i].y + v[i].z + v[i].w;
    }
    #pragma unroll
    for (int o = 16; o > 0; o >>= 1) s += __shfl_xor_sync(~0u, s, o);
    if (lane == 0) sm2[warp] = s;
    __syncthreads();
    s = 0.f;
    #pragma unroll
    for (int j = 0; j < 8; j++) s += sm2[j];
    float inv = 1.f / s;

    #pragma unroll
    for (int i = 0; i < 4; i++) {
        float e0 = v[i].x * inv, e1 = v[i].y * inv, e2 = v[i].z * inv, e3 = v[i].w * inv;
        size_t base = row * Nn + (size_t)(tid + i * 256) * 4;
        __nv_bfloat16 h0 = __float2bfloat16_rn(e0), h1 = __float2bfloat16_rn(e1);
        __nv_bfloat16 h2 = __float2bfloat16_rn(e2), h3 = __float2bfloat16_rn(e3);
        __nv_bfloat162 hh0 = {h0, h1}, hh1 = {h2, h3};
        __nv_bfloat162 ll0 = {__float2bfloat16_rn(e0 - __bfloat162float(h0)),
                              __float2bfloat16_rn(e1 - __bfloat162float(h1))};
        __nv_bfloat162 ll1 = {__float2bfloat16_rn(e2 - __bfloat162float(h2)),
                              __float2bfloat16_rn(e3 - __bfloat162float(h3))};
        ((__nv_bfloat162*)(g_ph + base))[0] = hh0;
        ((__nv_bfloat162*)(g_ph + base))[1] = hh1;
        ((__nv_bfloat162*)(g_pl + base))[0] = ll0;
        ((__nv_bfloat162*)(g_pl + base))[1] = ll1;
    }
}

// ---------------- residual ----------------
__global__ void residual_kernel(const float* __restrict__ x, float* __restrict__ out) {
    __shared__ float sm[32][33];
    int bz = blockIdx.z;
    int n0 = blockIdx.x * 32;
    int c0 = blockIdx.y * 32;
    int tx = threadIdx.x, ty = threadIdx.y;
    sm[ty][tx] = g_y[((size_t)bz * Nn + (n0 + ty)) * Cc + (c0 + tx)];
    __syncthreads();
    size_t idx = ((size_t)bz * Cc + (c0 + ty)) * Nn + (n0 + tx);
    out[idx] = x[idx] + sm[tx][ty];
}

// ---------------- launch ----------------
extern "C" void kernel_launch(void* const* d_in, const int* in_sizes, int n_in,
                              void* d_out, int out_size) {
    const float* x    = (const float*)d_in[0];
    const float* gn_w = (const float*)d_in[1];
    const float* gn_b = (const float*)d_in[2];
    const float* wq   = (const float*)d_in[3];
    const float* bq   = (const float*)d_in[4];
    const float* wk   = (const float*)d_in[5];
    const float* bk   = (const float*)d_in[6];
    const float* wv   = (const float*)d_in[7];
    const float* bv   = (const float*)d_in[8];
    const float* wo   = (const float*)d_in[9];
    const float* bo   = (const float*)d_in[10];
    float* out = (float*)d_out;

    __nv_bfloat16 *hh, *hl, *w4h, *w4l, *qh, *ql, *kh, *kl, *vth, *vtl, *ph, *pl, *aoh, *aol;
    float *v, *s, *y;
    cudaGetSymbolAddress((void**)&hh, g_hh);   cudaGetSymbolAddress((void**)&hl, g_hl);
    cudaGetSymbolAddress((void**)&w4h, g_w4h); cudaGetSymbolAddress((void**)&w4l, g_w4l);
    cudaGetSymbolAddress((void**)&qh, g_qh);   cudaGetSymbolAddress((void**)&ql, g_ql);
    cudaGetSymbolAddress((void**)&kh, g_kh);   cudaGetSymbolAddress((void**)&kl, g_kl);
    cudaGetSymbolAddress((void**)&vth, g_vth); cudaGetSymbolAddress((void**)&vtl, g_vtl);
    cudaGetSymbolAddress((void**)&ph, g_ph);   cudaGetSymbolAddress((void**)&pl, g_pl);
    cudaGetSymbolAddress((void**)&aoh, g_aoh); cudaGetSymbolAddress((void**)&aol, g_aol);
    cudaGetSymbolAddress((void**)&v, g_v);
    cudaGetSymbolAddress((void**)&s, g_s);
    cudaGetSymbolAddress((void**)&y, g_y);

    const int Mtot = Bb * Nn;                        // 32768
    const float scale = 0.044194173824159216f;       // 1/sqrt(512)
    const int WSZ = Cc * Cc;                         // 262144
    const int SMEM = NSTAGE * STGB;                  // 96 KB

    cudaFuncSetAttribute(mma_tn, cudaFuncAttributeMaxDynamicSharedMemorySize, SMEM);
    cudaFuncSetAttribute(mma_qkv, cudaFuncAttributeMaxDynamicSharedMemorySize, SMEM);

    gn_stats1_kernel<<<512, 256>>>(x);
    gn_stats2_kernel<<<2, 32>>>();
    gn_apply_kernel<<<dim3(Nn / 32, Cc / 32, Bb), dim3(32, 32)>>>(x, gn_w, gn_b);
    split_kernel<<<WSZ / 1024, 256>>>(wq, w4h + 0 * WSZ, w4l + 0 * WSZ);
    split_kernel<<<WSZ / 1024, 256>>>(wk, w4h + 1 * WSZ, w4l + 1 * WSZ);
    split_kernel<<<WSZ / 1024, 256>>>(wv, w4h + 2 * WSZ, w4l + 2 * WSZ);
    split_kernel<<<WSZ / 1024, 256>>>(wo, w4h + 3 * WSZ, w4l + 3 * WSZ);

    // fused QKV projection: grid (1536/128, 32768/128)
    mma_qkv<<<dim3(12, Mtot / 128), 256, SMEM>>>(hh, hl, w4h, w4l,
                                                 bq, bk, bv, v, qh, ql, kh, kl, Cc);
    vtrans_kernel<<<dim3(Nn / 32, Cc / 32, Bb), dim3(32, 32)>>>();
    mma_tn<<<dim3(Nn / 128, Nn / 128, Bb), 256, SMEM>>>(qh, ql, kh, kl, nullptr,
                                 s, nullptr, nullptr, Nn, Nn, Cc, scale, NCs, NCs, NNs);
    softmax_kernel<<<Bb * Nn, 256>>>();
    mma_tn<<<dim3(Cc / 128, Nn / 128, Bb), 256, SMEM>>>(ph, pl, vth, vtl, nullptr,
                                 nullptr, aoh, aol, Nn, Cc, Nn, 1.f, NNs, NCs, NCs);
    mma_tn<<<dim3(Cc / 128, Mtot / 128), 256, SMEM>>>(aoh, aol, w4h + 3 * WSZ, w4l + 3 * WSZ, bo,
                                 y, nullptr, nullptr, Mtot, Cc, Cc, 1.f, 0, 0, 0);
    residual_kernel<<<dim3(Nn / 32, Cc / 32, Bb), dim3(32, 32)>>>(x, out);
}

// round 9
// speedup vs baseline: 1.3655x; 1.0095x over previous
#include <cuda_runtime.h>
#include <cuda_bf16.h>
#include <math.h>
#include <stdint.h>

#define Cc 512
#define Bb 8
#define Nn 4096
#define GROUPS 8
#define EPS 1e-5f

#define MC ((size_t)Bb * Nn * Cc)
#define SC ((size_t)Bb * Nn * Nn)
#define NCs ((long long)Nn * Cc)
#define NNs ((long long)Nn * Nn)

// ---------------- scratch ----------------
__device__ __nv_bfloat16 g_hh[MC], g_hl[MC];
__device__ __nv_bfloat16 g_w4h[4 * Cc * Cc], g_w4l[4 * Cc * Cc];
__device__ __nv_bfloat16 g_qh[MC], g_ql[MC];
__device__ __nv_bfloat16 g_kh[MC], g_kl[MC];
__device__ __nv_bfloat16 g_vth[MC], g_vtl[MC];
__device__ float         g_s[SC];
__device__ __nv_bfloat16 g_ph[SC], g_pl[SC];
__device__ __nv_bfloat16 g_aoh[MC], g_aol[MC];
__device__ float         g_stats[Bb * GROUPS * 2];
__device__ float         g_part[512 * 2];

__device__ __forceinline__ void split_store(float v, __nv_bfloat16* ph, __nv_bfloat16* pl) {
    __nv_bfloat16 h = __float2bfloat16_rn(v);
    *ph = h;
    *pl = __float2bfloat16_rn(v - __bfloat162float(h));
}

// ---------------- 1) group-norm statistics (two-phase) ----------------
__global__ void gn_stats1_kernel(const float* __restrict__ x) {
    int blk = blockIdx.x;
    int bg = blk >> 3, sub = blk & 7;
    const size_t cnt = (size_t)(Cc / GROUPS) * Nn;
    const float4* p = (const float4*)(x + (size_t)bg * cnt + (size_t)sub * (cnt / 8));
    int tid = threadIdx.x;
    float s = 0.f, sq = 0.f;
    #pragma unroll 4
    for (int i = tid; i < (int)(cnt / 8 / 4); i += 256) {
        float4 v = p[i];
        s  += v.x + v.y + v.z + v.w;
        sq += v.x * v.x + v.y * v.y + v.z * v.z + v.w * v.w;
    }
    int lane = tid & 31, warp = tid >> 5;
    #pragma unroll
    for (int o = 16; o > 0; o >>= 1) {
        s  += __shfl_xor_sync(~0u, s, o);
        sq += __shfl_xor_sync(~0u, sq, o);
    }
    __shared__ float ss[8], ssq[8];
    if (lane == 0) { ss[warp] = s; ssq[warp] = sq; }
    __syncthreads();
    if (tid == 0) {
        float ts = 0.f, tq = 0.f;
        #pragma unroll
        for (int j = 0; j < 8; j++) { ts += ss[j]; tq += ssq[j]; }
        g_part[blk * 2 + 0] = ts;
        g_part[blk * 2 + 1] = tq;
    }
}
__global__ void gn_stats2_kernel() {
    int bg = blockIdx.x * blockDim.x + threadIdx.x;
    if (bg >= Bb * GROUPS) return;
    const float cnt = (float)((Cc / GROUPS) * Nn);
    float s = 0.f, sq = 0.f;
    #pragma unroll
    for (int j = 0; j < 8; j++) {
        s  += g_part[(bg * 8 + j) * 2 + 0];
        sq += g_part[(bg * 8 + j) * 2 + 1];
    }
    float mu = s / cnt;
    float var = sq / cnt - mu * mu;
    g_stats[bg * 2 + 0] = mu;
    g_stats[bg * 2 + 1] = rsqrtf(var + EPS);
}

// ---------------- 2) GN apply + transpose -> split bf16 [B,N,C] ----------------
__global__ void gn_apply_kernel(const float* __restrict__ x,
                                const float* __restrict__ w,
                                const float* __restrict__ b) {
    __shared__ float sm[32][33];
    int bz = blockIdx.z;
    int n0 = blockIdx.x * 32;
    int c0 = blockIdx.y * 32;
    int tx = threadIdx.x, ty = threadIdx.y;
    {
        int c = c0 + ty, n = n0 + tx;
        int g = c >> 6;
        float mu   = g_stats[(bz * GROUPS + g) * 2 + 0];
        float rstd = g_stats[(bz * GROUPS + g) * 2 + 1];
        float v = x[((size_t)bz * Cc + c) * Nn + n];
        sm[ty][tx] = (v - mu) * rstd * w[c] + b[c];
    }
    __syncthreads();
    {
        int n = n0 + ty, c = c0 + tx;
        size_t idx = ((size_t)bz * Nn + n) * Cc + c;
        split_store(sm[tx][ty], g_hh + idx, g_hl + idx);
    }
}

__global__ void split_kernel(const float* __restrict__ src,
                             __nv_bfloat16* __restrict__ dh,
                             __nv_bfloat16* __restrict__ dl) {
    int i = (blockIdx.x * 256 + threadIdx.x) * 4;
    float4 v = *(const float4*)(src + i);
    __nv_bfloat16 h0 = __float2bfloat16_rn(v.x), h1 = __float2bfloat16_rn(v.y);
    __nv_bfloat16 h2 = __float2bfloat16_rn(v.z), h3 = __float2bfloat16_rn(v.w);
    __nv_bfloat162 hh0 = {h0, h1}, hh1 = {h2, h3};
    __nv_bfloat162 ll0 = {__float2bfloat16_rn(v.x - __bfloat162float(h0)),
                          __float2bfloat16_rn(v.y - __bfloat162float(h1))};
    __nv_bfloat162 ll1 = {__float2bfloat16_rn(v.z - __bfloat162float(h2)),
                          __float2bfloat16_rn(v.w - __bfloat162float(h3))};
    ((__nv_bfloat162*)(dh + i))[0] = hh0;
    ((__nv_bfloat162*)(dh + i))[1] = hh1;
    ((__nv_bfloat162*)(dl + i))[0] = ll0;
    ((__nv_bfloat162*)(dl + i))[1] = ll1;
}

// ---------------- tensor-core TN GEMM machinery ----------------
#define PLB 8192
#define STGB (4 * PLB)
#define NSTAGE 3
#define TPITCH 129            // fp32 transpose buffer pitch

__device__ __forceinline__ uint32_t cvta_s(const void* p) {
    return (uint32_t)__cvta_generic_to_shared(p);
}
__device__ __forceinline__ void cp16(uint32_t s, const void* g) {
    asm volatile("cp.async.cg.shared.global [%0], [%1], 16;" :: "r"(s), "l"(g));
}
__device__ __forceinline__ void ldsm4(uint32_t& r0, uint32_t& r1, uint32_t& r2, uint32_t& r3, uint32_t a) {
    asm volatile("ldmatrix.sync.aligned.m8n8.x4.shared.b16 {%0,%1,%2,%3}, [%4];"
                 : "=r"(r0), "=r"(r1), "=r"(r2), "=r"(r3) : "r"(a));
}
__device__ __forceinline__ void mma16816(float* c, const uint32_t* a, const uint32_t* b) {
    asm volatile("mma.sync.aligned.m16n8k16.row.col.f32.bf16.bf16.f32 "
                 "{%0,%1,%2,%3},{%4,%5,%6,%7},{%8,%9},{%0,%1,%2,%3};"
                 : "+f"(c[0]), "+f"(c[1]), "+f"(c[2]), "+f"(c[3])
                 : "r"(a[0]), "r"(a[1]), "r"(a[2]), "r"(a[3]), "r"(b[0]), "r"(b[1]));
}
__device__ __forceinline__ uint32_t swz(int row, int chunk) {
    return (uint32_t)(row * 64 + ((chunk ^ ((row >> 1) & 3)) << 4));
}

__device__ __forceinline__ void gemm_mainloop(
    const __nv_bfloat16* Ah, const __nv_bfloat16* Al,
    const __nv_bfloat16* Bh, const __nv_bfloat16* Bl,
    int brow, int bcol, int K, uint32_t sbase,
    int tid, int lane, int wm, int wn,
    float acc[2][8][4]) {

    int ldrow = tid >> 1;
    int ldc0 = (tid & 1) * 2;

    auto load_stage = [&](int slot, int k0) {
        uint32_t so = sbase + (uint32_t)(slot * STGB);
        size_t ga = (size_t)(brow + ldrow) * K + k0;
        size_t gb = (size_t)(bcol + ldrow) * K + k0;
        #pragma unroll
        for (int cc = 0; cc < 2; cc++) {
            int c = ldc0 + cc;
            uint32_t off = swz(ldrow, c);
            cp16(so + 0 * PLB + off, Ah + ga + c * 8);
            cp16(so + 1 * PLB + off, Al + ga + c * 8);
            cp16(so + 2 * PLB + off, Bh + gb + c * 8);
            cp16(so + 3 * PLB + off, Bl + gb + c * 8);
        }
    };

    int nk = K >> 5;
    load_stage(0, 0);
    asm volatile("cp.async.commit_group;");
    load_stage(1, 32);
    asm volatile("cp.async.commit_group;");

    for (int kt = 0; kt < nk; kt++) {
        if (kt + 1 < nk) {
            asm volatile("cp.async.wait_group 1;");
        } else {
            asm volatile("cp.async.wait_group 0;");
        }
        __syncthreads();
        uint32_t so = sbase + (uint32_t)((kt % NSTAGE) * STGB);
        #pragma unroll
        for (int kk = 0; kk < 2; kk++) {
            uint32_t ah[2][4], al[2][4];
            int arow = wm * 32 + ((lane >> 3) & 1) * 8 + (lane & 7);
            int akof = kk * 16 + (lane >> 4) * 8;
            int achk = akof >> 3;
            #pragma unroll
            for (int mt = 0; mt < 2; mt++) {
                uint32_t addr = so + swz(arow + mt * 16, achk);
                ldsm4(ah[mt][0], ah[mt][1], ah[mt][2], ah[mt][3], addr);
                ldsm4(al[mt][0], al[mt][1], al[mt][2], al[mt][3], addr + PLB);
            }
            uint32_t bh[8][2], bl[8][2];
            int bphase = lane >> 3;
            int brl = wn * 64 + (lane & 7) + (bphase >> 1) * 8;
            int bkof = kk * 16 + (bphase & 1) * 8;
            int bchk = bkof >> 3;
            #pragma unroll
            for (int np = 0; np < 4; np++) {
                uint32_t addr = so + 2 * PLB + swz(brl + np * 16, bchk);
                uint32_t r0, r1, r2, r3;
                ldsm4(r0, r1, r2, r3, addr);
                bh[np * 2][0] = r0; bh[np * 2][1] = r1;
                bh[np * 2 + 1][0] = r2; bh[np * 2 + 1][1] = r3;
                ldsm4(r0, r1, r2, r3, addr + PLB);
                bl[np * 2][0] = r0; bl[np * 2][1] = r1;
                bl[np * 2 + 1][0] = r2; bl[np * 2 + 1][1] = r3;
            }
            #pragma unroll
            for (int mt = 0; mt < 2; mt++)
                #pragma unroll
                for (int nt = 0; nt < 8; nt++)
                    mma16816(acc[mt][nt], ah[mt], bh[nt]);
            #pragma unroll
            for (int mt = 0; mt < 2; mt++)
                #pragma unroll
                for (int nt = 0; nt < 8; nt++)
                    mma16816(acc[mt][nt], ah[mt], bl[nt]);
            #pragma unroll
            for (int mt = 0; mt < 2; mt++)
                #pragma unroll
                for (int nt = 0; nt < 8; nt++)
                    mma16816(acc[mt][nt], al[mt], bh[nt]);
        }
        if (kt + 2 < nk) {
            load_stage((kt + 2) % NSTAGE, (kt + 2) << 5);
            asm volatile("cp.async.commit_group;");
        }
    }
}

// stage a warp's 32x64 acc tile (+bias) into the fp32 transpose buffer
__device__ __forceinline__ void stage_acc(float* buf, float acc[2][8][4],
                                          const float* bias, int lane, int wm, int wn) {
    int gid = lane >> 2, tig = lane & 3;
    #pragma unroll
    for (int nt = 0; nt < 8; nt++) {
        int c = wn * 64 + nt * 8 + tig * 2;
        float b0 = bias ? bias[c] : 0.f;
        float b1 = bias ? bias[c + 1] : 0.f;
        #pragma unroll
        for (int mt = 0; mt < 2; mt++) {
            int r = wm * 32 + mt * 16 + gid;
            buf[r * TPITCH + c]           = acc[mt][nt][0] + b0;
            buf[r * TPITCH + c + 1]       = acc[mt][nt][1] + b1;
            buf[(r + 8) * TPITCH + c]     = acc[mt][nt][2] + b0;
            buf[(r + 8) * TPITCH + c + 1] = acc[mt][nt][3] + b1;
        }
    }
}

// generic TN GEMM (fp32 out and/or split bf16 out)
__global__ __launch_bounds__(256, 2)
void mma_tn(const __nv_bfloat16* __restrict__ Ah, const __nv_bfloat16* __restrict__ Al,
            const __nv_bfloat16* __restrict__ Bh, const __nv_bfloat16* __restrict__ Bl,
            const float* __restrict__ bias,
            float* __restrict__ Cf,
            __nv_bfloat16* __restrict__ Ch, __nv_bfloat16* __restrict__ Cl,
            int M, int N, int K, float alpha,
            long long sA, long long sB, long long sC) {
    extern __shared__ __nv_bfloat16 smbuf[];
    long long zb = blockIdx.z;
    Ah += zb * sA; Al += zb * sA;
    Bh += zb * sB; Bl += zb * sB;
    if (Cf) Cf += zb * sC;
    if (Ch) { Ch += zb * sC; Cl += zb * sC; }

    int tid = threadIdx.x;
    int lane = tid & 31, warp = tid >> 5;
    int wm = warp & 3, wn = warp >> 2;
    int brow = blockIdx.y * 128, bcol = blockIdx.x * 128;
    uint32_t sbase = cvta_s(smbuf);

    float acc[2][8][4];
    #pragma unroll
    for (int i = 0; i < 2; i++)
        #pragma unroll
        for (int j = 0; j < 8; j++)
            #pragma unroll
            for (int q = 0; q < 4; q++) acc[i][j][q] = 0.f;

    gemm_mainloop(Ah, Al, Bh, Bl, brow, bcol, K, sbase, tid, lane, wm, wn, acc);

    int gid = lane >> 2, tig = lane & 3;
    #pragma unroll
    for (int nt = 0; nt < 8; nt++) {
        int col = bcol + wn * 64 + nt * 8 + tig * 2;
        float b0 = bias ? bias[col] : 0.f;
        float b1 = bias ? bias[col + 1] : 0.f;
        #pragma unroll
        for (int mt = 0; mt < 2; mt++) {
            int row0 = brow + wm * 32 + mt * 16 + gid;
            float v00 = acc[mt][nt][0] * alpha + b0;
            float v01 = acc[mt][nt][1] * alpha + b1;
            float v10 = acc[mt][nt][2] * alpha + b0;
            float v11 = acc[mt][nt][3] * alpha + b1;
            if (Cf) {
                float2 p0 = {v00, v01}, p1 = {v10, v11};
                *(float2*)(Cf + (size_t)row0 * N + col) = p0;
                *(float2*)(Cf + (size_t)(row0 + 8) * N + col) = p1;
            }
            if (Ch) {
                __nv_bfloat16 h00 = __float2bfloat16_rn(v00);
                __nv_bfloat16 h01 = __float2bfloat16_rn(v01);
                __nv_bfloat16 h10 = __float2bfloat16_rn(v10);
                __nv_bfloat16 h11 = __float2bfloat16_rn(v11);
                __nv_bfloat162 hh0 = {h00, h01}, hh1 = {h10, h11};
                __nv_bfloat162 ll0 = {__float2bfloat16_rn(v00 - __bfloat162float(h00)),
                                      __float2bfloat16_rn(v01 - __bfloat162float(h01))};
                __nv_bfloat162 ll1 = {__float2bfloat16_rn(v10 - __bfloat162float(h10)),
                                      __float2bfloat16_rn(v11 - __bfloat162float(h11))};
                *(__nv_bfloat162*)(Ch + (size_t)row0 * N + col) = hh0;
                *(__nv_bfloat162*)(Cl + (size_t)row0 * N + col) = ll0;
                *(__nv_bfloat162*)(Ch + (size_t)(row0 + 8) * N + col) = hh1;
                *(__nv_bfloat162*)(Cl + (size_t)(row0 + 8) * N + col) = ll1;
            }
        }
    }
}

// fused QKV projection; V section writes V^T split directly via smem transpose.
__global__ __launch_bounds__(256, 2)
void mma_qkv(const __nv_bfloat16* __restrict__ Ah, const __nv_bfloat16* __restrict__ Al,
             const __nv_bfloat16* __restrict__ Bh, const __nv_bfloat16* __restrict__ Bl,
             const float* __restrict__ bq, const float* __restrict__ bk,
             const float* __restrict__ bv,
             __nv_bfloat16* __restrict__ Qh, __nv_bfloat16* __restrict__ Ql,
             __nv_bfloat16* __restrict__ Kh, __nv_bfloat16* __restrict__ Kl,
             __nv_bfloat16* __restrict__ Vth, __nv_bfloat16* __restrict__ Vtl,
             int K) {
    extern __shared__ __nv_bfloat16 smbuf[];
    int tid = threadIdx.x;
    int lane = tid & 31, warp = tid >> 5;
    int wm = warp & 3, wn = warp >> 2;
    int brow = blockIdx.y * 128, bcol = blockIdx.x * 128;
    uint32_t sbase = cvta_s(smbuf);

    float acc[2][8][4];
    #pragma unroll
    for (int i = 0; i < 2; i++)
        #pragma unroll
        for (int j = 0; j < 8; j++)
            #pragma unroll
            for (int q = 0; q < 4; q++) acc[i][j][q] = 0.f;

    gemm_mainloop(Ah, Al, Bh, Bl, brow, bcol, K, sbase, tid, lane, wm, wn, acc);

    int sec = bcol >> 9;            // 0=q 1=k 2=v
    int colbase = bcol & 511;

    if (sec == 2) {
        // V: transpose epilogue -> Vt[b][d][m] split
        __syncthreads();                 // pipeline smem now reusable
        float* buf = (float*)smbuf;      // [128][TPITCH]
        stage_acc(buf, acc, bv + colbase, lane, wm, wn);
        __syncthreads();
        int d = tid >> 1, mh = tid & 1;
        int b = brow >> 12, m0 = (brow & 4095) + mh * 64;
        size_t base = ((size_t)b * Cc + colbase + d) * Nn + m0;
        #pragma unroll 8
        for (int i = 0; i < 32; i++) {
            float f0 = buf[(mh * 64 + 2 * i) * TPITCH + d];
            float f1 = buf[(mh * 64 + 2 * i + 1) * TPITCH + d];
            __nv_bfloat16 h0 = __float2bfloat16_rn(f0);
            __nv_bfloat16 h1 = __float2bfloat16_rn(f1);
            __nv_bfloat162 hh = {h0, h1};
            __nv_bfloat162 ll = {__float2bfloat16_rn(f0 - __bfloat162float(h0)),
                                 __float2bfloat16_rn(f1 - __bfloat162float(h1))};
            *(__nv_bfloat162*)(Vth + base + 2 * i) = hh;
            *(__nv_bfloat162*)(Vtl + base + 2 * i) = ll;
        }
        return;
    }

    const float* bias = (sec == 0) ? bq : bk;
    __nv_bfloat16* Ch = (sec == 0) ? Qh : Kh;
    __nv_bfloat16* Cl = (sec == 0) ? Ql : Kl;

    int gid = lane >> 2, tig = lane & 3;
    #pragma unroll
    for (int nt = 0; nt < 8; nt++) {
        int col = colbase + wn * 64 + nt * 8 + tig * 2;
        float b0 = bias[col], b1 = bias[col + 1];
        #pragma unroll
        for (int mt = 0; mt < 2; mt++) {
            int row0 = brow + wm * 32 + mt * 16 + gid;
            float v00 = acc[mt][nt][0] + b0;
            float v01 = acc[mt][nt][1] + b1;
            float v10 = acc[mt][nt][2] + b0;
            float v11 = acc[mt][nt][3] + b1;
            __nv_bfloat16 h00 = __float2bfloat16_rn(v00);
            __nv_bfloat16 h01 = __float2bfloat16_rn(v01);
            __nv_bfloat16 h10 = __float2bfloat16_rn(v10);
            __nv_bfloat16 h11 = __float2bfloat16_rn(v11);
            __nv_bfloat162 hh0 = {h00, h01}, hh1 = {h10, h11};
            __nv_bfloat162 ll0 = {__float2bfloat16_rn(v00 - __bfloat162float(h00)),
                                  __float2bfloat16_rn(v01 - __bfloat162float(h01))};
            __nv_bfloat162 ll1 = {__float2bfloat16_rn(v10 - __bfloat162float(h10)),
                                  __float2bfloat16_rn(v11 - __bfloat162float(h11))};
            *(__nv_bfloat162*)(Ch + (size_t)row0 * Cc + col) = hh0;
            *(__nv_bfloat162*)(Cl + (size_t)row0 * Cc + col) = ll0;
            *(__nv_bfloat162*)(Ch + (size_t)(row0 + 8) * Cc + col) = hh1;
            *(__nv_bfloat162*)(Cl + (size_t)(row0 + 8) * Cc + col) = ll1;
        }
    }
}

// final projection fused with residual + transpose-back:
// out[b][c][n] = x[b][c][n] + (AO @ wo^T + bo)[token, c]
__global__ __launch_bounds__(256, 2)
void mma_resid(const __nv_bfloat16* __restrict__ Ah, const __nv_bfloat16* __restrict__ Al,
               const __nv_bfloat16* __restrict__ Bh, const __nv_bfloat16* __restrict__ Bl,
               const float* __restrict__ bias,
               const float* __restrict__ x, float* __restrict__ out,
               int K) {
    extern __shared__ __nv_bfloat16 smbuf[];
    int tid = threadIdx.x;
    int lane = tid & 31, warp = tid >> 5;
    int wm = warp & 3, wn = warp >> 2;
    int brow = blockIdx.y * 128, bcol = blockIdx.x * 128;
    uint32_t sbase = cvta_s(smbuf);

    float acc[2][8][4];
    #pragma unroll
    for (int i = 0; i < 2; i++)
        #pragma unroll
        for (int j = 0; j < 8; j++)
            #pragma unroll
            for (int q = 0; q < 4; q++) acc[i][j][q] = 0.f;

    gemm_mainloop(Ah, Al, Bh, Bl, brow, bcol, K, sbase, tid, lane, wm, wn, acc);

    __syncthreads();
    float* buf = (float*)smbuf;     // [128 tokens][TPITCH c]
    stage_acc(buf, acc, bias + bcol, lane, wm, wn);
    __syncthreads();

    int c = tid >> 1, nh = tid & 1;
    int b = brow >> 12, n0 = (brow & 4095) + nh * 64;
    size_t base = ((size_t)b * Cc + bcol + c) * Nn + n0;
    #pragma unroll
    for (int i = 0; i < 16; i++) {
        float4 xv = *(const float4*)(x + base + 4 * i);
        float4 o;
        o.x = xv.x + buf[(nh * 64 + 4 * i + 0) * TPITCH + c];
        o.y = xv.y + buf[(nh * 64 + 4 * i + 1) * TPITCH + c];
        o.z = xv.z + buf[(nh * 64 + 4 * i + 2) * TPITCH + c];
        o.w = xv.w + buf[(nh * 64 + 4 * i + 3) * TPITCH + c];
        *(float4*)(out + base + 4 * i) = o;
    }
}

// ---------------- softmax rows of g_s -> split bf16 probs ----------------
__global__ void softmax_kernel() {
    size_t row = blockIdx.x;
    float4* p = (float4*)(g_s + row * Nn);
    int tid = threadIdx.x;
    int lane = tid & 31, warp = tid >> 5;
    __shared__ float sm1[8], sm2[8];
    float4 v[4];
    float mx = -1e30f;
    #pragma unroll
    for (int i = 0; i < 4; i++) {
        v[i] = p[tid + i * 256];
        mx = fmaxf(mx, fmaxf(fmaxf(v[i].x, v[i].y), fmaxf(v[i].z, v[i].w)));
    }
    #pragma unroll
    for (int o = 16; o > 0; o >>= 1) mx = fmaxf(mx, __shfl_xor_sync(~0u, mx, o));
    if (lane == 0) sm1[warp] = mx;
    __syncthreads();
    mx = sm1[0];
    #pragma unroll
    for (int j = 1; j < 8; j++) mx = fmaxf(mx, sm1[j]);

    float s = 0.f;
    #pragma unroll
    for (int i = 0; i < 4; i++) {
        v[i].x = __expf(v[i].x - mx); v[i].y = __expf(v[i].y - mx);
        v[i].z = __expf(v[i].z - mx); v[i].w = __expf(v[i].w - mx);
        s += v[i].x + v[i].y + v[i].z + v[i].w;
    }
    #pragma unroll
    for (int o = 16; o > 0; o >>= 1) s += __shfl_xor_sync(~0u, s, o);
    if (lane == 0) sm2[warp] = s;
    __syncthreads();
    s = 0.f;
    #pragma unroll
    for (int j = 0; j < 8; j++) s += sm2[j];
    float inv = 1.f / s;

    #pragma unroll
    for (int i = 0; i < 4; i++) {
        float e0 = v[i].x * inv, e1 = v[i].y * inv, e2 = v[i].z * inv, e3 = v[i].w * inv;
        size_t base = row * Nn + (size_t)(tid + i * 256) * 4;
        __nv_bfloat16 h0 = __float2bfloat16_rn(e0), h1 = __float2bfloat16_rn(e1);
        __nv_bfloat16 h2 = __float2bfloat16_rn(e2), h3 = __float2bfloat16_rn(e3);
        __nv_bfloat162 hh0 = {h0, h1}, hh1 = {h2, h3};
        __nv_bfloat162 ll0 = {__float2bfloat16_rn(e0 - __bfloat162float(h0)),
                              __float2bfloat16_rn(e1 - __bfloat162float(h1))};
        __nv_bfloat162 ll1 = {__float2bfloat16_rn(e2 - __bfloat162float(h2)),
                              __float2bfloat16_rn(e3 - __bfloat162float(h3))};
        ((__nv_bfloat162*)(g_ph + base))[0] = hh0;
        ((__nv_bfloat162*)(g_ph + base))[1] = hh1;
        ((__nv_bfloat162*)(g_pl + base))[0] = ll0;
        ((__nv_bfloat162*)(g_pl + base))[1] = ll1;
    }
}

// ---------------- launch ----------------
extern "C" void kernel_launch(void* const* d_in, const int* in_sizes, int n_in,
                              void* d_out, int out_size) {
    const float* x    = (const float*)d_in[0];
    const float* gn_w = (const float*)d_in[1];
    const float* gn_b = (const float*)d_in[2];
    const float* wq   = (const float*)d_in[3];
    const float* bq   = (const float*)d_in[4];
    const float* wk   = (const float*)d_in[5];
    const float* bk   = (const float*)d_in[6];
    const float* wv   = (const float*)d_in[7];
    const float* bv   = (const float*)d_in[8];
    const float* wo   = (const float*)d_in[9];
    const float* bo   = (const float*)d_in[10];
    float* out = (float*)d_out;

    __nv_bfloat16 *hh, *hl, *w4h, *w4l, *qh, *ql, *kh, *kl, *vth, *vtl, *ph, *pl, *aoh, *aol;
    float *s;
    cudaGetSymbolAddress((void**)&hh, g_hh);   cudaGetSymbolAddress((void**)&hl, g_hl);
    cudaGetSymbolAddress((void**)&w4h, g_w4h); cudaGetSymbolAddress((void**)&w4l, g_w4l);
    cudaGetSymbolAddress((void**)&qh, g_qh);   cudaGetSymbolAddress((void**)&ql, g_ql);
    cudaGetSymbolAddress((void**)&kh, g_kh);   cudaGetSymbolAddress((void**)&kl, g_kl);
    cudaGetSymbolAddress((void**)&vth, g_vth); cudaGetSymbolAddress((void**)&vtl, g_vtl);
    cudaGetSymbolAddress((void**)&ph, g_ph);   cudaGetSymbolAddress((void**)&pl, g_pl);
    cudaGetSymbolAddress((void**)&aoh, g_aoh); cudaGetSymbolAddress((void**)&aol, g_aol);
    cudaGetSymbolAddress((void**)&s, g_s);

    const int Mtot = Bb * Nn;                        // 32768
    const float scale = 0.044194173824159216f;       // 1/sqrt(512)
    const int WSZ = Cc * Cc;                         // 262144
    const int SMEM = NSTAGE * STGB;                  // 96 KB

    cudaFuncSetAttribute(mma_tn, cudaFuncAttributeMaxDynamicSharedMemorySize, SMEM);
    cudaFuncSetAttribute(mma_qkv, cudaFuncAttributeMaxDynamicSharedMemorySize, SMEM);
    cudaFuncSetAttribute(mma_resid, cudaFuncAttributeMaxDynamicSharedMemorySize, SMEM);

    gn_stats1_kernel<<<512, 256>>>(x);
    gn_stats2_kernel<<<2, 32>>>();
    gn_apply_kernel<<<dim3(Nn / 32, Cc / 32, Bb), dim3(32, 32)>>>(x, gn_w, gn_b);
    split_kernel<<<WSZ / 1024, 256>>>(wq, w4h + 0 * WSZ, w4l + 0 * WSZ);
    split_kernel<<<WSZ / 1024, 256>>>(wk, w4h + 1 * WSZ, w4l + 1 * WSZ);
    split_kernel<<<WSZ / 1024, 256>>>(wv, w4h + 2 * WSZ, w4l + 2 * WSZ);
    split_kernel<<<WSZ / 1024, 256>>>(wo, w4h + 3 * WSZ, w4l + 3 * WSZ);

    // fused QKV projection (V written directly as transposed split)
    mma_qkv<<<dim3(12, Mtot / 128), 256, SMEM>>>(hh, hl, w4h, w4l,
                                                 bq, bk, bv, qh, ql, kh, kl, vth, vtl, Cc);
    // scores = q k^T * scale (batched)
    mma_tn<<<dim3(Nn / 128, Nn / 128, Bb), 256, SMEM>>>(qh, ql, kh, kl, nullptr,
                                 s, nullptr, nullptr, Nn, Nn, Cc, scale, NCs, NCs, NNs);
    softmax_kernel<<<Bb * Nn, 256>>>();
    // attn out = P @ V (vs V^T split)
    mma_tn<<<dim3(Cc / 128, Nn / 128, Bb), 256, SMEM>>>(ph, pl, vth, vtl, nullptr,
                                 nullptr, aoh, aol, Nn, Cc, Nn, 1.f, NNs, NCs, NCs);
    // final projection + residual + transpose-back
    mma_resid<<<dim3(Cc / 128, Mtot / 128), 256, SMEM>>>(aoh, aol,
                                 w4h + 3 * WSZ, w4l + 3 * WSZ, bo, x, out, Cc);
}

// round 10
// speedup vs baseline: 1.7612x; 1.2898x over previous
#include <cuda_runtime.h>
#include <cuda_fp16.h>
#include <math.h>
#include <stdint.h>

#define Cc 512
#define Bb 8
#define Nn 4096
#define GROUPS 8
#define EPS 1e-5f

#define MC ((size_t)Bb * Nn * Cc)
#define SC ((size_t)Bb * Nn * Nn)
#define NCs ((long long)Nn * Cc)
#define NNs ((long long)Nn * Nn)

// ---------------- scratch ----------------
__device__ __half g_hh[MC], g_hl[MC];
__device__ __half g_w4h[4 * Cc * Cc], g_w4l[4 * Cc * Cc];
__device__ __half g_qh[MC], g_ql[MC];
__device__ __half g_kh[MC];
__device__ __half g_vth[MC];
__device__ float  g_s[SC];
__device__ __half g_ph[SC], g_pl[SC];
__device__ __half g_aoh[MC], g_aol[MC];
__device__ float  g_stats[Bb * GROUPS * 2];
__device__ float  g_part[512 * 2];

__device__ __forceinline__ void split_store(float v, __half* ph, __half* pl) {
    __half h = __float2half_rn(v);
    *ph = h;
    *pl = __float2half_rn(v - __half2float(h));
}

// ---------------- 1) group-norm statistics (two-phase) ----------------
__global__ void gn_stats1_kernel(const float* __restrict__ x) {
    int blk = blockIdx.x;
    int bg = blk >> 3, sub = blk & 7;
    const size_t cnt = (size_t)(Cc / GROUPS) * Nn;
    const float4* p = (const float4*)(x + (size_t)bg * cnt + (size_t)sub * (cnt / 8));
    int tid = threadIdx.x;
    float s = 0.f, sq = 0.f;
    #pragma unroll 4
    for (int i = tid; i < (int)(cnt / 8 / 4); i += 256) {
        float4 v = p[i];
        s  += v.x + v.y + v.z + v.w;
        sq += v.x * v.x + v.y * v.y + v.z * v.z + v.w * v.w;
    }
    int lane = tid & 31, warp = tid >> 5;
    #pragma unroll
    for (int o = 16; o > 0; o >>= 1) {
        s  += __shfl_xor_sync(~0u, s, o);
        sq += __shfl_xor_sync(~0u, sq, o);
    }
    __shared__ float ss[8], ssq[8];
    if (lane == 0) { ss[warp] = s; ssq[warp] = sq; }
    __syncthreads();
    if (tid == 0) {
        float ts = 0.f, tq = 0.f;
        #pragma unroll
        for (int j = 0; j < 8; j++) { ts += ss[j]; tq += ssq[j]; }
        g_part[blk * 2 + 0] = ts;
        g_part[blk * 2 + 1] = tq;
    }
}
__global__ void gn_stats2_kernel() {
    int bg = blockIdx.x * blockDim.x + threadIdx.x;
    if (bg >= Bb * GROUPS) return;
    const float cnt = (float)((Cc / GROUPS) * Nn);
    float s = 0.f, sq = 0.f;
    #pragma unroll
    for (int j = 0; j < 8; j++) {
        s  += g_part[(bg * 8 + j) * 2 + 0];
        sq += g_part[(bg * 8 + j) * 2 + 1];
    }
    float mu = s / cnt;
    float var = sq / cnt - mu * mu;
    g_stats[bg * 2 + 0] = mu;
    g_stats[bg * 2 + 1] = rsqrtf(var + EPS);
}

// ---------------- 2) GN apply + transpose -> split fp16 [B,N,C] ----------------
__global__ void gn_apply_kernel(const float* __restrict__ x,
                                const float* __restrict__ w,
                                const float* __restrict__ b) {
    __shared__ float sm[32][33];
    int bz = blockIdx.z;
    int n0 = blockIdx.x * 32;
    int c0 = blockIdx.y * 32;
    int tx = threadIdx.x, ty = threadIdx.y;
    {
        int c = c0 + ty, n = n0 + tx;
        int g = c >> 6;
        float mu   = g_stats[(bz * GROUPS + g) * 2 + 0];
        float rstd = g_stats[(bz * GROUPS + g) * 2 + 1];
        float v = x[((size_t)bz * Cc + c) * Nn + n];
        sm[ty][tx] = (v - mu) * rstd * w[c] + b[c];
    }
    __syncthreads();
    {
        int n = n0 + ty, c = c0 + tx;
        size_t idx = ((size_t)bz * Nn + n) * Cc + c;
        split_store(sm[tx][ty], g_hh + idx, g_hl + idx);
    }
}

__global__ void split_kernel(const float* __restrict__ src,
                             __half* __restrict__ dh,
                             __half* __restrict__ dl) {
    int i = (blockIdx.x * 256 + threadIdx.x) * 4;
    float4 v = *(const float4*)(src + i);
    __half h0 = __float2half_rn(v.x), h1 = __float2half_rn(v.y);
    __half h2 = __float2half_rn(v.z), h3 = __float2half_rn(v.w);
    __half2 hh0 = {h0, h1}, hh1 = {h2, h3};
    __half2 ll0 = {__float2half_rn(v.x - __half2float(h0)),
                   __float2half_rn(v.y - __half2float(h1))};
    __half2 ll1 = {__float2half_rn(v.z - __half2float(h2)),
                   __float2half_rn(v.w - __half2float(h3))};
    ((__half2*)(dh + i))[0] = hh0;
    ((__half2*)(dh + i))[1] = hh1;
    ((__half2*)(dl + i))[0] = ll0;
    ((__half2*)(dl + i))[1] = ll1;
}

// ---------------- tensor-core TN GEMM machinery (fp16 split) ----------------
#define PLB 8192
#define STGB (4 * PLB)
#define NSTAGE 3
#define TPITCH 129

__device__ __forceinline__ uint32_t cvta_s(const void* p) {
    return (uint32_t)__cvta_generic_to_shared(p);
}
__device__ __forceinline__ void cp16(uint32_t s, const void* g) {
    asm volatile("cp.async.cg.shared.global [%0], [%1], 16;" :: "r"(s), "l"(g));
}
__device__ __forceinline__ void ldsm4(uint32_t& r0, uint32_t& r1, uint32_t& r2, uint32_t& r3, uint32_t a) {
    asm volatile("ldmatrix.sync.aligned.m8n8.x4.shared.b16 {%0,%1,%2,%3}, [%4];"
                 : "=r"(r0), "=r"(r1), "=r"(r2), "=r"(r3) : "r"(a));
}
__device__ __forceinline__ void mma16816(float* c, const uint32_t* a, const uint32_t* b) {
    asm volatile("mma.sync.aligned.m16n8k16.row.col.f32.f16.f16.f32 "
                 "{%0,%1,%2,%3},{%4,%5,%6,%7},{%8,%9},{%0,%1,%2,%3};"
                 : "+f"(c[0]), "+f"(c[1]), "+f"(c[2]), "+f"(c[3])
                 : "r"(a[0]), "r"(a[1]), "r"(a[2]), "r"(a[3]), "r"(b[0]), "r"(b[1]));
}
__device__ __forceinline__ uint32_t swz(int row, int chunk) {
    return (uint32_t)(row * 64 + ((chunk ^ ((row >> 1) & 3)) << 4));
}

// NT=3: C = Ah·Bh + Al·Bh + Ah·Bl ;  NT=2: C = Ah·Bh + Al·Bh  (B hi only)
template <int NT>
__device__ __forceinline__ void gemm_mainloop(
    const __half* Ah, const __half* Al,
    const __half* Bh, const __half* Bl,
    int brow, int bcol, int K, uint32_t sbase,
    int tid, int lane, int wm, int wn,
    float acc[2][8][4]) {

    int ldrow = tid >> 1;
    int ldc0 = (tid & 1) * 2;

    auto load_stage = [&](int slot, int k0) {
        uint32_t so = sbase + (uint32_t)(slot * STGB);
        size_t ga = (size_t)(brow + ldrow) * K + k0;
        size_t gb = (size_t)(bcol + ldrow) * K + k0;
        #pragma unroll
        for (int cc = 0; cc < 2; cc++) {
            int c = ldc0 + cc;
            uint32_t off = swz(ldrow, c);
            cp16(so + 0 * PLB + off, Ah + ga + c * 8);
            cp16(so + 1 * PLB + off, Al + ga + c * 8);
            cp16(so + 2 * PLB + off, Bh + gb + c * 8);
            if (NT == 3) cp16(so + 3 * PLB + off, Bl + gb + c * 8);
        }
    };

    int nk = K >> 5;
    load_stage(0, 0);
    asm volatile("cp.async.commit_group;");
    load_stage(1, 32);
    asm volatile("cp.async.commit_group;");

    for (int kt = 0; kt < nk; kt++) {
        if (kt + 1 < nk) {
            asm volatile("cp.async.wait_group 1;");
        } else {
            asm volatile("cp.async.wait_group 0;");
        }
        __syncthreads();
        uint32_t so = sbase + (uint32_t)((kt % NSTAGE) * STGB);
        #pragma unroll
        for (int kk = 0; kk < 2; kk++) {
            uint32_t ah[2][4], al[2][4];
            int arow = wm * 32 + ((lane >> 3) & 1) * 8 + (lane & 7);
            int akof = kk * 16 + (lane >> 4) * 8;
            int achk = akof >> 3;
            #pragma unroll
            for (int mt = 0; mt < 2; mt++) {
                uint32_t addr = so + swz(arow + mt * 16, achk);
                ldsm4(ah[mt][0], ah[mt][1], ah[mt][2], ah[mt][3], addr);
                ldsm4(al[mt][0], al[mt][1], al[mt][2], al[mt][3], addr + PLB);
            }
            uint32_t bh[8][2], bl[8][2];
            int bphase = lane >> 3;
            int brl = wn * 64 + (lane & 7) + (bphase >> 1) * 8;
            int bkof = kk * 16 + (bphase & 1) * 8;
            int bchk = bkof >> 3;
            #pragma unroll
            for (int np = 0; np < 4; np++) {
                uint32_t addr = so + 2 * PLB + swz(brl + np * 16, bchk);
                uint32_t r0, r1, r2, r3;
                ldsm4(r0, r1, r2, r3, addr);
                bh[np * 2][0] = r0; bh[np * 2][1] = r1;
                bh[np * 2 + 1][0] = r2; bh[np * 2 + 1][1] = r3;
                if (NT == 3) {
                    ldsm4(r0, r1, r2, r3, addr + PLB);
                    bl[np * 2][0] = r0; bl[np * 2][1] = r1;
                    bl[np * 2 + 1][0] = r2; bl[np * 2 + 1][1] = r3;
                }
            }
            #pragma unroll
            for (int mt = 0; mt < 2; mt++)
                #pragma unroll
                for (int nt = 0; nt < 8; nt++)
                    mma16816(acc[mt][nt], ah[mt], bh[nt]);
            #pragma unroll
            for (int mt = 0; mt < 2; mt++)
                #pragma unroll
                for (int nt = 0; nt < 8; nt++)
                    mma16816(acc[mt][nt], al[mt], bh[nt]);
            if (NT == 3) {
                #pragma unroll
                for (int mt = 0; mt < 2; mt++)
                    #pragma unroll
                    for (int nt = 0; nt < 8; nt++)
                        mma16816(acc[mt][nt], ah[mt], bl[nt]);
            }
        }
        if (kt + 2 < nk) {
            load_stage((kt + 2) % NSTAGE, (kt + 2) << 5);
            asm volatile("cp.async.commit_group;");
        }
    }
}

__device__ __forceinline__ void stage_acc(float* buf, float acc[2][8][4],
                                          const float* bias, int lane, int wm, int wn) {
    int gid = lane >> 2, tig = lane & 3;
    #pragma unroll
    for (int nt = 0; nt < 8; nt++) {
        int c = wn * 64 + nt * 8 + tig * 2;
        float b0 = bias ? bias[c] : 0.f;
        float b1 = bias ? bias[c + 1] : 0.f;
        #pragma unroll
        for (int mt = 0; mt < 2; mt++) {
            int r = wm * 32 + mt * 16 + gid;
            buf[r * TPITCH + c]           = acc[mt][nt][0] + b0;
            buf[r * TPITCH + c + 1]       = acc[mt][nt][1] + b1;
            buf[(r + 8) * TPITCH + c]     = acc[mt][nt][2] + b0;
            buf[(r + 8) * TPITCH + c + 1] = acc[mt][nt][3] + b1;
        }
    }
}

// generic TN GEMM (fp32 out and/or split fp16 out)
template <int NT>
__global__ __launch_bounds__(256, 2)
void mma_tn(const __half* __restrict__ Ah, const __half* __restrict__ Al,
            const __half* __restrict__ Bh, const __half* __restrict__ Bl,
            float* __restrict__ Cf,
            __half* __restrict__ Ch, __half* __restrict__ Cl,
            int M, int N, int K, float alpha,
            long long sA, long long sB, long long sC) {
    extern __shared__ __half smbuf[];
    long long zb = blockIdx.z;
    Ah += zb * sA; Al += zb * sA;
    Bh += zb * sB; if (Bl) Bl += zb * sB;
    if (Cf) Cf += zb * sC;
    if (Ch) { Ch += zb * sC; Cl += zb * sC; }

    int tid = threadIdx.x;
    int lane = tid & 31, warp = tid >> 5;
    int wm = warp & 3, wn = warp >> 2;
    int brow = blockIdx.y * 128, bcol = blockIdx.x * 128;
    uint32_t sbase = cvta_s(smbuf);

    float acc[2][8][4];
    #pragma unroll
    for (int i = 0; i < 2; i++)
        #pragma unroll
        for (int j = 0; j < 8; j++)
            #pragma unroll
            for (int q = 0; q < 4; q++) acc[i][j][q] = 0.f;

    gemm_mainloop<NT>(Ah, Al, Bh, Bl, brow, bcol, K, sbase, tid, lane, wm, wn, acc);

    int gid = lane >> 2, tig = lane & 3;
    #pragma unroll
    for (int nt = 0; nt < 8; nt++) {
        int col = bcol + wn * 64 + nt * 8 + tig * 2;
        #pragma unroll
        for (int mt = 0; mt < 2; mt++) {
            int row0 = brow + wm * 32 + mt * 16 + gid;
            float v00 = acc[mt][nt][0] * alpha;
            float v01 = acc[mt][nt][1] * alpha;
            float v10 = acc[mt][nt][2] * alpha;
            float v11 = acc[mt][nt][3] * alpha;
            if (Cf) {
                float2 p0 = {v00, v01}, p1 = {v10, v11};
                *(float2*)(Cf + (size_t)row0 * N + col) = p0;
                *(float2*)(Cf + (size_t)(row0 + 8) * N + col) = p1;
            }
            if (Ch) {
                __half h00 = __float2half_rn(v00);
                __half h01 = __float2half_rn(v01);
                __half h10 = __float2half_rn(v10);
                __half h11 = __float2half_rn(v11);
                __half2 hh0 = {h00, h01}, hh1 = {h10, h11};
                __half2 ll0 = {__float2half_rn(v00 - __half2float(h00)),
                               __float2half_rn(v01 - __half2float(h01))};
                __half2 ll1 = {__float2half_rn(v10 - __half2float(h10)),
                               __float2half_rn(v11 - __half2float(h11))};
                *(__half2*)(Ch + (size_t)row0 * N + col) = hh0;
                *(__half2*)(Cl + (size_t)row0 * N + col) = ll0;
                *(__half2*)(Ch + (size_t)(row0 + 8) * N + col) = hh1;
                *(__half2*)(Cl + (size_t)(row0 + 8) * N + col) = ll1;
            }
        }
    }
}

// fused QKV projection (3-term); Q split, K hi-only, V^T hi-only via transpose.
__global__ __launch_bounds__(256, 2)
void mma_qkv(const __half* __restrict__ Ah, const __half* __restrict__ Al,
             const __half* __restrict__ Bh, const __half* __restrict__ Bl,
             const float* __restrict__ bq, const float* __restrict__ bk,
             const float* __restrict__ bv,
             __half* __restrict__ Qh, __half* __restrict__ Ql,
             __half* __restrict__ Kh,
             __half* __restrict__ Vth,
             int K) {
    extern __shared__ __half smbuf[];
    int tid = threadIdx.x;
    int lane = tid & 31, warp = tid >> 5;
    int wm = warp & 3, wn = warp >> 2;
    int brow = blockIdx.y * 128, bcol = blockIdx.x * 128;
    uint32_t sbase = cvta_s(smbuf);

    float acc[2][8][4];
    #pragma unroll
    for (int i = 0; i < 2; i++)
        #pragma unroll
        for (int j = 0; j < 8; j++)
            #pragma unroll
            for (int q = 0; q < 4; q++) acc[i][j][q] = 0.f;

    gemm_mainloop<3>(Ah, Al, Bh, Bl, brow, bcol, K, sbase, tid, lane, wm, wn, acc);

    int sec = bcol >> 9;            // 0=q 1=k 2=v
    int colbase = bcol & 511;

    if (sec == 2) {
        // V: transpose epilogue -> Vt[b][d][m] hi plane
        __syncthreads();
        float* buf = (float*)smbuf;
        stage_acc(buf, acc, bv + colbase, lane, wm, wn);
        __syncthreads();
        int d = tid >> 1, mh = tid & 1;
        int b = brow >> 12, m0 = (brow & 4095) + mh * 64;
        size_t base = ((size_t)b * Cc + colbase + d) * Nn + m0;
        #pragma unroll 8
        for (int i = 0; i < 32; i++) {
            float f0 = buf[(mh * 64 + 2 * i) * TPITCH + d];
            float f1 = buf[(mh * 64 + 2 * i + 1) * TPITCH + d];
            __half2 hh = {__float2half_rn(f0), __float2half_rn(f1)};
            *(__half2*)(Vth + base + 2 * i) = hh;
        }
        return;
    }

    const float* bias = (sec == 0) ? bq : bk;
    int gid = lane >> 2, tig = lane & 3;
    #pragma unroll
    for (int nt = 0; nt < 8; nt++) {
        int col = colbase + wn * 64 + nt * 8 + tig * 2;
        float b0 = bias[col], b1 = bias[col + 1];
        #pragma unroll
        for (int mt = 0; mt < 2; mt++) {
            int row0 = brow + wm * 32 + mt * 16 + gid;
            float v00 = acc[mt][nt][0] + b0;
            float v01 = acc[mt][nt][1] + b1;
            float v10 = acc[mt][nt][2] + b0;
            float v11 = acc[mt][nt][3] + b1;
            __half h00 = __float2half_rn(v00);
            __half h01 = __float2half_rn(v01);
            __half h10 = __float2half_rn(v10);
            __half h11 = __float2half_rn(v11);
            __half2 hh0 = {h00, h01}, hh1 = {h10, h11};
            if (sec == 0) {
                __half2 ll0 = {__float2half_rn(v00 - __half2float(h00)),
                               __float2half_rn(v01 - __half2float(h01))};
                __half2 ll1 = {__float2half_rn(v10 - __half2float(h10)),
                               __float2half_rn(v11 - __half2float(h11))};
                *(__half2*)(Qh + (size_t)row0 * Cc + col) = hh0;
                *(__half2*)(Ql + (size_t)row0 * Cc + col) = ll0;
                *(__half2*)(Qh + (size_t)(row0 + 8) * Cc + col) = hh1;
                *(__half2*)(Ql + (size_t)(row0 + 8) * Cc + col) = ll1;
            } else {
                *(__half2*)(Kh + (size_t)row0 * Cc + col) = hh0;
                *(__half2*)(Kh + (size_t)(row0 + 8) * Cc + col) = hh1;
            }
        }
    }
}

// final projection (3-term) fused with residual + transpose-back
__global__ __launch_bounds__(256, 2)
void mma_resid(const __half* __restrict__ Ah, const __half* __restrict__ Al,
               const __half* __restrict__ Bh, const __half* __restrict__ Bl,
               const float* __restrict__ bias,
               const float* __restrict__ x, float* __restrict__ out,
               int K) {
    extern __shared__ __half smbuf[];
    int tid = threadIdx.x;
    int lane = tid & 31, warp = tid >> 5;
    int wm = warp & 3, wn = warp >> 2;
    int brow = blockIdx.y * 128, bcol = blockIdx.x * 128;
    uint32_t sbase = cvta_s(smbuf);

    float acc[2][8][4];
    #pragma unroll
    for (int i = 0; i < 2; i++)
        #pragma unroll
        for (int j = 0; j < 8; j++)
            #pragma unroll
            for (int q = 0; q < 4; q++) acc[i][j][q] = 0.f;

    gemm_mainloop<3>(Ah, Al, Bh, Bl, brow, bcol, K, sbase, tid, lane, wm, wn, acc);

    __syncthreads();
    float* buf = (float*)smbuf;
    stage_acc(buf, acc, bias + bcol, lane, wm, wn);
    __syncthreads();

    int c = tid >> 1, nh = tid & 1;
    int b = brow >> 12, n0 = (brow & 4095) + nh * 64;
    size_t base = ((size_t)b * Cc + bcol + c) * Nn + n0;
    #pragma unroll
    for (int i = 0; i < 16; i++) {
        float4 xv = *(const float4*)(x + base + 4 * i);
        float4 o;
        o.x = xv.x + buf[(nh * 64 + 4 * i + 0) * TPITCH + c];
        o.y = xv.y + buf[(nh * 64 + 4 * i + 1) * TPITCH + c];
        o.z = xv.z + buf[(nh * 64 + 4 * i + 2) * TPITCH + c];
        o.w = xv.w + buf[(nh * 64 + 4 * i + 3) * TPITCH + c];
        *(float4*)(out + base + 4 * i) = o;
    }
}

// ---------------- softmax rows of g_s -> split fp16 probs ----------------
__global__ void softmax_kernel() {
    size_t row = blockIdx.x;
    float4* p = (float4*)(g_s + row * Nn);
    int tid = threadIdx.x;
    int lane = tid & 31, warp = tid >> 5;
    __shared__ float sm1[8], sm2[8];
    float4 v[4];
    float mx = -1e30f;
    #pragma unroll
    for (int i = 0; i < 4; i++) {
        v[i] = p[tid + i * 256];
        mx = fmaxf(mx, fmaxf(fmaxf(v[i].x, v[i].y), fmaxf(v[i].z, v[i].w)));
    }
    #pragma unroll
    for (int o = 16; o > 0; o >>= 1) mx = fmaxf(mx, __shfl_xor_sync(~0u, mx, o));
    if (lane == 0) sm1[warp] = mx;
    __syncthreads();
    mx = sm1[0];
    #pragma unroll
    for (int j = 1; j < 8; j++) mx = fmaxf(mx, sm1[j]);

    float s = 0.f;
    #pragma unroll
    for (int i = 0; i < 4; i++) {
        v[i].x = __expf(v[i].x - mx); v[i].y = __expf(v[i].y - mx);
        v[i].z = __expf(v[i].z - mx); v[i].w = __expf(v[i].w - mx);
        s += v[i].x + v[i].y + v[i].z + v[i].w;
    }
    #pragma unroll
    for (int o = 16; o > 0; o >>= 1) s += __shfl_xor_sync(~0u, s, o);
    if (lane == 0) sm2[warp] = s;
    __syncthreads();
    s = 0.f;
    #pragma unroll
    for (int j = 0; j < 8; j++) s += sm2[j];
    float inv = 1.f / s;

    #pragma unroll
    for (int i = 0; i < 4; i++) {
        float e0 = v[i].x * inv, e1 = v[i].y * inv, e2 = v[i].z * inv, e3 = v[i].w * inv;
        size_t base = row * Nn + (size_t)(tid + i * 256) * 4;
        __half h0 = __float2half_rn(e0), h1 = __float2half_rn(e1);
        __half h2 = __float2half_rn(e2), h3 = __float2half_rn(e3);
        __half2 hh0 = {h0, h1}, hh1 = {h2, h3};
        __half2 ll0 = {__float2half_rn(e0 - __half2float(h0)),
                       __float2half_rn(e1 - __half2float(h1))};
        __half2 ll1 = {__float2half_rn(e2 - __half2float(h2)),
                       __float2half_rn(e3 - __half2float(h3))};
        ((__half2*)(g_ph + base))[0] = hh0;
        ((__half2*)(g_ph + base))[1] = hh1;
        ((__half2*)(g_pl + base))[0] = ll0;
        ((__half2*)(g_pl + base))[1] = ll1;
    }
}

// ---------------- launch ----------------
extern "C" void kernel_launch(void* const* d_in, const int* in_sizes, int n_in,
                              void* d_out, int out_size) {
    const float* x    = (const float*)d_in[0];
    const float* gn_w = (const float*)d_in[1];
    const float* gn_b = (const float*)d_in[2];
    const float* wq   = (const float*)d_in[3];
    const float* bq   = (const float*)d_in[4];
    const float* wk   = (const float*)d_in[5];
    const float* bk   = (const float*)d_in[6];
    const float* wv   = (const float*)d_in[7];
    const float* bv   = (const float*)d_in[8];
    const float* wo   = (const float*)d_in[9];
    const float* bo   = (const float*)d_in[10];
    float* out = (float*)d_out;

    __half *hh, *hl, *w4h, *w4l, *qh, *ql, *kh, *vth, *ph, *pl, *aoh, *aol;
    float *s;
    cudaGetSymbolAddress((void**)&hh, g_hh);   cudaGetSymbolAddress((void**)&hl, g_hl);
    cudaGetSymbolAddress((void**)&w4h, g_w4h); cudaGetSymbolAddress((void**)&w4l, g_w4l);
    cudaGetSymbolAddress((void**)&qh, g_qh);   cudaGetSymbolAddress((void**)&ql, g_ql);
    cudaGetSymbolAddress((void**)&kh, g_kh);
    cudaGetSymbolAddress((void**)&vth, g_vth);
    cudaGetSymbolAddress((void**)&ph, g_ph);   cudaGetSymbolAddress((void**)&pl, g_pl);
    cudaGetSymbolAddress((void**)&aoh, g_aoh); cudaGetSymbolAddress((void**)&aol, g_aol);
    cudaGetSymbolAddress((void**)&s, g_s);

    const int Mtot = Bb * Nn;                        // 32768
    const float scale = 0.044194173824159216f;       // 1/sqrt(512)
    const int WSZ = Cc * Cc;                         // 262144
    const int SMEM = NSTAGE * STGB;                  // 96 KB

    cudaFuncSetAttribute(mma_tn<2>, cudaFuncAttributeMaxDynamicSharedMemorySize, SMEM);
    cudaFuncSetAttribute(mma_qkv, cudaFuncAttributeMaxDynamicSharedMemorySize, SMEM);
    cudaFuncSetAttribute(mma_resid, cudaFuncAttributeMaxDynamicSharedMemorySize, SMEM);

    gn_stats1_kernel<<<512, 256>>>(x);
    gn_stats2_kernel<<<2, 32>>>();
    gn_apply_kernel<<<dim3(Nn / 32, Cc / 32, Bb), dim3(32, 32)>>>(x, gn_w, gn_b);
    split_kernel<<<WSZ / 1024, 256>>>(wq, w4h + 0 * WSZ, w4l + 0 * WSZ);
    split_kernel<<<WSZ / 1024, 256>>>(wk, w4h + 1 * WSZ, w4l + 1 * WSZ);
    split_kernel<<<WSZ / 1024, 256>>>(wv, w4h + 2 * WSZ, w4l + 2 * WSZ);
    split_kernel<<<WSZ / 1024, 256>>>(wo, w4h + 3 * WSZ, w4l + 3 * WSZ);

    // fused QKV projection (3-term fp16)
    mma_qkv<<<dim3(12, Mtot / 128), 256, SMEM>>>(hh, hl, w4h, w4l,
                                                 bq, bk, bv, qh, ql, kh, vth, Cc);
    // scores = q k^T * scale  (2-term: q split, k hi-only)
    mma_tn<2><<<dim3(Nn / 128, Nn / 128, Bb), 256, SMEM>>>(qh, ql, kh, nullptr,
                                 s, nullptr, nullptr, Nn, Nn, Cc, scale, NCs, NCs, NNs);
    softmax_kernel<<<Bb * Nn, 256>>>();
    // attn out = P @ V  (2-term: P split, V^T hi-only)
    mma_tn<2><<<dim3(Cc / 128, Nn / 128, Bb), 256, SMEM>>>(ph, pl, vth, nullptr,
                                 nullptr, aoh, aol, Nn, Cc, Nn, 1.f, NNs, NCs, NCs);
    // final projection (3-term) + residual + transpose-back
    mma_resid<<<dim3(Cc / 128, Mtot / 128), 256, SMEM>>>(aoh, aol,
                                 w4h + 3 * WSZ, w4l + 3 * WSZ, bo, x, out, Cc);
}

// round 11
// speedup vs baseline: 2.2933x; 1.3021x over previous
#include <cuda_runtime.h>
#include <cuda_fp16.h>
#include <math.h>
#include <stdint.h>

#define Cc 512
#define Bb 8
#define Nn 4096
#define GROUPS 8
#define EPS 1e-5f

#define MC ((size_t)Bb * Nn * Cc)
#define SC ((size_t)Bb * Nn * Nn)
#define NCs ((long long)Nn * Cc)
#define NNs ((long long)Nn * Nn)

// ---------------- scratch ----------------
__device__ __half g_hh[MC], g_hl[MC];
__device__ __half g_w4h[4 * Cc * Cc], g_w4l[4 * Cc * Cc];
__device__ __half g_qh[MC];
__device__ __half g_kh[MC];
__device__ __half g_vth[MC];
__device__ float  g_s[SC];
__device__ __half g_ph[SC];
__device__ __half g_aoh[MC], g_aol[MC];
__device__ float  g_stats[Bb * GROUPS * 2];
__device__ float  g_part[512 * 2];

__device__ __forceinline__ void split_store(float v, __half* ph, __half* pl) {
    __half h = __float2half_rn(v);
    *ph = h;
    *pl = __float2half_rn(v - __half2float(h));
}

// ---------------- 1) group-norm statistics (two-phase) ----------------
__global__ void gn_stats1_kernel(const float* __restrict__ x) {
    int blk = blockIdx.x;
    int bg = blk >> 3, sub = blk & 7;
    const size_t cnt = (size_t)(Cc / GROUPS) * Nn;
    const float4* p = (const float4*)(x + (size_t)bg * cnt + (size_t)sub * (cnt / 8));
    int tid = threadIdx.x;
    float s = 0.f, sq = 0.f;
    #pragma unroll 4
    for (int i = tid; i < (int)(cnt / 8 / 4); i += 256) {
        float4 v = p[i];
        s  += v.x + v.y + v.z + v.w;
        sq += v.x * v.x + v.y * v.y + v.z * v.z + v.w * v.w;
    }
    int lane = tid & 31, warp = tid >> 5;
    #pragma unroll
    for (int o = 16; o > 0; o >>= 1) {
        s  += __shfl_xor_sync(~0u, s, o);
        sq += __shfl_xor_sync(~0u, sq, o);
    }
    __shared__ float ss[8], ssq[8];
    if (lane == 0) { ss[warp] = s; ssq[warp] = sq; }
    __syncthreads();
    if (tid == 0) {
        float ts = 0.f, tq = 0.f;
        #pragma unroll
        for (int j = 0; j < 8; j++) { ts += ss[j]; tq += ssq[j]; }
        g_part[blk * 2 + 0] = ts;
        g_part[blk * 2 + 1] = tq;
    }
}
__global__ void gn_stats2_kernel() {
    int bg = blockIdx.x * blockDim.x + threadIdx.x;
    if (bg >= Bb * GROUPS) return;
    const float cnt = (float)((Cc / GROUPS) * Nn);
    float s = 0.f, sq = 0.f;
    #pragma unroll
    for (int j = 0; j < 8; j++) {
        s  += g_part[(bg * 8 + j) * 2 + 0];
        sq += g_part[(bg * 8 + j) * 2 + 1];
    }
    float mu = s / cnt;
    float var = sq / cnt - mu * mu;
    g_stats[bg * 2 + 0] = mu;
    g_stats[bg * 2 + 1] = rsqrtf(var + EPS);
}

// ---------------- 2) GN apply + transpose -> split fp16 [B,N,C] ----------------
__global__ void gn_apply_kernel(const float* __restrict__ x,
                                const float* __restrict__ w,
                                const float* __restrict__ b) {
    __shared__ float sm[32][33];
    int bz = blockIdx.z;
    int n0 = blockIdx.x * 32;
    int c0 = blockIdx.y * 32;
    int tx = threadIdx.x, ty = threadIdx.y;
    {
        int c = c0 + ty, n = n0 + tx;
        int g = c >> 6;
        float mu   = g_stats[(bz * GROUPS + g) * 2 + 0];
        float rstd = g_stats[(bz * GROUPS + g) * 2 + 1];
        float v = x[((size_t)bz * Cc + c) * Nn + n];
        sm[ty][tx] = (v - mu) * rstd * w[c] + b[c];
    }
    __syncthreads();
    {
        int n = n0 + ty, c = c0 + tx;
        size_t idx = ((size_t)bz * Nn + n) * Cc + c;
        split_store(sm[tx][ty], g_hh + idx, g_hl + idx);
    }
}

__global__ void split_kernel(const float* __restrict__ src,
                             __half* __restrict__ dh,
                             __half* __restrict__ dl) {
    int i = (blockIdx.x * 256 + threadIdx.x) * 4;
    float4 v = *(const float4*)(src + i);
    __half h0 = __float2half_rn(v.x), h1 = __float2half_rn(v.y);
    __half h2 = __float2half_rn(v.z), h3 = __float2half_rn(v.w);
    __half2 hh0 = {h0, h1}, hh1 = {h2, h3};
    __half2 ll0 = {__float2half_rn(v.x - __half2float(h0)),
                   __float2half_rn(v.y - __half2float(h1))};
    __half2 ll1 = {__float2half_rn(v.z - __half2float(h2)),
                   __float2half_rn(v.w - __half2float(h3))};
    ((__half2*)(dh + i))[0] = hh0;
    ((__half2*)(dh + i))[1] = hh1;
    ((__half2*)(dl + i))[0] = ll0;
    ((__half2*)(dl + i))[1] = ll1;
}

// ---------------- tensor-core TN GEMM machinery (fp16, 1/2/3-term) ----------------
#define PLB 8192
#define STGB (4 * PLB)
#define NSTAGE 3
#define TPITCH 129

__device__ __forceinline__ uint32_t cvta_s(const void* p) {
    return (uint32_t)__cvta_generic_to_shared(p);
}
__device__ __forceinline__ void cp16(uint32_t s, const void* g) {
    asm volatile("cp.async.cg.shared.global [%0], [%1], 16;" :: "r"(s), "l"(g));
}
__device__ __forceinline__ void ldsm4(uint32_t& r0, uint32_t& r1, uint32_t& r2, uint32_t& r3, uint32_t a) {
    asm volatile("ldmatrix.sync.aligned.m8n8.x4.shared.b16 {%0,%1,%2,%3}, [%4];"
                 : "=r"(r0), "=r"(r1), "=r"(r2), "=r"(r3) : "r"(a));
}
__device__ __forceinline__ void mma16816(float* c, const uint32_t* a, const uint32_t* b) {
    asm volatile("mma.sync.aligned.m16n8k16.row.col.f32.f16.f16.f32 "
                 "{%0,%1,%2,%3},{%4,%5,%6,%7},{%8,%9},{%0,%1,%2,%3};"
                 : "+f"(c[0]), "+f"(c[1]), "+f"(c[2]), "+f"(c[3])
                 : "r"(a[0]), "r"(a[1]), "r"(a[2]), "r"(a[3]), "r"(b[0]), "r"(b[1]));
}
__device__ __forceinline__ uint32_t swz(int row, int chunk) {
    return (uint32_t)(row * 64 + ((chunk ^ ((row >> 1) & 3)) << 4));
}

// NT=1: C = Ah·Bh ; NT=2: C = (Ah+Al)·Bh ; NT=3: C = Ah·Bh + Al·Bh + Ah·Bl
template <int NT>
__device__ __forceinline__ void gemm_mainloop(
    const __half* Ah, const __half* Al,
    const __half* Bh, const __half* Bl,
    int brow, int bcol, int K, uint32_t sbase,
    int tid, int lane, int wm, int wn,
    float acc[2][8][4]) {

    int ldrow = tid >> 1;
    int ldc0 = (tid & 1) * 2;

    auto load_stage = [&](int slot, int k0) {
        uint32_t so = sbase + (uint32_t)(slot * STGB);
        size_t ga = (size_t)(brow + ldrow) * K + k0;
        size_t gb = (size_t)(bcol + ldrow) * K + k0;
        #pragma unroll
        for (int cc = 0; cc < 2; cc++) {
            int c = ldc0 + cc;
            uint32_t off = swz(ldrow, c);
            cp16(so + 0 * PLB + off, Ah + ga + c * 8);
            if (NT >= 2) cp16(so + 1 * PLB + off, Al + ga + c * 8);
            cp16(so + 2 * PLB + off, Bh + gb + c * 8);
            if (NT == 3) cp16(so + 3 * PLB + off, Bl + gb + c * 8);
        }
    };

    int nk = K >> 5;
    load_stage(0, 0);
    asm volatile("cp.async.commit_group;");
    load_stage(1, 32);
    asm volatile("cp.async.commit_group;");

    for (int kt = 0; kt < nk; kt++) {
        if (kt + 1 < nk) {
            asm volatile("cp.async.wait_group 1;");
        } else {
            asm volatile("cp.async.wait_group 0;");
        }
        __syncthreads();
        uint32_t so = sbase + (uint32_t)((kt % NSTAGE) * STGB);
        #pragma unroll
        for (int kk = 0; kk < 2; kk++) {
            uint32_t ah[2][4], al[2][4];
            int arow = wm * 32 + ((lane >> 3) & 1) * 8 + (lane & 7);
            int akof = kk * 16 + (lane >> 4) * 8;
            int achk = akof >> 3;
            #pragma unroll
            for (int mt = 0; mt < 2; mt++) {
                uint32_t addr = so + swz(arow + mt * 16, achk);
                ldsm4(ah[mt][0], ah[mt][1], ah[mt][2], ah[mt][3], addr);
                if (NT >= 2)
                    ldsm4(al[mt][0], al[mt][1], al[mt][2], al[mt][3], addr + PLB);
            }
            uint32_t bh[8][2], bl[8][2];
            int bphase = lane >> 3;
            int brl = wn * 64 + (lane & 7) + (bphase >> 1) * 8;
            int bkof = kk * 16 + (bphase & 1) * 8;
            int bchk = bkof >> 3;
            #pragma unroll
            for (int np = 0; np < 4; np++) {
                uint32_t addr = so + 2 * PLB + swz(brl + np * 16, bchk);
                uint32_t r0, r1, r2, r3;
                ldsm4(r0, r1, r2, r3, addr);
                bh[np * 2][0] = r0; bh[np * 2][1] = r1;
                bh[np * 2 + 1][0] = r2; bh[np * 2 + 1][1] = r3;
                if (NT == 3) {
                    ldsm4(r0, r1, r2, r3, addr + PLB);
                    bl[np * 2][0] = r0; bl[np * 2][1] = r1;
                    bl[np * 2 + 1][0] = r2; bl[np * 2 + 1][1] = r3;
                }
            }
            #pragma unroll
            for (int mt = 0; mt < 2; mt++)
                #pragma unroll
                for (int nt = 0; nt < 8; nt++)
                    mma16816(acc[mt][nt], ah[mt], bh[nt]);
            if (NT >= 2) {
                #pragma unroll
                for (int mt = 0; mt < 2; mt++)
                    #pragma unroll
                    for (int nt = 0; nt < 8; nt++)
                        mma16816(acc[mt][nt], al[mt], bh[nt]);
            }
            if (NT == 3) {
                #pragma unroll
                for (int mt = 0; mt < 2; mt++)
                    #pragma unroll
                    for (int nt = 0; nt < 8; nt++)
                        mma16816(acc[mt][nt], ah[mt], bl[nt]);
            }
        }
        if (kt + 2 < nk) {
            load_stage((kt + 2) % NSTAGE, (kt + 2) << 5);
            asm volatile("cp.async.commit_group;");
        }
    }
}

__device__ __forceinline__ void stage_acc(float* buf, float acc[2][8][4],
                                          const float* bias, int lane, int wm, int wn) {
    int gid = lane >> 2, tig = lane & 3;
    #pragma unroll
    for (int nt = 0; nt < 8; nt++) {
        int c = wn * 64 + nt * 8 + tig * 2;
        float b0 = bias ? bias[c] : 0.f;
        float b1 = bias ? bias[c + 1] : 0.f;
        #pragma unroll
        for (int mt = 0; mt < 2; mt++) {
            int r = wm * 32 + mt * 16 + gid;
            buf[r * TPITCH + c]           = acc[mt][nt][0] + b0;
            buf[r * TPITCH + c + 1]       = acc[mt][nt][1] + b1;
            buf[(r + 8) * TPITCH + c]     = acc[mt][nt][2] + b0;
            buf[(r + 8) * TPITCH + c + 1] = acc[mt][nt][3] + b1;
        }
    }
}

// generic TN GEMM (fp32 out and/or split fp16 out)
template <int NT>
__global__ __launch_bounds__(256, 2)
void mma_tn(const __half* __restrict__ Ah, const __half* __restrict__ Al,
            const __half* __restrict__ Bh, const __half* __restrict__ Bl,
            float* __restrict__ Cf,
            __half* __restrict__ Ch, __half* __restrict__ Cl,
            int M, int N, int K, float alpha,
            long long sA, long long sB, long long sC) {
    extern __shared__ __half smbuf[];
    long long zb = blockIdx.z;
    Ah += zb * sA;
    if (NT >= 2) Al += zb * sA;
    Bh += zb * sB;
    if (NT == 3) Bl += zb * sB;
    if (Cf) Cf += zb * sC;
    if (Ch) { Ch += zb * sC; Cl += zb * sC; }

    int tid = threadIdx.x;
    int lane = tid & 31, warp = tid >> 5;
    int wm = warp & 3, wn = warp >> 2;
    int brow = blockIdx.y * 128, bcol = blockIdx.x * 128;
    uint32_t sbase = cvta_s(smbuf);

    float acc[2][8][4];
    #pragma unroll
    for (int i = 0; i < 2; i++)
        #pragma unroll
        for (int j = 0; j < 8; j++)
            #pragma unroll
            for (int q = 0; q < 4; q++) acc[i][j][q] = 0.f;

    gemm_mainloop<NT>(Ah, Al, Bh, Bl, brow, bcol, K, sbase, tid, lane, wm, wn, acc);

    int gid = lane >> 2, tig = lane & 3;
    #pragma unroll
    for (int nt = 0; nt < 8; nt++) {
        int col = bcol + wn * 64 + nt * 8 + tig * 2;
        #pragma unroll
        for (int mt = 0; mt < 2; mt++) {
            int row0 = brow + wm * 32 + mt * 16 + gid;
            float v00 = acc[mt][nt][0] * alpha;
            float v01 = acc[mt][nt][1] * alpha;
            float v10 = acc[mt][nt][2] * alpha;
            float v11 = acc[mt][nt][3] * alpha;
            if (Cf) {
                float2 p0 = {v00, v01}, p1 = {v10, v11};
                *(float2*)(Cf + (size_t)row0 * N + col) = p0;
                *(float2*)(Cf + (size_t)(row0 + 8) * N + col) = p1;
            }
            if (Ch) {
                __half h00 = __float2half_rn(v00);
                __half h01 = __float2half_rn(v01);
                __half h10 = __float2half_rn(v10);
                __half h11 = __float2half_rn(v11);
                __half2 hh0 = {h00, h01}, hh1 = {h10, h11};
                __half2 ll0 = {__float2half_rn(v00 - __half2float(h00)),
                               __float2half_rn(v01 - __half2float(h01))};
                __half2 ll1 = {__float2half_rn(v10 - __half2float(h10)),
                               __float2half_rn(v11 - __half2float(h11))};
                *(__half2*)(Ch + (size_t)row0 * N + col) = hh0;
                *(__half2*)(Cl + (size_t)row0 * N + col) = ll0;
                *(__half2*)(Ch + (size_t)(row0 + 8) * N + col) = hh1;
                *(__half2*)(Cl + (size_t)(row0 + 8) * N + col) = ll1;
            }
        }
    }
}

// fused QKV projection (3-term); Q hi-only, K hi-only, V^T hi-only via transpose.
__global__ __launch_bounds__(256, 2)
void mma_qkv(const __half* __restrict__ Ah, const __half* __restrict__ Al,
             const __half* __restrict__ Bh, const __half* __restrict__ Bl,
             const float* __restrict__ bq, const float* __restrict__ bk,
             const float* __restrict__ bv,
             __half* __restrict__ Qh,
             __half* __restrict__ Kh,
             __half* __restrict__ Vth,
             int K) {
    extern __shared__ __half smbuf[];
    int tid = threadIdx.x;
    int lane = tid & 31, warp = tid >> 5;
    int wm = warp & 3, wn = warp >> 2;
    int brow = blockIdx.y * 128, bcol = blockIdx.x * 128;
    uint32_t sbase = cvta_s(smbuf);

    float acc[2][8][4];
    #pragma unroll
    for (int i = 0; i < 2; i++)
        #pragma unroll
        for (int j = 0; j < 8; j++)
            #pragma unroll
            for (int q = 0; q < 4; q++) acc[i][j][q] = 0.f;

    gemm_mainloop<3>(Ah, Al, Bh, Bl, brow, bcol, K, sbase, tid, lane, wm, wn, acc);

    int sec = bcol >> 9;            // 0=q 1=k 2=v
    int colbase = bcol & 511;

    if (sec == 2) {
        // V: transpose epilogue -> Vt[b][d][m] hi plane
        __syncthreads();
        float* buf = (float*)smbuf;
        stage_acc(buf, acc, bv + colbase, lane, wm, wn);
        __syncthreads();
        int d = tid >> 1, mh = tid & 1;
        int b = brow >> 12, m0 = (brow & 4095) + mh * 64;
        size_t base = ((size_t)b * Cc + colbase + d) * Nn + m0;
        #pragma unroll 8
        for (int i = 0; i < 32; i++) {
            float f0 = buf[(mh * 64 + 2 * i) * TPITCH + d];
            float f1 = buf[(mh * 64 + 2 * i + 1) * TPITCH + d];
            __half2 hh = {__float2half_rn(f0), __float2half_rn(f1)};
            *(__half2*)(Vth + base + 2 * i) = hh;
        }
        return;
    }

    const float* bias = (sec == 0) ? bq : bk;
    __half* Ch = (sec == 0) ? Qh : Kh;
    int gid = lane >> 2, tig = lane & 3;
    #pragma unroll
    for (int nt = 0; nt < 8; nt++) {
        int col = colbase + wn * 64 + nt * 8 + tig * 2;
        float b0 = bias[col], b1 = bias[col + 1];
        #pragma unroll
        for (int mt = 0; mt < 2; mt++) {
            int row0 = brow + wm * 32 + mt * 16 + gid;
            __half2 hh0 = {__float2half_rn(acc[mt][nt][0] + b0),
                           __float2half_rn(acc[mt][nt][1] + b1)};
            __half2 hh1 = {__float2half_rn(acc[mt][nt][2] + b0),
                           __float2half_rn(acc[mt][nt][3] + b1)};
            *(__half2*)(Ch + (size_t)row0 * Cc + col) = hh0;
            *(__half2*)(Ch + (size_t)(row0 + 8) * Cc + col) = hh1;
        }
    }
}

// final projection (3-term) fused with residual + transpose-back
__global__ __launch_bounds__(256, 2)
void mma_resid(const __half* __restrict__ Ah, const __half* __restrict__ Al,
               const __half* __restrict__ Bh, const __half* __restrict__ Bl,
               const float* __restrict__ bias,
               const float* __restrict__ x, float* __restrict__ out,
               int K) {
    extern __shared__ __half smbuf[];
    int tid = threadIdx.x;
    int lane = tid & 31, warp = tid >> 5;
    int wm = warp & 3, wn = warp >> 2;
    int brow = blockIdx.y * 128, bcol = blockIdx.x * 128;
    uint32_t sbase = cvta_s(smbuf);

    float acc[2][8][4];
    #pragma unroll
    for (int i = 0; i < 2; i++)
        #pragma unroll
        for (int j = 0; j < 8; j++)
            #pragma unroll
            for (int q = 0; q < 4; q++) acc[i][j][q] = 0.f;

    gemm_mainloop<3>(Ah, Al, Bh, Bl, brow, bcol, K, sbase, tid, lane, wm, wn, acc);

    __syncthreads();
    float* buf = (float*)smbuf;
    stage_acc(buf, acc, bias + bcol, lane, wm, wn);
    __syncthreads();

    int c = tid >> 1, nh = tid & 1;
    int b = brow >> 12, n0 = (brow & 4095) + nh * 64;
    size_t base = ((size_t)b * Cc + bcol + c) * Nn + n0;
    #pragma unroll
    for (int i = 0; i < 16; i++) {
        float4 xv = *(const float4*)(x + base + 4 * i);
        float4 o;
        o.x = xv.x + buf[(nh * 64 + 4 * i + 0) * TPITCH + c];
        o.y = xv.y + buf[(nh * 64 + 4 * i + 1) * TPITCH + c];
        o.z = xv.z + buf[(nh * 64 + 4 * i + 2) * TPITCH + c];
        o.w = xv.w + buf[(nh * 64 + 4 * i + 3) * TPITCH + c];
        *(float4*)(out + base + 4 * i) = o;
    }
}

// ---------------- softmax rows of g_s -> fp16 probs (hi only) ----------------
__global__ void softmax_kernel() {
    size_t row = blockIdx.x;
    float4* p = (float4*)(g_s + row * Nn);
    int tid = threadIdx.x;
    int lane = tid & 31, warp = tid >> 5;
    __shared__ float sm1[8], sm2[8];
    float4 v[4];
    float mx = -1e30f;
    #pragma unroll
    for (int i = 0; i < 4; i++) {
        v[i] = p[tid + i * 256];
        mx = fmaxf(mx, fmaxf(fmaxf(v[i].x, v[i].y), fmaxf(v[i].z, v[i].w)));
    }
    #pragma unroll
    for (int o = 16; o > 0; o >>= 1) mx = fmaxf(mx, __shfl_xor_sync(~0u, mx, o));
    if (lane == 0) sm1[warp] = mx;
    __syncthreads();
    mx = sm1[0];
    #pragma unroll
    for (int j = 1; j < 8; j++) mx = fmaxf(mx, sm1[j]);

    float s = 0.f;
    #pragma unroll
    for (int i = 0; i < 4; i++) {
        v[i].x = __expf(v[i].x - mx); v[i].y = __expf(v[i].y - mx);
        v[i].z = __expf(v[i].z - mx); v[i].w = __expf(v[i].w - mx);
        s += v[i].x + v[i].y + v[i].z + v[i].w;
    }
    #pragma unroll
    for (int o = 16; o > 0; o >>= 1) s += __shfl_xor_sync(~0u, s, o);
    if (lane == 0) sm2[warp] = s;
    __syncthreads();
    s = 0.f;
    #pragma unroll
    for (int j = 0; j < 8; j++) s += sm2[j];
    float inv = 1.f / s;

    #pragma unroll
    for (int i = 0; i < 4; i++) {
        size_t base = row * Nn + (size_t)(tid + i * 256) * 4;
        __half2 hh0 = {__float2half_rn(v[i].x * inv), __float2half_rn(v[i].y * inv)};
        __half2 hh1 = {__float2half_rn(v[i].z * inv), __float2half_rn(v[i].w * inv)};
        ((__half2*)(g_ph + base))[0] = hh0;
        ((__half2*)(g_ph + base))[1] = hh1;
    }
}

// ---------------- launch ----------------
extern "C" void kernel_launch(void* const* d_in, const int* in_sizes, int n_in,
                              void* d_out, int out_size) {
    const float* x    = (const float*)d_in[0];
    const float* gn_w = (const float*)d_in[1];
    const float* gn_b = (const float*)d_in[2];
    const float* wq   = (const float*)d_in[3];
    const float* bq   = (const float*)d_in[4];
    const float* wk   = (const float*)d_in[5];
    const float* bk   = (const float*)d_in[6];
    const float* wv   = (const float*)d_in[7];
    const float* bv   = (const float*)d_in[8];
    const float* wo   = (const float*)d_in[9];
    const float* bo   = (const float*)d_in[10];
    float* out = (float*)d_out;

    __half *hh, *hl, *w4h, *w4l, *qh, *kh, *vth, *ph, *aoh, *aol;
    float *s;
    cudaGetSymbolAddress((void**)&hh, g_hh);   cudaGetSymbolAddress((void**)&hl, g_hl);
    cudaGetSymbolAddress((void**)&w4h, g_w4h); cudaGetSymbolAddress((void**)&w4l, g_w4l);
    cudaGetSymbolAddress((void**)&qh, g_qh);
    cudaGetSymbolAddress((void**)&kh, g_kh);
    cudaGetSymbolAddress((void**)&vth, g_vth);
    cudaGetSymbolAddress((void**)&ph, g_ph);
    cudaGetSymbolAddress((void**)&aoh, g_aoh); cudaGetSymbolAddress((void**)&aol, g_aol);
    cudaGetSymbolAddress((void**)&s, g_s);

    const int Mtot = Bb * Nn;                        // 32768
    const float scale = 0.044194173824159216f;       // 1/sqrt(512)
    const int WSZ = Cc * Cc;                         // 262144
    const int SMEM = NSTAGE * STGB;                  // 96 KB

    cudaFuncSetAttribute(mma_tn<1>, cudaFuncAttributeMaxDynamicSharedMemorySize, SMEM);
    cudaFuncSetAttribute(mma_qkv, cudaFuncAttributeMaxDynamicSharedMemorySize, SMEM);
    cudaFuncSetAttribute(mma_resid, cudaFuncAttributeMaxDynamicSharedMemorySize, SMEM);

    gn_stats1_kernel<<<512, 256>>>(x);
    gn_stats2_kernel<<<2, 32>>>();
    gn_apply_kernel<<<dim3(Nn / 32, Cc / 32, Bb), dim3(32, 32)>>>(x, gn_w, gn_b);
    split_kernel<<<WSZ / 1024, 256>>>(wq, w4h + 0 * WSZ, w4l + 0 * WSZ);
    split_kernel<<<WSZ / 1024, 256>>>(wk, w4h + 1 * WSZ, w4l + 1 * WSZ);
    split_kernel<<<WSZ / 1024, 256>>>(wv, w4h + 2 * WSZ, w4l + 2 * WSZ);
    split_kernel<<<WSZ / 1024, 256>>>(wo, w4h + 3 * WSZ, w4l + 3 * WSZ);

    // fused QKV projection (3-term fp16; outputs hi-only q/k/vt)
    mma_qkv<<<dim3(12, Mtot / 128), 256, SMEM>>>(hh, hl, w4h, w4l,
                                                 bq, bk, bv, qh, kh, vth, Cc);
    // scores = q k^T * scale  (1-term fp16)
    mma_tn<1><<<dim3(Nn / 128, Nn / 128, Bb), 256, SMEM>>>(qh, nullptr, kh, nullptr,
                                 s, nullptr, nullptr, Nn, Nn, Cc, scale, NCs, NCs, NNs);
    softmax_kernel<<<Bb * Nn, 256>>>();
    // attn out = P @ V  (1-term fp16)
    mma_tn<1><<<dim3(Cc / 128, Nn / 128, Bb), 256, SMEM>>>(ph, nullptr, vth, nullptr,
                                 nullptr, aoh, aol, Nn, Cc, Nn, 1.f, NNs, NCs, NCs);
    // final projection (3-term) + residual + transpose-back
    mma_resid<<<dim3(Cc / 128, Mtot / 128), 256, SMEM>>>(aoh, aol,
                                 w4h + 3 * WSZ, w4l + 3 * WSZ, bo, x, out, Cc);
}

// round 12
// speedup vs baseline: 2.5924x; 1.1304x over previous
#include <cuda_runtime.h>
#include <cuda_fp16.h>
#include <math.h>
#include <stdint.h>

#define Cc 512
#define Bb 8
#define Nn 4096
#define GROUPS 8
#define EPS 1e-5f

#define MC ((size_t)Bb * Nn * Cc)
#define SC ((size_t)Bb * Nn * Nn)
#define NCs ((long long)Nn * Cc)
#define NNs ((long long)Nn * Nn)

// ---------------- scratch ----------------
__device__ __half g_hh[MC], g_hl[MC];
__device__ __half g_w4h[4 * Cc * Cc];
__device__ __half g_qh[MC];
__device__ __half g_kh[MC];
__device__ __half g_vth[MC];
__device__ __half g_sh[SC];            // scores fp16
__device__ __half g_ph[SC];            // probs fp16
__device__ __half g_aoh[MC], g_aol[MC];
__device__ float  g_stats[Bb * GROUPS * 2];
__device__ float  g_part[512 * 2];

__device__ __forceinline__ void split_store(float v, __half* ph, __half* pl) {
    __half h = __float2half_rn(v);
    *ph = h;
    *pl = __float2half_rn(v - __half2float(h));
}

// ---------------- 1) group-norm statistics (two-phase) ----------------
__global__ void gn_stats1_kernel(const float* __restrict__ x) {
    int blk = blockIdx.x;
    int bg = blk >> 3, sub = blk & 7;
    const size_t cnt = (size_t)(Cc / GROUPS) * Nn;
    const float4* p = (const float4*)(x + (size_t)bg * cnt + (size_t)sub * (cnt / 8));
    int tid = threadIdx.x;
    float s = 0.f, sq = 0.f;
    #pragma unroll 4
    for (int i = tid; i < (int)(cnt / 8 / 4); i += 256) {
        float4 v = p[i];
        s  += v.x + v.y + v.z + v.w;
        sq += v.x * v.x + v.y * v.y + v.z * v.z + v.w * v.w;
    }
    int lane = tid & 31, warp = tid >> 5;
    #pragma unroll
    for (int o = 16; o > 0; o >>= 1) {
        s  += __shfl_xor_sync(~0u, s, o);
        sq += __shfl_xor_sync(~0u, sq, o);
    }
    __shared__ float ss[8], ssq[8];
    if (lane == 0) { ss[warp] = s; ssq[warp] = sq; }
    __syncthreads();
    if (tid == 0) {
        float ts = 0.f, tq = 0.f;
        #pragma unroll
        for (int j = 0; j < 8; j++) { ts += ss[j]; tq += ssq[j]; }
        g_part[blk * 2 + 0] = ts;
        g_part[blk * 2 + 1] = tq;
    }
}
__global__ void gn_stats2_kernel() {
    int bg = blockIdx.x * blockDim.x + threadIdx.x;
    if (bg >= Bb * GROUPS) return;
    const float cnt = (float)((Cc / GROUPS) * Nn);
    float s = 0.f, sq = 0.f;
    #pragma unroll
    for (int j = 0; j < 8; j++) {
        s  += g_part[(bg * 8 + j) * 2 + 0];
        sq += g_part[(bg * 8 + j) * 2 + 1];
    }
    float mu = s / cnt;
    float var = sq / cnt - mu * mu;
    g_stats[bg * 2 + 0] = mu;
    g_stats[bg * 2 + 1] = rsqrtf(var + EPS);
}

// ---------------- 2) GN apply + transpose -> split fp16 [B,N,C] ----------------
__global__ void gn_apply_kernel(const float* __restrict__ x,
                                const float* __restrict__ w,
                                const float* __restrict__ b) {
    __shared__ float sm[32][33];
    int bz = blockIdx.z;
    int n0 = blockIdx.x * 32;
    int c0 = blockIdx.y * 32;
    int tx = threadIdx.x, ty = threadIdx.y;
    {
        int c = c0 + ty, n = n0 + tx;
        int g = c >> 6;
        float mu   = g_stats[(bz * GROUPS + g) * 2 + 0];
        float rstd = g_stats[(bz * GROUPS + g) * 2 + 1];
        float v = x[((size_t)bz * Cc + c) * Nn + n];
        sm[ty][tx] = (v - mu) * rstd * w[c] + b[c];
    }
    __syncthreads();
    {
        int n = n0 + ty, c = c0 + tx;
        size_t idx = ((size_t)bz * Nn + n) * Cc + c;
        split_store(sm[tx][ty], g_hh + idx, g_hl + idx);
    }
}

// weight convert: fp32 -> fp16 hi only
__global__ void cvt_kernel(const float* __restrict__ src, __half* __restrict__ dh) {
    int i = (blockIdx.x * 256 + threadIdx.x) * 4;
    float4 v = *(const float4*)(src + i);
    __half2 hh0 = {__float2half_rn(v.x), __float2half_rn(v.y)};
    __half2 hh1 = {__float2half_rn(v.z), __float2half_rn(v.w)};
    ((__half2*)(dh + i))[0] = hh0;
    ((__half2*)(dh + i))[1] = hh1;
}

// ---------------- tensor-core TN GEMM machinery (fp16, 1/2-term) ----------------
#define PLB 8192
#define STGB (4 * PLB)
#define NSTAGE 3
#define TPITCH 129

__device__ __forceinline__ uint32_t cvta_s(const void* p) {
    return (uint32_t)__cvta_generic_to_shared(p);
}
__device__ __forceinline__ void cp16(uint32_t s, const void* g) {
    asm volatile("cp.async.cg.shared.global [%0], [%1], 16;" :: "r"(s), "l"(g));
}
__device__ __forceinline__ void ldsm4(uint32_t& r0, uint32_t& r1, uint32_t& r2, uint32_t& r3, uint32_t a) {
    asm volatile("ldmatrix.sync.aligned.m8n8.x4.shared.b16 {%0,%1,%2,%3}, [%4];"
                 : "=r"(r0), "=r"(r1), "=r"(r2), "=r"(r3) : "r"(a));
}
__device__ __forceinline__ void mma16816(float* c, const uint32_t* a, const uint32_t* b) {
    asm volatile("mma.sync.aligned.m16n8k16.row.col.f32.f16.f16.f32 "
                 "{%0,%1,%2,%3},{%4,%5,%6,%7},{%8,%9},{%0,%1,%2,%3};"
                 : "+f"(c[0]), "+f"(c[1]), "+f"(c[2]), "+f"(c[3])
                 : "r"(a[0]), "r"(a[1]), "r"(a[2]), "r"(a[3]), "r"(b[0]), "r"(b[1]));
}
__device__ __forceinline__ uint32_t swz(int row, int chunk) {
    return (uint32_t)(row * 64 + ((chunk ^ ((row >> 1) & 3)) << 4));
}

// NT=1: C = Ah·Bh ; NT=2: C = (Ah+Al)·Bh
template <int NT>
__device__ __forceinline__ void gemm_mainloop(
    const __half* Ah, const __half* Al,
    const __half* Bh,
    int brow, int bcol, int K, uint32_t sbase,
    int tid, int lane, int wm, int wn,
    float acc[2][8][4]) {

    int ldrow = tid >> 1;
    int ldc0 = (tid & 1) * 2;

    auto load_stage = [&](int slot, int k0) {
        uint32_t so = sbase + (uint32_t)(slot * STGB);
        size_t ga = (size_t)(brow + ldrow) * K + k0;
        size_t gb = (size_t)(bcol + ldrow) * K + k0;
        #pragma unroll
        for (int cc = 0; cc < 2; cc++) {
            int c = ldc0 + cc;
            uint32_t off = swz(ldrow, c);
            cp16(so + 0 * PLB + off, Ah + ga + c * 8);
            if (NT >= 2) cp16(so + 1 * PLB + off, Al + ga + c * 8);
            cp16(so + 2 * PLB + off, Bh + gb + c * 8);
        }
    };

    int nk = K >> 5;
    load_stage(0, 0);
    asm volatile("cp.async.commit_group;");
    load_stage(1, 32);
    asm volatile("cp.async.commit_group;");

    for (int kt = 0; kt < nk; kt++) {
        if (kt + 1 < nk) {
            asm volatile("cp.async.wait_group 1;");
        } else {
            asm volatile("cp.async.wait_group 0;");
        }
        __syncthreads();
        uint32_t so = sbase + (uint32_t)((kt % NSTAGE) * STGB);
        #pragma unroll
        for (int kk = 0; kk < 2; kk++) {
            uint32_t ah[2][4], al[2][4];
            int arow = wm * 32 + ((lane >> 3) & 1) * 8 + (lane & 7);
            int akof = kk * 16 + (lane >> 4) * 8;
            int achk = akof >> 3;
            #pragma unroll
            for (int mt = 0; mt < 2; mt++) {
                uint32_t addr = so + swz(arow + mt * 16, achk);
                ldsm4(ah[mt][0], ah[mt][1], ah[mt][2], ah[mt][3], addr);
                if (NT >= 2)
                    ldsm4(al[mt][0], al[mt][1], al[mt][2], al[mt][3], addr + PLB);
            }
            uint32_t bh[8][2];
            int bphase = lane >> 3;
            int brl = wn * 64 + (lane & 7) + (bphase >> 1) * 8;
            int bkof = kk * 16 + (bphase & 1) * 8;
            int bchk = bkof >> 3;
            #pragma unroll
            for (int np = 0; np < 4; np++) {
                uint32_t addr = so + 2 * PLB + swz(brl + np * 16, bchk);
                uint32_t r0, r1, r2, r3;
                ldsm4(r0, r1, r2, r3, addr);
                bh[np * 2][0] = r0; bh[np * 2][1] = r1;
                bh[np * 2 + 1][0] = r2; bh[np * 2 + 1][1] = r3;
            }
            #pragma unroll
            for (int mt = 0; mt < 2; mt++)
                #pragma unroll
                for (int nt = 0; nt < 8; nt++)
                    mma16816(acc[mt][nt], ah[mt], bh[nt]);
            if (NT >= 2) {
                #pragma unroll
                for (int mt = 0; mt < 2; mt++)
                    #pragma unroll
                    for (int nt = 0; nt < 8; nt++)
                        mma16816(acc[mt][nt], al[mt], bh[nt]);
            }
        }
        if (kt + 2 < nk) {
            load_stage((kt + 2) % NSTAGE, (kt + 2) << 5);
            asm volatile("cp.async.commit_group;");
        }
    }
}

__device__ __forceinline__ void stage_acc(float* buf, float acc[2][8][4],
                                          const float* bias, int lane, int wm, int wn) {
    int gid = lane >> 2, tig = lane & 3;
    #pragma unroll
    for (int nt = 0; nt < 8; nt++) {
        int c = wn * 64 + nt * 8 + tig * 2;
        float b0 = bias ? bias[c] : 0.f;
        float b1 = bias ? bias[c + 1] : 0.f;
        #pragma unroll
        for (int mt = 0; mt < 2; mt++) {
            int r = wm * 32 + mt * 16 + gid;
            buf[r * TPITCH + c]           = acc[mt][nt][0] + b0;
            buf[r * TPITCH + c + 1]       = acc[mt][nt][1] + b1;
            buf[(r + 8) * TPITCH + c]     = acc[mt][nt][2] + b0;
            buf[(r + 8) * TPITCH + c + 1] = acc[mt][nt][3] + b1;
        }
    }
}

// generic TN GEMM; output: fp16 hi (Ch) + optional lo (Cl)
template <int NT>
__global__ __launch_bounds__(256, 2)
void mma_tn(const __half* __restrict__ Ah, const __half* __restrict__ Al,
            const __half* __restrict__ Bh,
            __half* __restrict__ Ch, __half* __restrict__ Cl,
            int M, int N, int K, float alpha,
            long long sA, long long sB, long long sC) {
    extern __shared__ __half smbuf[];
    long long zb = blockIdx.z;
    Ah += zb * sA;
    if (NT >= 2) Al += zb * sA;
    Bh += zb * sB;
    Ch += zb * sC;
    if (Cl) Cl += zb * sC;

    int tid = threadIdx.x;
    int lane = tid & 31, warp = tid >> 5;
    int wm = warp & 3, wn = warp >> 2;
    int brow = blockIdx.y * 128, bcol = blockIdx.x * 128;
    uint32_t sbase = cvta_s(smbuf);

    float acc[2][8][4];
    #pragma unroll
    for (int i = 0; i < 2; i++)
        #pragma unroll
        for (int j = 0; j < 8; j++)
            #pragma unroll
            for (int q = 0; q < 4; q++) acc[i][j][q] = 0.f;

    gemm_mainloop<NT>(Ah, Al, Bh, brow, bcol, K, sbase, tid, lane, wm, wn, acc);

    int gid = lane >> 2, tig = lane & 3;
    #pragma unroll
    for (int nt = 0; nt < 8; nt++) {
        int col = bcol + wn * 64 + nt * 8 + tig * 2;
        #pragma unroll
        for (int mt = 0; mt < 2; mt++) {
            int row0 = brow + wm * 32 + mt * 16 + gid;
            float v00 = acc[mt][nt][0] * alpha;
            float v01 = acc[mt][nt][1] * alpha;
            float v10 = acc[mt][nt][2] * alpha;
            float v11 = acc[mt][nt][3] * alpha;
            __half h00 = __float2half_rn(v00);
            __half h01 = __float2half_rn(v01);
            __half h10 = __float2half_rn(v10);
            __half h11 = __float2half_rn(v11);
            __half2 hh0 = {h00, h01}, hh1 = {h10, h11};
            *(__half2*)(Ch + (size_t)row0 * N + col) = hh0;
            *(__half2*)(Ch + (size_t)(row0 + 8) * N + col) = hh1;
            if (Cl) {
                __half2 ll0 = {__float2half_rn(v00 - __half2float(h00)),
                               __float2half_rn(v01 - __half2float(h01))};
                __half2 ll1 = {__float2half_rn(v10 - __half2float(h10)),
                               __float2half_rn(v11 - __half2float(h11))};
                *(__half2*)(Cl + (size_t)row0 * N + col) = ll0;
                *(__half2*)(Cl + (size_t)(row0 + 8) * N + col) = ll1;
            }
        }
    }
}

// fused QKV projection (2-term); Q hi-only, K hi-only, V^T hi-only via transpose.
__global__ __launch_bounds__(256, 2)
void mma_qkv(const __half* __restrict__ Ah, const __half* __restrict__ Al,
             const __half* __restrict__ Bh,
             const float* __restrict__ bq, const float* __restrict__ bk,
             const float* __restrict__ bv,
             __half* __restrict__ Qh,
             __half* __restrict__ Kh,
             __half* __restrict__ Vth,
             int K) {
    extern __shared__ __half smbuf[];
    int tid = threadIdx.x;
    int lane = tid & 31, warp = tid >> 5;
    int wm = warp & 3, wn = warp >> 2;
    int brow = blockIdx.y * 128, bcol = blockIdx.x * 128;
    uint32_t sbase = cvta_s(smbuf);

    float acc[2][8][4];
    #pragma unroll
    for (int i = 0; i < 2; i++)
        #pragma unroll
        for (int j = 0; j < 8; j++)
            #pragma unroll
            for (int q = 0; q < 4; q++) acc[i][j][q] = 0.f;

    gemm_mainloop<2>(Ah, Al, Bh, brow, bcol, K, sbase, tid, lane, wm, wn, acc);

    int sec = bcol >> 9;            // 0=q 1=k 2=v
    int colbase = bcol & 511;

    if (sec == 2) {
        __syncthreads();
        float* buf = (float*)smbuf;
        stage_acc(buf, acc, bv + colbase, lane, wm, wn);
        __syncthreads();
        int d = tid >> 1, mh = tid & 1;
        int b = brow >> 12, m0 = (brow & 4095) + mh * 64;
        size_t base = ((size_t)b * Cc + colbase + d) * Nn + m0;
        #pragma unroll 8
        for (int i = 0; i < 32; i++) {
            float f0 = buf[(mh * 64 + 2 * i) * TPITCH + d];
            float f1 = buf[(mh * 64 + 2 * i + 1) * TPITCH + d];
            __half2 hh = {__float2half_rn(f0), __float2half_rn(f1)};
            *(__half2*)(Vth + base + 2 * i) = hh;
        }
        return;
    }

    const float* bias = (sec == 0) ? bq : bk;
    __half* Ch = (sec == 0) ? Qh : Kh;
    int gid = lane >> 2, tig = lane & 3;
    #pragma unroll
    for (int nt = 0; nt < 8; nt++) {
        int col = colbase + wn * 64 + nt * 8 + tig * 2;
        float b0 = bias[col], b1 = bias[col + 1];
        #pragma unroll
        for (int mt = 0; mt < 2; mt++) {
            int row0 = brow + wm * 32 + mt * 16 + gid;
            __half2 hh0 = {__float2half_rn(acc[mt][nt][0] + b0),
                           __float2half_rn(acc[mt][nt][1] + b1)};
            __half2 hh1 = {__float2half_rn(acc[mt][nt][2] + b0),
                           __float2half_rn(acc[mt][nt][3] + b1)};
            *(__half2*)(Ch + (size_t)row0 * Cc + col) = hh0;
            *(__half2*)(Ch + (size_t)(row0 + 8) * Cc + col) = hh1;
        }
    }
}

// final projection (2-term) fused with residual + transpose-back
__global__ __launch_bounds__(256, 2)
void mma_resid(const __half* __restrict__ Ah, const __half* __restrict__ Al,
               const __half* __restrict__ Bh,
               const float* __restrict__ bias,
               const float* __restrict__ x, float* __restrict__ out,
               int K) {
    extern __shared__ __half smbuf[];
    int tid = threadIdx.x;
    int lane = tid & 31, warp = tid >> 5;
    int wm = warp & 3, wn = warp >> 2;
    int brow = blockIdx.y * 128, bcol = blockIdx.x * 128;
    uint32_t sbase = cvta_s(smbuf);

    float acc[2][8][4];
    #pragma unroll
    for (int i = 0; i < 2; i++)
        #pragma unroll
        for (int j = 0; j < 8; j++)
            #pragma unroll
            for (int q = 0; q < 4; q++) acc[i][j][q] = 0.f;

    gemm_mainloop<2>(Ah, Al, Bh, brow, bcol, K, sbase, tid, lane, wm, wn, acc);

    __syncthreads();
    float* buf = (float*)smbuf;
    stage_acc(buf, acc, bias + bcol, lane, wm, wn);
    __syncthreads();

    int c = tid >> 1, nh = tid & 1;
    int b = brow >> 12, n0 = (brow & 4095) + nh * 64;
    size_t base = ((size_t)b * Cc + bcol + c) * Nn + n0;
    #pragma unroll
    for (int i = 0; i < 16; i++) {
        float4 xv = *(const float4*)(x + base + 4 * i);
        float4 o;
        o.x = xv.x + buf[(nh * 64 + 4 * i + 0) * TPITCH + c];
        o.y = xv.y + buf[(nh * 64 + 4 * i + 1) * TPITCH + c];
        o.z = xv.z + buf[(nh * 64 + 4 * i + 2) * TPITCH + c];
        o.w = xv.w + buf[(nh * 64 + 4 * i + 3) * TPITCH + c];
        *(float4*)(out + base + 4 * i) = o;
    }
}

// ---------------- softmax rows of fp16 scores -> fp16 probs ----------------
__global__ void softmax_kernel() {
    size_t row = blockIdx.x;
    __half2* p = (__half2*)(g_sh + row * Nn);
    __half2* q = (__half2*)(g_ph + row * Nn);
    int tid = threadIdx.x;
    int lane = tid & 31, warp = tid >> 5;
    __shared__ float sm1[8], sm2[8];
    float v[16];
    float mx = -1e30f;
    #pragma unroll
    for (int i = 0; i < 8; i++) {
        float2 f = __half22float2(p[tid + i * 256]);
        v[i * 2] = f.x; v[i * 2 + 1] = f.y;
        mx = fmaxf(mx, fmaxf(f.x, f.y));
    }
    #pragma unroll
    for (int o = 16; o > 0; o >>= 1) mx = fmaxf(mx, __shfl_xor_sync(~0u, mx, o));
    if (lane == 0) sm1[warp] = mx;
    __syncthreads();
    mx = sm1[0];
    #pragma unroll
    for (int j = 1; j < 8; j++) mx = fmaxf(mx, sm1[j]);

    float s = 0.f;
    #pragma unroll
    for (int i = 0; i < 16; i++) {
        v[i] = __expf(v[i] - mx);
        s += v[i];
    }
    #pragma unroll
    for (int o = 16; o > 0; o >>= 1) s += __shfl_xor_sync(~0u, s, o);
    if (lane == 0) sm2[warp] = s;
    __syncthreads();
    s = 0.f;
    #pragma unroll
    for (int j = 0; j < 8; j++) s += sm2[j];
    float inv = 1.f / s;

    #pragma unroll
    for (int i = 0; i < 8; i++) {
        __half2 hh = {__float2half_rn(v[i * 2] * inv),
                      __float2half_rn(v[i * 2 + 1] * inv)};
        q[tid + i * 256] = hh;
    }
}

// ---------------- launch ----------------
extern "C" void kernel_launch(void* const* d_in, const int* in_sizes, int n_in,
                              void* d_out, int out_size) {
    const float* x    = (const float*)d_in[0];
    const float* gn_w = (const float*)d_in[1];
    const float* gn_b = (const float*)d_in[2];
    const float* wq   = (const float*)d_in[3];
    const float* bq   = (const float*)d_in[4];
    const float* wk   = (const float*)d_in[5];
    const float* bk   = (const float*)d_in[6];
    const float* wv   = (const float*)d_in[7];
    const float* bv   = (const float*)d_in[8];
    const float* wo   = (const float*)d_in[9];
    const float* bo   = (const float*)d_in[10];
    float* out = (float*)d_out;

    __half *hh, *hl, *w4h, *qh, *kh, *vth, *sh, *ph, *aoh, *aol;
    cudaGetSymbolAddress((void**)&hh, g_hh);   cudaGetSymbolAddress((void**)&hl, g_hl);
    cudaGetSymbolAddress((void**)&w4h, g_w4h);
    cudaGetSymbolAddress((void**)&qh, g_qh);
    cudaGetSymbolAddress((void**)&kh, g_kh);
    cudaGetSymbolAddress((void**)&vth, g_vth);
    cudaGetSymbolAddress((void**)&sh, g_sh);
    cudaGetSymbolAddress((void**)&ph, g_ph);
    cudaGetSymbolAddress((void**)&aoh, g_aoh); cudaGetSymbolAddress((void**)&aol, g_aol);

    const int Mtot = Bb * Nn;                        // 32768
    const float scale = 0.044194173824159216f;       // 1/sqrt(512)
    const int WSZ = Cc * Cc;                         // 262144
    const int SMEM = NSTAGE * STGB;                  // 96 KB

    cudaFuncSetAttribute(mma_tn<1>, cudaFuncAttributeMaxDynamicSharedMemorySize, SMEM);
    cudaFuncSetAttribute(mma_qkv, cudaFuncAttributeMaxDynamicSharedMemorySize, SMEM);
    cudaFuncSetAttribute(mma_resid, cudaFuncAttributeMaxDynamicSharedMemorySize, SMEM);

    gn_stats1_kernel<<<512, 256>>>(x);
    gn_stats2_kernel<<<2, 32>>>();
    gn_apply_kernel<<<dim3(Nn / 32, Cc / 32, Bb), dim3(32, 32)>>>(x, gn_w, gn_b);
    cvt_kernel<<<WSZ / 1024, 256>>>(wq, w4h + 0 * WSZ);
    cvt_kernel<<<WSZ / 1024, 256>>>(wk, w4h + 1 * WSZ);
    cvt_kernel<<<WSZ / 1024, 256>>>(wv, w4h + 2 * WSZ);
    cvt_kernel<<<WSZ / 1024, 256>>>(wo, w4h + 3 * WSZ);

    // fused QKV projection (2-term fp16; outputs hi-only q/k/vt)
    mma_qkv<<<dim3(12, Mtot / 128), 256, SMEM>>>(hh, hl, w4h,
                                                 bq, bk, bv, qh, kh, vth, Cc);
    // scores = q k^T * scale  (1-term fp16, fp16 out)
    mma_tn<1><<<dim3(Nn / 128, Nn / 128, Bb), 256, SMEM>>>(qh, nullptr, kh,
                                 sh, nullptr, Nn, Nn, Cc, scale, NCs, NCs, NNs);
    softmax_kernel<<<Bb * Nn, 256>>>();
    // attn out = P @ V  (1-term fp16, split out for 2-term O-proj)
    mma_tn<1><<<dim3(Cc / 128, Nn / 128, Bb), 256, SMEM>>>(ph, nullptr, vth,
                                 aoh, aol, Nn, Cc, Nn, 1.f, NNs, NCs, NCs);
    // final projection (2-term) + residual + transpose-back
    mma_resid<<<dim3(Cc / 128, Mtot / 128), 256, SMEM>>>(aoh, aol,
                                 w4h + 3 * WSZ, bo, x, out, Cc);
}

// round 13
// speedup vs baseline: 2.9003x; 1.1188x over previous
#include <cuda_runtime.h>
#include <cuda_fp16.h>
#include <math.h>
#include <stdint.h>

#define Cc 512
#define Bb 8
#define Nn 4096
#define GROUPS 8
#define EPS 1e-5f

#define MC ((size_t)Bb * Nn * Cc)
#define SC ((size_t)Bb * Nn * Nn)
#define NCs ((long long)Nn * Cc)
#define NNs ((long long)Nn * Nn)

// ---------------- scratch ----------------
__device__ __half g_hh[MC];
__device__ __half g_w4h[4 * Cc * Cc];
__device__ __half g_qh[MC];
__device__ __half g_kh[MC];
__device__ __half g_vth[MC];
__device__ __half g_sh[SC];            // scores fp16
__device__ __half g_ph[SC];            // probs fp16
__device__ __half g_aoh[MC];
__device__ float  g_stats[Bb * GROUPS * 2];
__device__ float  g_part[512 * 2];

// ---------------- 1) group-norm statistics (two-phase) ----------------
__global__ void gn_stats1_kernel(const float* __restrict__ x) {
    int blk = blockIdx.x;
    int bg = blk >> 3, sub = blk & 7;
    const size_t cnt = (size_t)(Cc / GROUPS) * Nn;
    const float4* p = (const float4*)(x + (size_t)bg * cnt + (size_t)sub * (cnt / 8));
    int tid = threadIdx.x;
    float s = 0.f, sq = 0.f;
    #pragma unroll 4
    for (int i = tid; i < (int)(cnt / 8 / 4); i += 256) {
        float4 v = p[i];
        s  += v.x + v.y + v.z + v.w;
        sq += v.x * v.x + v.y * v.y + v.z * v.z + v.w * v.w;
    }
    int lane = tid & 31, warp = tid >> 5;
    #pragma unroll
    for (int o = 16; o > 0; o >>= 1) {
        s  += __shfl_xor_sync(~0u, s, o);
        sq += __shfl_xor_sync(~0u, sq, o);
    }
    __shared__ float ss[8], ssq[8];
    if (lane == 0) { ss[warp] = s; ssq[warp] = sq; }
    __syncthreads();
    if (tid == 0) {
        float ts = 0.f, tq = 0.f;
        #pragma unroll
        for (int j = 0; j < 8; j++) { ts += ss[j]; tq += ssq[j]; }
        g_part[blk * 2 + 0] = ts;
        g_part[blk * 2 + 1] = tq;
    }
}
__global__ void gn_stats2_kernel() {
    int bg = blockIdx.x * blockDim.x + threadIdx.x;
    if (bg >= Bb * GROUPS) return;
    const float cnt = (float)((Cc / GROUPS) * Nn);
    float s = 0.f, sq = 0.f;
    #pragma unroll
    for (int j = 0; j < 8; j++) {
        s  += g_part[(bg * 8 + j) * 2 + 0];
        sq += g_part[(bg * 8 + j) * 2 + 1];
    }
    float mu = s / cnt;
    float var = sq / cnt - mu * mu;
    g_stats[bg * 2 + 0] = mu;
    g_stats[bg * 2 + 1] = rsqrtf(var + EPS);
}

// ---------------- 2) GN apply + transpose -> fp16 [B,N,C] ----------------
__global__ void gn_apply_kernel(const float* __restrict__ x,
                                const float* __restrict__ w,
                                const float* __restrict__ b) {
    __shared__ float sm[32][33];
    int bz = blockIdx.z;
    int n0 = blockIdx.x * 32;
    int c0 = blockIdx.y * 32;
    int tx = threadIdx.x, ty = threadIdx.y;
    {
        int c = c0 + ty, n = n0 + tx;
        int g = c >> 6;
        float mu   = g_stats[(bz * GROUPS + g) * 2 + 0];
        float rstd = g_stats[(bz * GROUPS + g) * 2 + 1];
        float v = x[((size_t)bz * Cc + c) * Nn + n];
        sm[ty][tx] = (v - mu) * rstd * w[c] + b[c];
    }
    __syncthreads();
    {
        int n = n0 + ty, c = c0 + tx;
        size_t idx = ((size_t)bz * Nn + n) * Cc + c;
        g_hh[idx] = __float2half_rn(sm[tx][ty]);
    }
}

// weight convert: fp32 -> fp16, 4 weights in one launch (blockIdx.y selects)
__global__ void cvt_kernel(const float* __restrict__ w0, const float* __restrict__ w1,
                           const float* __restrict__ w2, const float* __restrict__ w3,
                           __half* __restrict__ dh) {
    int sel = blockIdx.y;
    const float* src = (sel == 0) ? w0 : (sel == 1) ? w1 : (sel == 2) ? w2 : w3;
    int i = (blockIdx.x * 256 + threadIdx.x) * 4;
    float4 v = *(const float4*)(src + i);
    __half2 hh0 = {__float2half_rn(v.x), __float2half_rn(v.y)};
    __half2 hh1 = {__float2half_rn(v.z), __float2half_rn(v.w)};
    __half* d = dh + (size_t)sel * Cc * Cc + i;
    ((__half2*)d)[0] = hh0;
    ((__half2*)d)[1] = hh1;
}

// ---------------- tensor-core TN GEMM machinery (fp16, 1-term) ----------------
#define PLB 8192
#define STGB (4 * PLB)
#define NSTAGE 3
#define TPITCH 129

__device__ __forceinline__ uint32_t cvta_s(const void* p) {
    return (uint32_t)__cvta_generic_to_shared(p);
}
__device__ __forceinline__ void cp16(uint32_t s, const void* g) {
    asm volatile("cp.async.cg.shared.global [%0], [%1], 16;" :: "r"(s), "l"(g));
}
__device__ __forceinline__ void ldsm4(uint32_t& r0, uint32_t& r1, uint32_t& r2, uint32_t& r3, uint32_t a) {
    asm volatile("ldmatrix.sync.aligned.m8n8.x4.shared.b16 {%0,%1,%2,%3}, [%4];"
                 : "=r"(r0), "=r"(r1), "=r"(r2), "=r"(r3) : "r"(a));
}
__device__ __forceinline__ void mma16816(float* c, const uint32_t* a, const uint32_t* b) {
    asm volatile("mma.sync.aligned.m16n8k16.row.col.f32.f16.f16.f32 "
                 "{%0,%1,%2,%3},{%4,%5,%6,%7},{%8,%9},{%0,%1,%2,%3};"
                 : "+f"(c[0]), "+f"(c[1]), "+f"(c[2]), "+f"(c[3])
                 : "r"(a[0]), "r"(a[1]), "r"(a[2]), "r"(a[3]), "r"(b[0]), "r"(b[1]));
}
__device__ __forceinline__ uint32_t swz(int row, int chunk) {
    return (uint32_t)(row * 64 + ((chunk ^ ((row >> 1) & 3)) << 4));
}

// C = A·B^T, plain fp16, fp32 accum
__device__ __forceinline__ void gemm_mainloop(
    const __half* Ah, const __half* Bh,
    int brow, int bcol, int K, uint32_t sbase,
    int tid, int lane, int wm, int wn,
    float acc[2][8][4]) {

    int ldrow = tid >> 1;
    int ldc0 = (tid & 1) * 2;

    auto load_stage = [&](int slot, int k0) {
        uint32_t so = sbase + (uint32_t)(slot * STGB);
        size_t ga = (size_t)(brow + ldrow) * K + k0;
        size_t gb = (size_t)(bcol + ldrow) * K + k0;
        #pragma unroll
        for (int cc = 0; cc < 2; cc++) {
            int c = ldc0 + cc;
            uint32_t off = swz(ldrow, c);
            cp16(so + 0 * PLB + off, Ah + ga + c * 8);
            cp16(so + 2 * PLB + off, Bh + gb + c * 8);
        }
    };

    int nk = K >> 5;
    load_stage(0, 0);
    asm volatile("cp.async.commit_group;");
    load_stage(1, 32);
    asm volatile("cp.async.commit_group;");

    for (int kt = 0; kt < nk; kt++) {
        if (kt + 1 < nk) {
            asm volatile("cp.async.wait_group 1;");
        } else {
            asm volatile("cp.async.wait_group 0;");
        }
        __syncthreads();
        uint32_t so = sbase + (uint32_t)((kt % NSTAGE) * STGB);
        #pragma unroll
        for (int kk = 0; kk < 2; kk++) {
            uint32_t ah[2][4];
            int arow = wm * 32 + ((lane >> 3) & 1) * 8 + (lane & 7);
            int akof = kk * 16 + (lane >> 4) * 8;
            int achk = akof >> 3;
            #pragma unroll
            for (int mt = 0; mt < 2; mt++) {
                uint32_t addr = so + swz(arow + mt * 16, achk);
                ldsm4(ah[mt][0], ah[mt][1], ah[mt][2], ah[mt][3], addr);
            }
            uint32_t bh[8][2];
            int bphase = lane >> 3;
            int brl = wn * 64 + (lane & 7) + (bphase >> 1) * 8;
            int bkof = kk * 16 + (bphase & 1) * 8;
            int bchk = bkof >> 3;
            #pragma unroll
            for (int np = 0; np < 4; np++) {
                uint32_t addr = so + 2 * PLB + swz(brl + np * 16, bchk);
                uint32_t r0, r1, r2, r3;
                ldsm4(r0, r1, r2, r3, addr);
                bh[np * 2][0] = r0; bh[np * 2][1] = r1;
                bh[np * 2 + 1][0] = r2; bh[np * 2 + 1][1] = r3;
            }
            #pragma unroll
            for (int mt = 0; mt < 2; mt++)
                #pragma unroll
                for (int nt = 0; nt < 8; nt++)
                    mma16816(acc[mt][nt], ah[mt], bh[nt]);
        }
        if (kt + 2 < nk) {
            load_stage((kt + 2) % NSTAGE, (kt + 2) << 5);
            asm volatile("cp.async.commit_group;");
        }
    }
}

__device__ __forceinline__ void stage_acc(float* buf, float acc[2][8][4],
                                          const float* bias, int lane, int wm, int wn) {
    int gid = lane >> 2, tig = lane & 3;
    #pragma unroll
    for (int nt = 0; nt < 8; nt++) {
        int c = wn * 64 + nt * 8 + tig * 2;
        float b0 = bias ? bias[c] : 0.f;
        float b1 = bias ? bias[c + 1] : 0.f;
        #pragma unroll
        for (int mt = 0; mt < 2; mt++) {
            int r = wm * 32 + mt * 16 + gid;
            buf[r * TPITCH + c]           = acc[mt][nt][0] + b0;
            buf[r * TPITCH + c + 1]       = acc[mt][nt][1] + b1;
            buf[(r + 8) * TPITCH + c]     = acc[mt][nt][2] + b0;
            buf[(r + 8) * TPITCH + c + 1] = acc[mt][nt][3] + b1;
        }
    }
}

// generic TN GEMM; fp16 output
__global__ __launch_bounds__(256, 2)
void mma_tn(const __half* __restrict__ Ah, const __half* __restrict__ Bh,
            __half* __restrict__ Ch,
            int M, int N, int K, float alpha,
            long long sA, long long sB, long long sC) {
    extern __shared__ __half smbuf[];
    long long zb = blockIdx.z;
    Ah += zb * sA;
    Bh += zb * sB;
    Ch += zb * sC;

    int tid = threadIdx.x;
    int lane = tid & 31, warp = tid >> 5;
    int wm = warp & 3, wn = warp >> 2;
    int brow = blockIdx.y * 128, bcol = blockIdx.x * 128;
    uint32_t sbase = cvta_s(smbuf);

    float acc[2][8][4];
    #pragma unroll
    for (int i = 0; i < 2; i++)
        #pragma unroll
        for (int j = 0; j < 8; j++)
            #pragma unroll
            for (int q = 0; q < 4; q++) acc[i][j][q] = 0.f;

    gemm_mainloop(Ah, Bh, brow, bcol, K, sbase, tid, lane, wm, wn, acc);

    int gid = lane >> 2, tig = lane & 3;
    #pragma unroll
    for (int nt = 0; nt < 8; nt++) {
        int col = bcol + wn * 64 + nt * 8 + tig * 2;
        #pragma unroll
        for (int mt = 0; mt < 2; mt++) {
            int row0 = brow + wm * 32 + mt * 16 + gid;
            __half2 hh0 = {__float2half_rn(acc[mt][nt][0] * alpha),
                           __float2half_rn(acc[mt][nt][1] * alpha)};
            __half2 hh1 = {__float2half_rn(acc[mt][nt][2] * alpha),
                           __float2half_rn(acc[mt][nt][3] * alpha)};
            *(__half2*)(Ch + (size_t)row0 * N + col) = hh0;
            *(__half2*)(Ch + (size_t)(row0 + 8) * N + col) = hh1;
        }
    }
}

// fused QKV projection (1-term); Q, K, V^T(via transpose) fp16.
__global__ __launch_bounds__(256, 2)
void mma_qkv(const __half* __restrict__ Ah, const __half* __restrict__ Bh,
             const float* __restrict__ bq, const float* __restrict__ bk,
             const float* __restrict__ bv,
             __half* __restrict__ Qh,
             __half* __restrict__ Kh,
             __half* __restrict__ Vth,
             int K) {
    extern __shared__ __half smbuf[];
    int tid = threadIdx.x;
    int lane = tid & 31, warp = tid >> 5;
    int wm = warp & 3, wn = warp >> 2;
    int brow = blockIdx.y * 128, bcol = blockIdx.x * 128;
    uint32_t sbase = cvta_s(smbuf);

    float acc[2][8][4];
    #pragma unroll
    for (int i = 0; i < 2; i++)
        #pragma unroll
        for (int j = 0; j < 8; j++)
            #pragma unroll
            for (int q = 0; q < 4; q++) acc[i][j][q] = 0.f;

    gemm_mainloop(Ah, Bh, brow, bcol, K, sbase, tid, lane, wm, wn, acc);

    int sec = bcol >> 9;            // 0=q 1=k 2=v
    int colbase = bcol & 511;

    if (sec == 2) {
        __syncthreads();
        float* buf = (float*)smbuf;
        stage_acc(buf, acc, bv + colbase, lane, wm, wn);
        __syncthreads();
        int d = tid >> 1, mh = tid & 1;
        int b = brow >> 12, m0 = (brow & 4095) + mh * 64;
        size_t base = ((size_t)b * Cc + colbase + d) * Nn + m0;
        #pragma unroll 8
        for (int i = 0; i < 32; i++) {
            float f0 = buf[(mh * 64 + 2 * i) * TPITCH + d];
            float f1 = buf[(mh * 64 + 2 * i + 1) * TPITCH + d];
            __half2 hh = {__float2half_rn(f0), __float2half_rn(f1)};
            *(__half2*)(Vth + base + 2 * i) = hh;
        }
        return;
    }

    const float* bias = (sec == 0) ? bq : bk;
    __half* Ch = (sec == 0) ? Qh : Kh;
    int gid = lane >> 2, tig = lane & 3;
    #pragma unroll
    for (int nt = 0; nt < 8; nt++) {
        int col = colbase + wn * 64 + nt * 8 + tig * 2;
        float b0 = bias[col], b1 = bias[col + 1];
        #pragma unroll
        for (int mt = 0; mt < 2; mt++) {
            int row0 = brow + wm * 32 + mt * 16 + gid;
            __half2 hh0 = {__float2half_rn(acc[mt][nt][0] + b0),
                           __float2half_rn(acc[mt][nt][1] + b1)};
            __half2 hh1 = {__float2half_rn(acc[mt][nt][2] + b0),
                           __float2half_rn(acc[mt][nt][3] + b1)};
            *(__half2*)(Ch + (size_t)row0 * Cc + col) = hh0;
            *(__half2*)(Ch + (size_t)(row0 + 8) * Cc + col) = hh1;
        }
    }
}

// final projection (1-term) fused with residual + transpose-back
__global__ __launch_bounds__(256, 2)
void mma_resid(const __half* __restrict__ Ah, const __half* __restrict__ Bh,
               const float* __restrict__ bias,
               const float* __restrict__ x, float* __restrict__ out,
               int K) {
    extern __shared__ __half smbuf[];
    int tid = threadIdx.x;
    int lane = tid & 31, warp = tid >> 5;
    int wm = warp & 3, wn = warp >> 2;
    int brow = blockIdx.y * 128, bcol = blockIdx.x * 128;
    uint32_t sbase = cvta_s(smbuf);

    float acc[2][8][4];
    #pragma unroll
    for (int i = 0; i < 2; i++)
        #pragma unroll
        for (int j = 0; j < 8; j++)
            #pragma unroll
            for (int q = 0; q < 4; q++) acc[i][j][q] = 0.f;

    gemm_mainloop(Ah, Bh, brow, bcol, K, sbase, tid, lane, wm, wn, acc);

    __syncthreads();
    float* buf = (float*)smbuf;
    stage_acc(buf, acc, bias + bcol, lane, wm, wn);
    __syncthreads();

    int c = tid >> 1, nh = tid & 1;
    int b = brow >> 12, n0 = (brow & 4095) + nh * 64;
    size_t base = ((size_t)b * Cc + bcol + c) * Nn + n0;
    #pragma unroll
    for (int i = 0; i < 16; i++) {
        float4 xv = *(const float4*)(x + base + 4 * i);
        float4 o;
        o.x = xv.x + buf[(nh * 64 + 4 * i + 0) * TPITCH + c];
        o.y = xv.y + buf[(nh * 64 + 4 * i + 1) * TPITCH + c];
        o.z = xv.z + buf[(nh * 64 + 4 * i + 2) * TPITCH + c];
        o.w = xv.w + buf[(nh * 64 + 4 * i + 3) * TPITCH + c];
        *(float4*)(out + base + 4 * i) = o;
    }
}

// ---------------- softmax rows of fp16 scores -> fp16 probs ----------------
__global__ void softmax_kernel() {
    size_t row = blockIdx.x;
    __half2* p = (__half2*)(g_sh + row * Nn);
    __half2* q = (__half2*)(g_ph + row * Nn);
    int tid = threadIdx.x;
    int lane = tid & 31, warp = tid >> 5;
    __shared__ float sm1[8], sm2[8];
    float v[16];
    float mx = -1e30f;
    #pragma unroll
    for (int i = 0; i < 8; i++) {
        float2 f = __half22float2(p[tid + i * 256]);
        v[i * 2] = f.x; v[i * 2 + 1] = f.y;
        mx = fmaxf(mx, fmaxf(f.x, f.y));
    }
    #pragma unroll
    for (int o = 16; o > 0; o >>= 1) mx = fmaxf(mx, __shfl_xor_sync(~0u, mx, o));
    if (lane == 0) sm1[warp] = mx;
    __syncthreads();
    mx = sm1[0];
    #pragma unroll
    for (int j = 1; j < 8; j++) mx = fmaxf(mx, sm1[j]);

    float s = 0.f;
    #pragma unroll
    for (int i = 0; i < 16; i++) {
        v[i] = __expf(v[i] - mx);
        s += v[i];
    }
    #pragma unroll
    for (int o = 16; o > 0; o >>= 1) s += __shfl_xor_sync(~0u, s, o);
    if (lane == 0) sm2[warp] = s;
    __syncthreads();
    s = 0.f;
    #pragma unroll
    for (int j = 0; j < 8; j++) s += sm2[j];
    float inv = 1.f / s;

    #pragma unroll
    for (int i = 0; i < 8; i++) {
        __half2 hh = {__float2half_rn(v[i * 2] * inv),
                      __float2half_rn(v[i * 2 + 1] * inv)};
        q[tid + i * 256] = hh;
    }
}

// ---------------- launch ----------------
extern "C" void kernel_launch(void* const* d_in, const int* in_sizes, int n_in,
                              void* d_out, int out_size) {
    const float* x    = (const float*)d_in[0];
    const float* gn_w = (const float*)d_in[1];
    const float* gn_b = (const float*)d_in[2];
    const float* wq   = (const float*)d_in[3];
    const float* bq   = (const float*)d_in[4];
    const float* wk   = (const float*)d_in[5];
    const float* bk   = (const float*)d_in[6];
    const float* wv   = (const float*)d_in[7];
    const float* bv   = (const float*)d_in[8];
    const float* wo   = (const float*)d_in[9];
    const float* bo   = (const float*)d_in[10];
    float* out = (float*)d_out;

    __half *hh, *w4h, *qh, *kh, *vth, *sh, *ph, *aoh;
    cudaGetSymbolAddress((void**)&hh, g_hh);
    cudaGetSymbolAddress((void**)&w4h, g_w4h);
    cudaGetSymbolAddress((void**)&qh, g_qh);
    cudaGetSymbolAddress((void**)&kh, g_kh);
    cudaGetSymbolAddress((void**)&vth, g_vth);
    cudaGetSymbolAddress((void**)&sh, g_sh);
    cudaGetSymbolAddress((void**)&ph, g_ph);
    cudaGetSymbolAddress((void**)&aoh, g_aoh);

    const int Mtot = Bb * Nn;                        // 32768
    const float scale = 0.044194173824159216f;       // 1/sqrt(512)
    const int WSZ = Cc * Cc;                         // 262144
    const int SMEM = NSTAGE * STGB;                  // 96 KB

    cudaFuncSetAttribute(mma_tn, cudaFuncAttributeMaxDynamicSharedMemorySize, SMEM);
    cudaFuncSetAttribute(mma_qkv, cudaFuncAttributeMaxDynamicSharedMemorySize, SMEM);
    cudaFuncSetAttribute(mma_resid, cudaFuncAttributeMaxDynamicSharedMemorySize, SMEM);

    gn_stats1_kernel<<<512, 256>>>(x);
    gn_stats2_kernel<<<2, 32>>>();
    gn_apply_kernel<<<dim3(Nn / 32, Cc / 32, Bb), dim3(32, 32)>>>(x, gn_w, gn_b);
    cvt_kernel<<<dim3(WSZ / 1024, 4), 256>>>(wq, wk, wv, wo, w4h);

    // fused QKV projection (1-term fp16)
    mma_qkv<<<dim3(12, Mtot / 128), 256, SMEM>>>(hh, w4h,
                                                 bq, bk, bv, qh, kh, vth, Cc);
    // scores = q k^T * scale  (fp16 out)
    mma_tn<<<dim3(Nn / 128, Nn / 128, Bb), 256, SMEM>>>(qh, kh,
                                 sh, Nn, Nn, Cc, scale, NCs, NCs, NNs);
    softmax_kernel<<<Bb * Nn, 256>>>();
    // attn out = P @ V
    mma_tn<<<dim3(Cc / 128, Nn / 128, Bb), 256, SMEM>>>(ph, vth,
                                 aoh, Nn, Cc, Nn, 1.f, NNs, NCs, NCs);
    // final projection + residual + transpose-back
    mma_resid<<<dim3(Cc / 128, Mtot / 128), 256, SMEM>>>(aoh,
                                 w4h + 3 * WSZ, bo, x, out, Cc);
}